// round 11
// baseline (speedup 1.0000x reference)
#include <cuda_runtime.h>
#include <cuda_bf16.h>
#include <stdint.h>

// ---------------- problem constants ----------------
namespace {
constexpr int B = 2, TCOND = 1024, TPRED = 512, NVC = 8, NVP = 4;
constexpr int D = 128, KW = 3, H = 8, DFF = 512, L = 2, HOR = 96, NQ = 3;
constexpr int T = TCOND + TPRED;   // 1536
constexpr int DKh = D / H;         // 16
constexpr int NJ = T / 32;         // 48 (12 per chunk * 4 chunks)
constexpr int SL = DKh * T;        // 24576 floats per (b,h) kT slab
constexpr int RPT = 16;            // rows per tile (2 per warp, 8 warps)
constexpr int NTILE = B * (T / RPT); // 192 tiles
constexpr int CHW = 384;           // chunk width (columns)
constexpr int CHF = DKh * CHW;     // 6144 floats per chunk (24 KB)

constexpr int VC_OFS   = B * NQ * HOR;              // 576
constexpr int VP_OFS   = VC_OFS + B * TCOND * NVC;  // 16960
constexpr int LOGS_OFS = VP_OFS + B * TPRED * NVP;  // 21056
}

// ---------------- device scratch (static, no allocation) ----------------
__device__ float g_x[B*T*D];
__device__ float g_q[B*T*D];
__device__ float g_kT[B*H*SL];
__device__ float g_vcT[B*DKh*T];     // v_comb transposed: [b][e][T]
__device__ float g_y[B*T*DKh];
__device__ float g_wc[B*TCOND*NVC];
__device__ float g_wp[B*TPRED*NVP];
__device__ float g_Ac[NVC*KW], g_Cc[NVC], g_Ap[NVP*KW], g_Cp[NVP];
__device__ float g_Wvc[L*D*DKh], g_bvc[L*DKh];
__device__ unsigned g_key[4];
__device__ int g_ctr;                // attention tile work queue

// ---------------- threefry2x32 (matches JAX) ----------------
__device__ __forceinline__ unsigned rotl32(unsigned v, int r){ return (v<<r)|(v>>(32-r)); }

__device__ __forceinline__ void threefry(unsigned k0, unsigned k1,
                                         unsigned x0, unsigned x1,
                                         unsigned& o0, unsigned& o1){
  unsigned ks2 = k0 ^ k1 ^ 0x1BD11BDAu;
  unsigned ks[3] = {k0, k1, ks2};
  x0 += ks[0]; x1 += ks[1];
  const int R0[4] = {13,15,26,6};
  const int R1[4] = {17,29,16,24};
  #pragma unroll
  for (int i = 0; i < 5; ++i){
    #pragma unroll
    for (int j = 0; j < 4; ++j){
      int r = (i & 1) ? R1[j] : R0[j];
      x0 += x1; x1 = rotl32(x1, r); x1 ^= x0;
    }
    x0 += ks[(i+1)%3];
    x1 += ks[(i+2)%3] + (unsigned)(i+1);
  }
  o0 = x0; o1 = x1;
}

// ---------------- XLA f32 erfinv ----------------
__device__ __forceinline__ float erfinv32(float x){
  float w = -log1pf(-x*x);
  float p;
  if (w < 5.0f){
    w = w - 2.5f;
    p = 2.81022636e-08f;
    p = fmaf(p, w, 3.43273939e-07f);
    p = fmaf(p, w, -3.5233877e-06f);
    p = fmaf(p, w, -4.39150654e-06f);
    p = fmaf(p, w, 0.00021858087f);
    p = fmaf(p, w, -0.00125372503f);
    p = fmaf(p, w, -0.00417768164f);
    p = fmaf(p, w, 0.246640727f);
    p = fmaf(p, w, 1.50140941f);
  } else {
    w = sqrtf(w) - 3.0f;
    p = -0.000200214257f;
    p = fmaf(p, w, 0.000100950558f);
    p = fmaf(p, w, 0.00134934322f);
    p = fmaf(p, w, -0.00367342844f);
    p = fmaf(p, w, 0.00573950773f);
    p = fmaf(p, w, -0.0076224613f);
    p = fmaf(p, w, 0.00943887047f);
    p = fmaf(p, w, 1.00167406f);
    p = fmaf(p, w, 2.83297682f);
  }
  return p * x;
}

// ---------------- prep: keys, folded selector weights, head-averaged Wv ----------------
__global__ void prep_kernel(const float* __restrict__ cwc, const float* __restrict__ cbc,
                            const float* __restrict__ swc, const float* __restrict__ sbc,
                            const float* __restrict__ cwp, const float* __restrict__ cbp,
                            const float* __restrict__ swp, const float* __restrict__ sbp,
                            const float* __restrict__ Wv,  const float* __restrict__ bv){
  int tid = threadIdx.x;
  if (tid == 0) threefry(0u, 42u, 0u, 0u, g_key[0], g_key[1]);
  if (tid == 1) threefry(0u, 42u, 0u, 1u, g_key[2], g_key[3]);

  if (tid >= 2 && tid < 2 + NVC*KW){
    int i = tid - 2, g = i / KW, k = i % KW;
    float s = 0.f;
    for (int d = 0; d < D; ++d) s = fmaf(cwc[(g*D + d)*KW + k], swc[d], s);
    g_Ac[i] = s;
  } else if (tid >= 26 && tid < 26 + NVC){
    int g = tid - 26;
    float s = 0.f;
    for (int d = 0; d < D; ++d) s = fmaf(cbc[g*D + d], swc[d], s);
    g_Cc[g] = s + sbc[0];
  } else if (tid >= 34 && tid < 34 + NVP*KW){
    int i = tid - 34, g = i / KW, k = i % KW;
    float s = 0.f;
    for (int d = 0; d < D; ++d) s = fmaf(cwp[(g*D + d)*KW + k], swp[d], s);
    g_Ap[i] = s;
  } else if (tid >= 46 && tid < 46 + NVP){
    int g = tid - 46;
    float s = 0.f;
    for (int d = 0; d < D; ++d) s = fmaf(cbp[g*D + d], swp[d], s);
    g_Cp[g] = s + sbp[0];
  } else if (tid >= 50 && tid < 50 + L*DKh){
    int i = tid - 50, l = i / DKh, d = i % DKh;
    float s = 0.f;
    for (int h = 0; h < H; ++h) s += bv[l*D + h*DKh + d];
    g_bvc[i] = s * (1.0f/H);
  }

  for (int i = tid; i < L*D*DKh; i += blockDim.x){
    int l = i / (D*DKh), e = (i / DKh) % D, d = i % DKh;
    float s = 0.f;
    for (int h = 0; h < H; ++h) s += Wv[l*D*D + e*D + h*DKh + d];
    g_Wvc[i] = s * (1.0f/H);
  }
}

// ---------------- selector ----------------
template<int NV, int TS, int WHICH>
__global__ void selector_kernel(const float* __restrict__ xin,
                                float* __restrict__ dout, int oofs){
  int r = blockIdx.x * blockDim.x + threadIdx.x;
  if (r >= B*TS) return;
  int b = r / TS, t = r % TS;

  const float* A = (WHICH == 0) ? g_Ac : g_Ap;
  const float* C = (WHICH == 0) ? g_Cc : g_Cp;
  float* wscr    = (WHICH == 0) ? g_wc : g_wp;
  unsigned k0 = g_key[WHICH*2], k1 = g_key[WHICH*2 + 1];

  const int N = B*TS*NV, half = N >> 1;
  float z[NV];
  float m = -1e30f;
  #pragma unroll
  for (int g = 0; g < NV; ++g){
    float x0  = xin[(b*TS + t)*NV + g];
    float xm1 = (t >= 1) ? xin[(b*TS + t - 1)*NV + g] : 0.f;
    float xm2 = (t >= 2) ? xin[(b*TS + t - 2)*NV + g] : 0.f;
    float s = A[g*KW+0]*xm2 + A[g*KW+1]*xm1 + A[g*KW+2]*x0 + C[g];
    s = fminf(10.f, fmaxf(-10.f, s));
    int idx = (b*TS + t)*NV + g;
    unsigned o0, o1, bits;
    if (idx < half){ threefry(k0, k1, (unsigned)idx, (unsigned)(idx + half), o0, o1); bits = o0; }
    else           { threefry(k0, k1, (unsigned)(idx - half), (unsigned)idx, o0, o1); bits = o1; }
    float fu = __uint_as_float((bits >> 9) | 0x3f800000u) - 1.0f;
    const float lom = -0.99999994f, him = 1.0f;
    float u = fmaxf(lom, fmaf(fu, him - lom, lom));
    s = s + 1e-4f * (1.41421356f * erfinv32(u));
    z[g] = 0.5f * s;
    m = fmaxf(m, z[g]);
  }
  #pragma unroll
  for (int g = 0; g < NV; ++g) z[g] -= m;

  float tau = -1.0f;
  #pragma unroll 1
  for (int it = 0; it < 22; ++it){
    float f = 0.f, gg = 0.f;
    #pragma unroll
    for (int g = 0; g < NV; ++g){
      float dd = fmaxf(z[g] - tau, 0.f);
      f = fmaf(dd, dd, f); gg += dd;
    }
    tau += (f - 1.0f) / fmaxf(2.0f*gg, 1e-30f);
  }
  #pragma unroll
  for (int g = 0; g < NV; ++g){
    float dd = fmaxf(z[g] - tau, 0.f);
    float p = dd*dd;
    wscr[r*NV + g] = p;
    dout[oofs + r*NV + g] = p;
  }
}

// ---------------- weighted conv features -> concat x (B,T,128) ----------------
__global__ void weighted_kernel(const float* __restrict__ xc, const float* __restrict__ xp,
                                const float* __restrict__ cwc, const float* __restrict__ cbc,
                                const float* __restrict__ cwp, const float* __restrict__ cbp){
  int bt = blockIdx.x;
  int d = threadIdx.x;
  int b = bt / T, t = bt % T;
  const float *xin, *cw, *cb, *wsel;
  int nv, Ts, tt;
  if (t < TCOND){ xin = xc; cw = cwc; cb = cbc; wsel = g_wc; nv = NVC; Ts = TCOND; tt = t; }
  else          { xin = xp; cw = cwp; cb = cbp; wsel = g_wp; nv = NVP; Ts = TPRED; tt = t - TCOND; }
  float acc = 0.f;
  for (int g = 0; g < nv; ++g){
    float w = wsel[(b*Ts + tt)*nv + g];
    float x0  = xin[(b*Ts + tt)*nv + g];
    float xm1 = (tt >= 1) ? xin[(b*Ts + tt - 1)*nv + g] : 0.f;
    float xm2 = (tt >= 2) ? xin[(b*Ts + tt - 2)*nv + g] : 0.f;
    const float* cwg = cw + (g*D + d)*KW;
    float ls = cb[g*D + d] + cwg[0]*xm2 + cwg[1]*xm1 + cwg[2]*x0;
    acc = fmaf(w, ls, acc);
  }
  g_x[(b*T + t)*D + d] = acc;
}

// ---------------- QKV (+ head-averaged V, transposed): 16 rows per block ----------------
__global__ void __launch_bounds__(256) qkv_kernel(int l,
                           const float* __restrict__ Wq, const float* __restrict__ bq,
                           const float* __restrict__ Wk, const float* __restrict__ bk){
  __shared__ float xrT[D][16];           // 8 KB, transposed activations
  if (blockIdx.x == 0 && threadIdx.x == 0) g_ctr = 0;   // reset attn work queue
  int b  = blockIdx.x / (T/16);
  int t0 = (blockIdx.x % (T/16)) * 16;
  int tid = threadIdx.x;  // 256
  for (int i = tid; i < 16*D; i += 256){
    int r = i >> 7, e = i & 127;
    xrT[e][r] = g_x[(b*T + t0 + r)*D + e];
  }
  __syncthreads();

  for (int col = tid; col < 2*D + DKh; col += 256){
    const float* W; float bias; int c, ld, kind;
    if (col < D)        { c = col;       W = Wq + l*D*D;       bias = bq[l*D + c];     ld = D;   kind = 0; }
    else if (col < 2*D) { c = col - D;   W = Wk + l*D*D;       bias = bk[l*D + c];     ld = D;   kind = 1; }
    else                { c = col - 2*D; W = g_Wvc + l*D*DKh;  bias = g_bvc[l*DKh+c];  ld = DKh; kind = 2; }
    float acc[16];
    #pragma unroll
    for (int r = 0; r < 16; ++r) acc[r] = bias;
    for (int e = 0; e < D; ++e){
      float w = W[e*ld + c];
      float4 xA = *(const float4*)&xrT[e][0];
      float4 xB = *(const float4*)&xrT[e][4];
      float4 xC = *(const float4*)&xrT[e][8];
      float4 xD = *(const float4*)&xrT[e][12];
      acc[0]=fmaf(w,xA.x,acc[0]);  acc[1]=fmaf(w,xA.y,acc[1]);  acc[2]=fmaf(w,xA.z,acc[2]);  acc[3]=fmaf(w,xA.w,acc[3]);
      acc[4]=fmaf(w,xB.x,acc[4]);  acc[5]=fmaf(w,xB.y,acc[5]);  acc[6]=fmaf(w,xB.z,acc[6]);  acc[7]=fmaf(w,xB.w,acc[7]);
      acc[8]=fmaf(w,xC.x,acc[8]);  acc[9]=fmaf(w,xC.y,acc[9]);  acc[10]=fmaf(w,xC.z,acc[10]); acc[11]=fmaf(w,xC.w,acc[11]);
      acc[12]=fmaf(w,xD.x,acc[12]); acc[13]=fmaf(w,xD.y,acc[13]); acc[14]=fmaf(w,xD.z,acc[14]); acc[15]=fmaf(w,xD.w,acc[15]);
    }
    #pragma unroll
    for (int r = 0; r < 16; ++r){
      int t = t0 + r;
      if (kind == 0)      g_q[(b*T + t)*D + c] = acc[r];
      else if (kind == 1){ int h = c / DKh, d = c % DKh;
                           g_kT[((b*H + h)*DKh + d)*T + t] = acc[r]; }
      else                g_vcT[((size_t)b*DKh + c)*T + t] = acc[r];
    }
  }
}

// ---------------- chunk loader: 16 rows x 384 cols from row-strided source ----------------
// 256 threads: 6 x 16B per thread
__device__ __forceinline__ void issue_chunk(unsigned sdst, const float* gsrc, int tid){
  #pragma unroll
  for (int i = 0; i < 6; ++i){
    int u = i*256 + tid;
    int e = u / 96, off = u - e*96;
    unsigned sa = sdst + (unsigned)(e*1536 + off*16);
    const char* ga = (const char*)gsrc + (size_t)e*T*4 + (size_t)off*16;
    asm volatile("cp.async.cg.shared.global [%0], [%1], 16;\n" :: "r"(sa), "l"(ga) : "memory");
  }
  asm volatile("cp.async.commit_group;\n" ::: "memory");
}

// ---------------- fused attention: persistent, work-stealing, 2 rows per warp ----------------
// block = 256 threads (8 warps x 2 rows = 16-row tile); smem = 2 x 24KB chunk buffers
__global__ void __launch_bounds__(256, 1) attn_fused_kernel(int l, float* __restrict__ dout){
  extern __shared__ float chbuf[];         // 2 * CHF floats (48 KB)
  __shared__ float qs[RPT*D];              // 8 KB q tile
  __shared__ int s_tile;

  const int tid = threadIdx.x, w = tid >> 5, lane = tid & 31;
  const unsigned sbase = (unsigned)__cvta_generic_to_shared(chbuf);
  int cur = 0;

  for (;;){
    __syncthreads();
    if (tid == 0) s_tile = atomicAdd(&g_ctr, 1);
    __syncthreads();
    int u = s_tile;
    if (u >= NTILE) break;

    // descending-cost (LPT) ordering
    int tr = (T/RPT - 1) - (u >> 1);
    int b  = u & 1;
    int t0 = tr*RPT + w*2;                 // this warp's rows: t0, t0+1
    int t1 = t0 + 1;
    int tmax = tr*RPT + (RPT-1);
    int ncc  = tmax/CHW + 1;               // active chunks (1..4), block-uniform

    // stage q tile [16][128]
    for (int i = tid; i < RPT*D; i += 256)
      qs[i] = g_q[(size_t)(b*T + tr*RPT + (i >> 7))*D + (i & 127)];

    const float* kbase = g_kT + (size_t)b*H*SL;
    const float* vbase = g_vcT + (size_t)b*DKh*T;

    // prologue: issue k chunk (h=0, c=0) into buf[cur]
    issue_chunk(sbase + (unsigned)cur*(CHF*4), kbase, tid);

    float wa0[NJ], wa1[NJ];
    #pragma unroll
    for (int j = 0; j < NJ; ++j){ wa0[j] = 0.f; wa1[j] = 0.f; }

    #pragma unroll 1
    for (int h = 0; h < H; ++h){
      float z0[NJ], z1[NJ];
      #pragma unroll
      for (int c = 0; c < 4; ++c){
        if (c < ncc){
          asm volatile("cp.async.wait_group 0;\n" ::: "memory");
          __syncthreads();
          // issue next chunk into other buffer
          if (c + 1 < ncc)      issue_chunk(sbase + (unsigned)(cur^1)*(CHF*4), kbase + (size_t)h*SL + (c+1)*CHW, tid);
          else if (h + 1 < H)   issue_chunk(sbase + (unsigned)(cur^1)*(CHF*4), kbase + (size_t)(h+1)*SL, tid);
          else                  issue_chunk(sbase + (unsigned)(cur^1)*(CHF*4), vbase, tid);
          // scores for chunk c: lane owns columns c*384 + g*128 + lane*4 + r
          const float* kb = chbuf + cur*CHF;
          #pragma unroll
          for (int g = 0; g < 3; ++g){
            #pragma unroll
            for (int r = 0; r < 4; ++r){ z0[c*12 + g*4 + r] = 0.f; z1[c*12 + g*4 + r] = 0.f; }
          }
          #pragma unroll 4
          for (int e = 0; e < DKh; ++e){
            float qe0 = qs[(w*2+0)*D + h*DKh + e];
            float qe1 = qs[(w*2+1)*D + h*DKh + e];
            const float4* kr = (const float4*)(kb + e*CHW);
            #pragma unroll
            for (int g = 0; g < 3; ++g){
              float4 kv = kr[g*32 + lane];
              z0[c*12 + g*4 + 0] = fmaf(qe0, kv.x, z0[c*12 + g*4 + 0]);
              z0[c*12 + g*4 + 1] = fmaf(qe0, kv.y, z0[c*12 + g*4 + 1]);
              z0[c*12 + g*4 + 2] = fmaf(qe0, kv.z, z0[c*12 + g*4 + 2]);
              z0[c*12 + g*4 + 3] = fmaf(qe0, kv.w, z0[c*12 + g*4 + 3]);
              z1[c*12 + g*4 + 0] = fmaf(qe1, kv.x, z1[c*12 + g*4 + 0]);
              z1[c*12 + g*4 + 1] = fmaf(qe1, kv.y, z1[c*12 + g*4 + 1]);
              z1[c*12 + g*4 + 2] = fmaf(qe1, kv.z, z1[c*12 + g*4 + 2]);
              z1[c*12 + g*4 + 3] = fmaf(qe1, kv.w, z1[c*12 + g*4 + 3]);
            }
          }
          cur ^= 1;
        }
      }

      // mask + zmax (both rows)
      float m0 = -3.0e30f, m1 = -3.0e30f;
      #pragma unroll
      for (int c = 0; c < 4; ++c){
        if (c < ncc){
          #pragma unroll
          for (int g = 0; g < 3; ++g){
            int sb4 = c*CHW + g*128 + (lane << 2);
            #pragma unroll
            for (int r = 0; r < 4; ++r){
              int j = c*12 + g*4 + r;
              int col = sb4 + r;
              float a0 = (col <= t0) ? z0[j]*0.125f : -5000.0f;
              float a1 = (col <= t1) ? z1[j]*0.125f : -5000.0f;
              z0[j] = a0; z1[j] = a1;
              m0 = fmaxf(m0, a0); m1 = fmaxf(m1, a1);
            }
          }
        }
      }
      #pragma unroll
      for (int off = 16; off; off >>= 1){
        m0 = fmaxf(m0, __shfl_xor_sync(~0u, m0, off));
        m1 = fmaxf(m1, __shfl_xor_sync(~0u, m1, off));
      }

      // active-set exact-quadratic solver for both rows (interleaved)
      float lo0 = m0 - 1.f, hi0 = m0, tau0 = m0 - 1.f;
      float lo1 = m1 - 1.f, hi1 = m1, tau1 = m1 - 1.f;
      #pragma unroll 1
      for (int it = 0; it < 6; ++it){
        float f0 = 0.f, g0 = 0.f, n0 = 0.f;
        float f1 = 0.f, g1 = 0.f, n1 = 0.f;
        #pragma unroll
        for (int c = 0; c < 4; ++c){
          if (c < ncc){
            #pragma unroll
            for (int jj = 0; jj < 12; ++jj){
              int j = c*12 + jj;
              float d0 = z0[j] - tau0, d1 = z1[j] - tau1;
              float p0 = fmaxf(d0, 0.f), p1 = fmaxf(d1, 0.f);
              f0 = fmaf(p0, p0, f0); g0 += p0; n0 += (d0 > 0.f) ? 1.f : 0.f;
              f1 = fmaf(p1, p1, f1); g1 += p1; n1 += (d1 > 0.f) ? 1.f : 0.f;
            }
          }
        }
        #pragma unroll
        for (int off = 16; off; off >>= 1){
          f0 += __shfl_xor_sync(~0u, f0, off);
          f1 += __shfl_xor_sync(~0u, f1, off);
          g0 += __shfl_xor_sync(~0u, g0, off);
          g1 += __shfl_xor_sync(~0u, g1, off);
          n0 += __shfl_xor_sync(~0u, n0, off);
          n1 += __shfl_xor_sync(~0u, n1, off);
        }
        if (f0 > 1.f) lo0 = fmaxf(lo0, tau0); else hi0 = fminf(hi0, tau0);
        if (f1 > 1.f) lo1 = fmaxf(lo1, tau1); else hi1 = fminf(hi1, tau1);
        float d0 = fmaf(g0, g0, -n0*(f0 - 1.f));
        float d1 = fmaf(g1, g1, -n1*(f1 - 1.f));
        float nt0 = tau0 + (g0 - sqrtf(fmaxf(d0, 0.f))) / n0;
        float nt1 = tau1 + (g1 - sqrtf(fmaxf(d1, 0.f))) / n1;
        if (!(d0 > 0.f) || !(nt0 >= lo0 && nt0 <= hi0)) nt0 = 0.5f*(lo0 + hi0);
        if (!(d1 > 0.f) || !(nt1 >= lo1 && nt1 <= hi1)) nt1 = 0.5f*(lo1 + hi1);
        tau0 = nt0; tau1 = nt1;
      }
      #pragma unroll
      for (int c = 0; c < 4; ++c){
        if (c < ncc){
          #pragma unroll
          for (int jj = 0; jj < 12; ++jj){
            int j = c*12 + jj;
            float p0 = fmaxf(z0[j] - tau0, 0.f);
            float p1 = fmaxf(z1[j] - tau1, 0.f);
            wa0[j] = fmaf(p0, p0, wa0[j]);
            wa1[j] = fmaf(p1, p1, wa1[j]);
          }
        }
      }
    }

    // epilogue: head-average -> logs, y = w_avg @ v_comb (v chunks pipelined)
    float* logrow0 = dout + LOGS_OFS + (size_t)((l*B + b)*T + t0)*T;
    float* logrow1 = dout + LOGS_OFS + (size_t)((l*B + b)*T + t1)*T;
    float acc0[DKh], acc1[DKh];
    #pragma unroll
    for (int e = 0; e < DKh; ++e){ acc0[e] = 0.f; acc1[e] = 0.f; }

    #pragma unroll
    for (int c = 0; c < 4; ++c){
      if (c < ncc){
        asm volatile("cp.async.wait_group 0;\n" ::: "memory");
        __syncthreads();
        if (c + 1 < ncc) issue_chunk(sbase + (unsigned)(cur^1)*(CHF*4), vbase + (c+1)*CHW, tid);
        const float* vb = chbuf + cur*CHF;
        #pragma unroll
        for (int g = 0; g < 3; ++g){
          int j = c*12 + g*4;
          float a0 = wa0[j+0]*0.125f, a1 = wa0[j+1]*0.125f, a2 = wa0[j+2]*0.125f, a3 = wa0[j+3]*0.125f;
          float b0 = wa1[j+0]*0.125f, b1 = wa1[j+1]*0.125f, b2 = wa1[j+2]*0.125f, b3 = wa1[j+3]*0.125f;
          ((float4*)(logrow0 + c*CHW + g*128))[lane] = make_float4(a0, a1, a2, a3);
          ((float4*)(logrow1 + c*CHW + g*128))[lane] = make_float4(b0, b1, b2, b3);
          #pragma unroll
          for (int e = 0; e < DKh; ++e){
            float4 vv = ((const float4*)(vb + e*CHW + g*128))[lane];
            acc0[e] = fmaf(a0, vv.x, acc0[e]);
            acc0[e] = fmaf(a1, vv.y, acc0[e]);
            acc0[e] = fmaf(a2, vv.z, acc0[e]);
            acc0[e] = fmaf(a3, vv.w, acc0[e]);
            acc1[e] = fmaf(b0, vv.x, acc1[e]);
            acc1[e] = fmaf(b1, vv.y, acc1[e]);
            acc1[e] = fmaf(b2, vv.z, acc1[e]);
            acc1[e] = fmaf(b3, vv.w, acc1[e]);
          }
        }
        cur ^= 1;
      } else {
        #pragma unroll
        for (int g = 0; g < 3; ++g){
          ((float4*)(logrow0 + c*CHW + g*128))[lane] = make_float4(0.f, 0.f, 0.f, 0.f);
          ((float4*)(logrow1 + c*CHW + g*128))[lane] = make_float4(0.f, 0.f, 0.f, 0.f);
        }
      }
    }

    float myv0 = 0.f, myv1 = 0.f;
    #pragma unroll
    for (int e = 0; e < DKh; ++e){
      float v0 = acc0[e], v1 = acc1[e];
      #pragma unroll
      for (int off = 16; off; off >>= 1){
        v0 += __shfl_xor_sync(~0u, v0, off);
        v1 += __shfl_xor_sync(~0u, v1, off);
      }
      if (lane == e){ myv0 = v0; myv1 = v1; }
    }
    if (lane < DKh){
      g_y[(size_t)(b*T + t0)*DKh + lane] = myv0;
      g_y[(size_t)(b*T + t1)*DKh + lane] = myv1;
    }
  }
}

// ---------------- fused Wo + LN1 + FFN + LN2 : 16 rows per block, 512 threads ----------------
// dynamic smem layout (floats): xs[16*128] @0 | xsT[128*16] @2048 (aliased by o3) | hsT[512*16] @4096
__global__ void __launch_bounds__(512, 2) ffn_kernel(
    int l,
    const float* __restrict__ Wo,  const float* __restrict__ bo,
    const float* __restrict__ g1,  const float* __restrict__ b1,
    const float* __restrict__ fw1, const float* __restrict__ fb1,
    const float* __restrict__ fw2, const float* __restrict__ fb2,
    const float* __restrict__ g2,  const float* __restrict__ b2){
  extern __shared__ float fsm[];
  float* xs  = fsm;            // [16][128]
  float* xsT = fsm + 2048;     // [128][16]  (reused as o3 after step 2)
  float* hsT = fsm + 4096;     // [512][16]
  float* o3  = fsm + 2048;     // alias of xsT

  int bidx = blockIdx.x;
  int b  = bidx / (T/16);
  int t0 = (bidx % (T/16)) * 16;
  int tid = threadIdx.x, w = tid >> 5, lane = tid & 31;  // 16 warps, warp = row
  int t = t0 + w;

  // step 1: a = y@Wo + bo ; LN1(x + a) -> xs, xsT
  {
    float yv[DKh];
    #pragma unroll
    for (int e = 0; e < DKh; ++e) yv[e] = g_y[(b*T + t)*DKh + e];
    float tv[4];
    #pragma unroll
    for (int i = 0; i < 4; ++i){
      int c = lane + 32*i;
      float a = bo[l*D + c];
      #pragma unroll
      for (int e = 0; e < DKh; ++e) a = fmaf(yv[e], Wo[l*DKh*D + e*D + c], a);
      tv[i] = g_x[(b*T + t)*D + c] + a;
    }
    float s = tv[0] + tv[1] + tv[2] + tv[3];
    #pragma unroll
    for (int off = 16; off; off >>= 1) s += __shfl_xor_sync(~0u, s, off);
    float m = s * (1.0f/D);
    float sq = 0.f;
    #pragma unroll
    for (int i = 0; i < 4; ++i){ float dv = tv[i] - m; sq = fmaf(dv, dv, sq); }
    #pragma unroll
    for (int off = 16; off; off >>= 1) sq += __shfl_xor_sync(~0u, sq, off);
    float rs = rsqrtf(sq * (1.0f/D) + 1e-5f);
    #pragma unroll
    for (int i = 0; i < 4; ++i){
      int c = lane + 32*i;
      float v = (tv[i] - m) * rs * g1[l*D + c] + b1[l*D + c];
      xs[w*D + c] = v;
      xsT[c*16 + w] = v;
    }
  }
  __syncthreads();

  // step 2: hT = relu(xs @ fw1 + fb1), transposed [DFF][16]; thread = one DFF column
  {
    int c = tid;
    float acc[16];
    float bb = fb1[l*DFF + c];
    #pragma unroll
    for (int r = 0; r < 16; ++r) acc[r] = bb;
    const float* W = fw1 + l*D*DFF;
    for (int e = 0; e < D; ++e){
      float w0 = W[e*DFF + c];
      float4 xA = *(const float4*)&xsT[e*16 + 0];
      float4 xB = *(const float4*)&xsT[e*16 + 4];
      float4 xC = *(const float4*)&xsT[e*16 + 8];
      float4 xD = *(const float4*)&xsT[e*16 + 12];
      acc[0]=fmaf(w0,xA.x,acc[0]);  acc[1]=fmaf(w0,xA.y,acc[1]);  acc[2]=fmaf(w0,xA.z,acc[2]);  acc[3]=fmaf(w0,xA.w,acc[3]);
      acc[4]=fmaf(w0,xB.x,acc[4]);  acc[5]=fmaf(w0,xB.y,acc[5]);  acc[6]=fmaf(w0,xB.z,acc[6]);  acc[7]=fmaf(w0,xB.w,acc[7]);
      acc[8]=fmaf(w0,xC.x,acc[8]);  acc[9]=fmaf(w0,xC.y,acc[9]);  acc[10]=fmaf(w0,xC.z,acc[10]); acc[11]=fmaf(w0,xC.w,acc[11]);
      acc[12]=fmaf(w0,xD.x,acc[12]); acc[13]=fmaf(w0,xD.y,acc[13]); acc[14]=fmaf(w0,xD.z,acc[14]); acc[15]=fmaf(w0,xD.w,acc[15]);
    }
    #pragma unroll
    for (int r = 0; r < 16; ++r) acc[r] = fmaxf(acc[r], 0.f);
    *(float4*)&hsT[c*16 + 0]  = make_float4(acc[0],  acc[1],  acc[2],  acc[3]);
    *(float4*)&hsT[c*16 + 4]  = make_float4(acc[4],  acc[5],  acc[6],  acc[7]);
    *(float4*)&hsT[c*16 + 8]  = make_float4(acc[8],  acc[9],  acc[10], acc[11]);
    *(float4*)&hsT[c*16 + 12] = make_float4(acc[12], acc[13], acc[14], acc[15]);
  }
  __syncthreads();

  // step 3: o3 = h @ fw2 + fb2 + xs   (thread: col c, 4 rows; o3 aliases xsT)
  float res[4];
  {
    int c  = tid & 127;
    int rh = tid >> 7;           // 0..3 -> rows rh*4 .. rh*4+3
    float acc[4] = {0.f, 0.f, 0.f, 0.f};
    const float* W = fw2 + l*DFF*D;
    for (int s2 = 0; s2 < DFF; ++s2){
      float wv = W[s2*D + c];
      float4 hv = *(const float4*)&hsT[s2*16 + rh*4];
      acc[0] = fmaf(wv, hv.x, acc[0]);
      acc[1] = fmaf(wv, hv.y, acc[1]);
      acc[2] = fmaf(wv, hv.z, acc[2]);
      acc[3] = fmaf(wv, hv.w, acc[3]);
    }
    float bb = fb2[l*D + c];
    #pragma unroll
    for (int k = 0; k < 4; ++k) res[k] = acc[k] + bb + xs[(rh*4 + k)*D + c];
  }
  __syncthreads();   // xs reads done; xsT free for o3 alias
  {
    int c  = tid & 127;
    int rh = tid >> 7;
    #pragma unroll
    for (int k = 0; k < 4; ++k) o3[(rh*4 + k)*D + c] = res[k];
  }
  __syncthreads();

  // step 4: LN2 -> g_x (warp = row)
  {
    float tv[4];
    #pragma unroll
    for (int i = 0; i < 4; ++i) tv[i] = o3[w*D + lane + 32*i];
    float s = tv[0] + tv[1] + tv[2] + tv[3];
    #pragma unroll
    for (int off = 16; off; off >>= 1) s += __shfl_xor_sync(~0u, s, off);
    float m = s * (1.0f/D);
    float sq = 0.f;
    #pragma unroll
    for (int i = 0; i < 4; ++i){ float dv = tv[i] - m; sq = fmaf(dv, dv, sq); }
    #pragma unroll
    for (int off = 16; off; off >>= 1) sq += __shfl_xor_sync(~0u, sq, off);
    float rs = rsqrtf(sq * (1.0f/D) + 1e-5f);
    #pragma unroll
    for (int i = 0; i < 4; ++i){
      int c = lane + 32*i;
      g_x[(b*T + t)*D + c] = (tv[i] - m) * rs * g2[l*D + c] + b2[l*D + c];
    }
  }
}

// ---------------- final projection ----------------
__global__ void proj_kernel(const float* __restrict__ pw, const float* __restrict__ pb,
                            float* __restrict__ dout){
  int i = threadIdx.x;  // 576 threads
  int b = i / (NQ*HOR), q = (i / HOR) % NQ, hh = i % HOR;
  float acc = pb[q*HOR + hh];
  const float* xr = g_x + (b*T + (T-1))*D;
  for (int d = 0; d < D; ++d) acc = fmaf(xr[d], pw[(q*D + d)*HOR + hh], acc);
  dout[(b*NQ + q)*HOR + hh] = acc;
}

// ---------------- launch ----------------
extern "C" void kernel_launch(void* const* d_in, const int* in_sizes, int n_in,
                              void* d_out, int out_size) {
  const float* x_cond = (const float*)d_in[0];
  const float* x_pred = (const float*)d_in[1];
  const float* cw_c   = (const float*)d_in[2];
  const float* cb_c   = (const float*)d_in[3];
  const float* sw_c   = (const float*)d_in[4];
  const float* sb_c   = (const float*)d_in[5];
  const float* cw_p   = (const float*)d_in[6];
  const float* cb_p   = (const float*)d_in[7];
  const float* sw_p   = (const float*)d_in[8];
  const float* sb_p   = (const float*)d_in[9];
  const float* Wq     = (const float*)d_in[10];
  const float* bq     = (const float*)d_in[11];
  const float* Wk     = (const float*)d_in[12];
  const float* bk     = (const float*)d_in[13];
  const float* Wv     = (const float*)d_in[14];
  const float* bv     = (const float*)d_in[15];
  const float* Wo     = (const float*)d_in[16];
  const float* bo     = (const float*)d_in[17];
  const float* ln1_g  = (const float*)d_in[18];
  const float* ln1_b  = (const float*)d_in[19];
  const float* fw1    = (const float*)d_in[20];
  const float* fb1    = (const float*)d_in[21];
  const float* fw2    = (const float*)d_in[22];
  const float* fb2    = (const float*)d_in[23];
  const float* ln2_g  = (const float*)d_in[24];
  const float* ln2_b  = (const float*)d_in[25];
  const float* proj_w = (const float*)d_in[26];
  const float* proj_b = (const float*)d_in[27];
  float* out = (float*)d_out;

  const int smemA = 2 * CHF * (int)sizeof(float);   // 49152 B dynamic
  cudaFuncSetAttribute(attn_fused_kernel, cudaFuncAttributeMaxDynamicSharedMemorySize, smemA);
  const int smemF = 12288 * (int)sizeof(float);     // 49152 B dynamic
  cudaFuncSetAttribute(ffn_kernel, cudaFuncAttributeMaxDynamicSharedMemorySize, smemF);

  prep_kernel<<<1, 256>>>(cw_c, cb_c, sw_c, sb_c, cw_p, cb_p, sw_p, sb_p, Wv, bv);
  selector_kernel<NVC, TCOND, 0><<<(B*TCOND + 127)/128, 128>>>(x_cond, out, VC_OFS);
  selector_kernel<NVP, TPRED, 1><<<(B*TPRED + 127)/128, 128>>>(x_pred, out, VP_OFS);
  weighted_kernel<<<B*T, 128>>>(x_cond, x_pred, cw_c, cb_c, cw_p, cb_p);

  for (int l = 0; l < L; ++l){
    qkv_kernel<<<B*T/16, 256>>>(l, Wq, bq, Wk, bk);
    attn_fused_kernel<<<148, 256, smemA>>>(l, out);
    ffn_kernel<<<B*T/16, 512, smemF>>>(l, Wo, bo, ln1_g, ln1_b, fw1, fb1, fw2, fb2, ln2_g, ln2_b);
  }
  proj_kernel<<<1, B*NQ*HOR>>>(proj_w, proj_b, out);
}

// round 12
// speedup vs baseline: 1.0924x; 1.0924x over previous
#include <cuda_runtime.h>
#include <cuda_bf16.h>
#include <stdint.h>

// ---------------- problem constants ----------------
namespace {
constexpr int B = 2, TCOND = 1024, TPRED = 512, NVC = 8, NVP = 4;
constexpr int D = 128, KW = 3, H = 8, DFF = 512, L = 2, HOR = 96, NQ = 3;
constexpr int T = TCOND + TPRED;   // 1536
constexpr int DKh = D / H;         // 16
constexpr int NJ = T / 32;         // 48 (12 per chunk * 4 chunks)
constexpr int SL = DKh * T;        // 24576 floats per (b,h) kT slab
constexpr int RPT = 16;            // rows per tile (2 per warp, 8 warps)
constexpr int NTILE = B * (T / RPT); // 192 tiles
constexpr int CHW = 384;           // chunk width (columns)
constexpr int CHF = DKh * CHW;     // 6144 floats per chunk (24 KB)

constexpr int VC_OFS   = B * NQ * HOR;              // 576
constexpr int VP_OFS   = VC_OFS + B * TCOND * NVC;  // 16960
constexpr int LOGS_OFS = VP_OFS + B * TPRED * NVP;  // 21056
}

// ---------------- device scratch (static, no allocation) ----------------
__device__ float g_x[B*T*D];
__device__ float g_q[B*T*D];
__device__ float g_kT[B*H*SL];
__device__ float g_vcT[B*DKh*T];     // v_comb transposed: [b][e][T]
__device__ float g_y[B*T*DKh];
__device__ float g_wc[B*TCOND*NVC];
__device__ float g_wp[B*TPRED*NVP];
__device__ float g_Ac[NVC*KW], g_Cc[NVC], g_Ap[NVP*KW], g_Cp[NVP];
__device__ float g_Wvc[L*D*DKh], g_bvc[L*DKh];
__device__ unsigned g_key[4];
__device__ int g_ctr;                // attention tile work queue

// ---------------- threefry2x32 (matches JAX) ----------------
__device__ __forceinline__ unsigned rotl32(unsigned v, int r){ return (v<<r)|(v>>(32-r)); }

__device__ __forceinline__ void threefry(unsigned k0, unsigned k1,
                                         unsigned x0, unsigned x1,
                                         unsigned& o0, unsigned& o1){
  unsigned ks2 = k0 ^ k1 ^ 0x1BD11BDAu;
  unsigned ks[3] = {k0, k1, ks2};
  x0 += ks[0]; x1 += ks[1];
  const int R0[4] = {13,15,26,6};
  const int R1[4] = {17,29,16,24};
  #pragma unroll
  for (int i = 0; i < 5; ++i){
    #pragma unroll
    for (int j = 0; j < 4; ++j){
      int r = (i & 1) ? R1[j] : R0[j];
      x0 += x1; x1 = rotl32(x1, r); x1 ^= x0;
    }
    x0 += ks[(i+1)%3];
    x1 += ks[(i+2)%3] + (unsigned)(i+1);
  }
  o0 = x0; o1 = x1;
}

// ---------------- XLA f32 erfinv ----------------
__device__ __forceinline__ float erfinv32(float x){
  float w = -log1pf(-x*x);
  float p;
  if (w < 5.0f){
    w = w - 2.5f;
    p = 2.81022636e-08f;
    p = fmaf(p, w, 3.43273939e-07f);
    p = fmaf(p, w, -3.5233877e-06f);
    p = fmaf(p, w, -4.39150654e-06f);
    p = fmaf(p, w, 0.00021858087f);
    p = fmaf(p, w, -0.00125372503f);
    p = fmaf(p, w, -0.00417768164f);
    p = fmaf(p, w, 0.246640727f);
    p = fmaf(p, w, 1.50140941f);
  } else {
    w = sqrtf(w) - 3.0f;
    p = -0.000200214257f;
    p = fmaf(p, w, 0.000100950558f);
    p = fmaf(p, w, 0.00134934322f);
    p = fmaf(p, w, -0.00367342844f);
    p = fmaf(p, w, 0.00573950773f);
    p = fmaf(p, w, -0.0076224613f);
    p = fmaf(p, w, 0.00943887047f);
    p = fmaf(p, w, 1.00167406f);
    p = fmaf(p, w, 2.83297682f);
  }
  return p * x;
}

// ---------------- prep: keys, folded selector weights, head-averaged Wv ----------------
__global__ void prep_kernel(const float* __restrict__ cwc, const float* __restrict__ cbc,
                            const float* __restrict__ swc, const float* __restrict__ sbc,
                            const float* __restrict__ cwp, const float* __restrict__ cbp,
                            const float* __restrict__ swp, const float* __restrict__ sbp,
                            const float* __restrict__ Wv,  const float* __restrict__ bv){
  int tid = threadIdx.x;
  if (tid == 0) threefry(0u, 42u, 0u, 0u, g_key[0], g_key[1]);
  if (tid == 1) threefry(0u, 42u, 0u, 1u, g_key[2], g_key[3]);

  if (tid >= 2 && tid < 2 + NVC*KW){
    int i = tid - 2, g = i / KW, k = i % KW;
    float s = 0.f;
    for (int d = 0; d < D; ++d) s = fmaf(cwc[(g*D + d)*KW + k], swc[d], s);
    g_Ac[i] = s;
  } else if (tid >= 26 && tid < 26 + NVC){
    int g = tid - 26;
    float s = 0.f;
    for (int d = 0; d < D; ++d) s = fmaf(cbc[g*D + d], swc[d], s);
    g_Cc[g] = s + sbc[0];
  } else if (tid >= 34 && tid < 34 + NVP*KW){
    int i = tid - 34, g = i / KW, k = i % KW;
    float s = 0.f;
    for (int d = 0; d < D; ++d) s = fmaf(cwp[(g*D + d)*KW + k], swp[d], s);
    g_Ap[i] = s;
  } else if (tid >= 46 && tid < 46 + NVP){
    int g = tid - 46;
    float s = 0.f;
    for (int d = 0; d < D; ++d) s = fmaf(cbp[g*D + d], swp[d], s);
    g_Cp[g] = s + sbp[0];
  } else if (tid >= 50 && tid < 50 + L*DKh){
    int i = tid - 50, l = i / DKh, d = i % DKh;
    float s = 0.f;
    for (int h = 0; h < H; ++h) s += bv[l*D + h*DKh + d];
    g_bvc[i] = s * (1.0f/H);
  }

  for (int i = tid; i < L*D*DKh; i += blockDim.x){
    int l = i / (D*DKh), e = (i / DKh) % D, d = i % DKh;
    float s = 0.f;
    for (int h = 0; h < H; ++h) s += Wv[l*D*D + e*D + h*DKh + d];
    g_Wvc[i] = s * (1.0f/H);
  }
}

// ---------------- selector ----------------
template<int NV, int TS, int WHICH>
__global__ void selector_kernel(const float* __restrict__ xin,
                                float* __restrict__ dout, int oofs){
  int r = blockIdx.x * blockDim.x + threadIdx.x;
  if (r >= B*TS) return;
  int b = r / TS, t = r % TS;

  const float* A = (WHICH == 0) ? g_Ac : g_Ap;
  const float* C = (WHICH == 0) ? g_Cc : g_Cp;
  float* wscr    = (WHICH == 0) ? g_wc : g_wp;
  unsigned k0 = g_key[WHICH*2], k1 = g_key[WHICH*2 + 1];

  const int N = B*TS*NV, half = N >> 1;
  float z[NV];
  float m = -1e30f;
  #pragma unroll
  for (int g = 0; g < NV; ++g){
    float x0  = xin[(b*TS + t)*NV + g];
    float xm1 = (t >= 1) ? xin[(b*TS + t - 1)*NV + g] : 0.f;
    float xm2 = (t >= 2) ? xin[(b*TS + t - 2)*NV + g] : 0.f;
    float s = A[g*KW+0]*xm2 + A[g*KW+1]*xm1 + A[g*KW+2]*x0 + C[g];
    s = fminf(10.f, fmaxf(-10.f, s));
    int idx = (b*TS + t)*NV + g;
    unsigned o0, o1, bits;
    if (idx < half){ threefry(k0, k1, (unsigned)idx, (unsigned)(idx + half), o0, o1); bits = o0; }
    else           { threefry(k0, k1, (unsigned)(idx - half), (unsigned)idx, o0, o1); bits = o1; }
    float fu = __uint_as_float((bits >> 9) | 0x3f800000u) - 1.0f;
    const float lom = -0.99999994f, him = 1.0f;
    float u = fmaxf(lom, fmaf(fu, him - lom, lom));
    s = s + 1e-4f * (1.41421356f * erfinv32(u));
    z[g] = 0.5f * s;
    m = fmaxf(m, z[g]);
  }
  #pragma unroll
  for (int g = 0; g < NV; ++g) z[g] -= m;

  float tau = -1.0f;
  #pragma unroll 1
  for (int it = 0; it < 22; ++it){
    float f = 0.f, gg = 0.f;
    #pragma unroll
    for (int g = 0; g < NV; ++g){
      float dd = fmaxf(z[g] - tau, 0.f);
      f = fmaf(dd, dd, f); gg += dd;
    }
    tau += (f - 1.0f) / fmaxf(2.0f*gg, 1e-30f);
  }
  #pragma unroll
  for (int g = 0; g < NV; ++g){
    float dd = fmaxf(z[g] - tau, 0.f);
    float p = dd*dd;
    wscr[r*NV + g] = p;
    dout[oofs + r*NV + g] = p;
  }
}

// ---------------- weighted conv features -> concat x (B,T,128) ----------------
__global__ void weighted_kernel(const float* __restrict__ xc, const float* __restrict__ xp,
                                const float* __restrict__ cwc, const float* __restrict__ cbc,
                                const float* __restrict__ cwp, const float* __restrict__ cbp){
  int bt = blockIdx.x;
  int d = threadIdx.x;
  int b = bt / T, t = bt % T;
  const float *xin, *cw, *cb, *wsel;
  int nv, Ts, tt;
  if (t < TCOND){ xin = xc; cw = cwc; cb = cbc; wsel = g_wc; nv = NVC; Ts = TCOND; tt = t; }
  else          { xin = xp; cw = cwp; cb = cbp; wsel = g_wp; nv = NVP; Ts = TPRED; tt = t - TCOND; }
  float acc = 0.f;
  for (int g = 0; g < nv; ++g){
    float w = wsel[(b*Ts + tt)*nv + g];
    float x0  = xin[(b*Ts + tt)*nv + g];
    float xm1 = (tt >= 1) ? xin[(b*Ts + tt - 1)*nv + g] : 0.f;
    float xm2 = (tt >= 2) ? xin[(b*Ts + tt - 2)*nv + g] : 0.f;
    const float* cwg = cw + (g*D + d)*KW;
    float ls = cb[g*D + d] + cwg[0]*xm2 + cwg[1]*xm1 + cwg[2]*x0;
    acc = fmaf(w, ls, acc);
  }
  g_x[(b*T + t)*D + d] = acc;
}

// ---------------- QKV (+ head-averaged V, transposed): 16 rows per block ----------------
__global__ void __launch_bounds__(256) qkv_kernel(int l,
                           const float* __restrict__ Wq, const float* __restrict__ bq,
                           const float* __restrict__ Wk, const float* __restrict__ bk){
  __shared__ float xrT[D][16];           // 8 KB, transposed activations
  if (blockIdx.x == 0 && threadIdx.x == 0) g_ctr = 0;   // reset attn work queue
  int b  = blockIdx.x / (T/16);
  int t0 = (blockIdx.x % (T/16)) * 16;
  int tid = threadIdx.x;  // 256
  for (int i = tid; i < 16*D; i += 256){
    int r = i >> 7, e = i & 127;
    xrT[e][r] = g_x[(b*T + t0 + r)*D + e];
  }
  __syncthreads();

  for (int col = tid; col < 2*D + DKh; col += 256){
    const float* W; float bias; int c, ld, kind;
    if (col < D)        { c = col;       W = Wq + l*D*D;       bias = bq[l*D + c];     ld = D;   kind = 0; }
    else if (col < 2*D) { c = col - D;   W = Wk + l*D*D;       bias = bk[l*D + c];     ld = D;   kind = 1; }
    else                { c = col - 2*D; W = g_Wvc + l*D*DKh;  bias = g_bvc[l*DKh+c];  ld = DKh; kind = 2; }
    float acc[16];
    #pragma unroll
    for (int r = 0; r < 16; ++r) acc[r] = bias;
    for (int e = 0; e < D; ++e){
      float w = W[e*ld + c];
      float4 xA = *(const float4*)&xrT[e][0];
      float4 xB = *(const float4*)&xrT[e][4];
      float4 xC = *(const float4*)&xrT[e][8];
      float4 xD = *(const float4*)&xrT[e][12];
      acc[0]=fmaf(w,xA.x,acc[0]);  acc[1]=fmaf(w,xA.y,acc[1]);  acc[2]=fmaf(w,xA.z,acc[2]);  acc[3]=fmaf(w,xA.w,acc[3]);
      acc[4]=fmaf(w,xB.x,acc[4]);  acc[5]=fmaf(w,xB.y,acc[5]);  acc[6]=fmaf(w,xB.z,acc[6]);  acc[7]=fmaf(w,xB.w,acc[7]);
      acc[8]=fmaf(w,xC.x,acc[8]);  acc[9]=fmaf(w,xC.y,acc[9]);  acc[10]=fmaf(w,xC.z,acc[10]); acc[11]=fmaf(w,xC.w,acc[11]);
      acc[12]=fmaf(w,xD.x,acc[12]); acc[13]=fmaf(w,xD.y,acc[13]); acc[14]=fmaf(w,xD.z,acc[14]); acc[15]=fmaf(w,xD.w,acc[15]);
    }
    #pragma unroll
    for (int r = 0; r < 16; ++r){
      int t = t0 + r;
      if (kind == 0)      g_q[(b*T + t)*D + c] = acc[r];
      else if (kind == 1){ int h = c / DKh, d = c % DKh;
                           g_kT[((b*H + h)*DKh + d)*T + t] = acc[r]; }
      else                g_vcT[((size_t)b*DKh + c)*T + t] = acc[r];
    }
  }
}

// ---------------- chunk loader: 16 rows x 384 cols from row-strided source ----------------
// 256 threads: 6 x 16B per thread
__device__ __forceinline__ void issue_chunk(unsigned sdst, const float* gsrc, int tid){
  #pragma unroll
  for (int i = 0; i < 6; ++i){
    int u = i*256 + tid;
    int e = u / 96, off = u - e*96;
    unsigned sa = sdst + (unsigned)(e*1536 + off*16);
    const char* ga = (const char*)gsrc + (size_t)e*T*4 + (size_t)off*16;
    asm volatile("cp.async.cg.shared.global [%0], [%1], 16;\n" :: "r"(sa), "l"(ga) : "memory");
  }
  asm volatile("cp.async.commit_group;\n" ::: "memory");
}

// ---------------- fused attention: persistent, work-stealing, 2 rows per warp ----------------
// block = 256 threads (8 warps x 2 rows = 16-row tile); smem = 2 x 24KB chunk buffers
__global__ void __launch_bounds__(256, 1) attn_fused_kernel(int l, float* __restrict__ dout){
  extern __shared__ float chbuf[];         // 2 * CHF floats (48 KB)
  __shared__ float qs[RPT*D];              // 8 KB q tile
  __shared__ int s_tile;

  const int tid = threadIdx.x, w = tid >> 5, lane = tid & 31;
  const unsigned sbase = (unsigned)__cvta_generic_to_shared(chbuf);
  int cur = 0;

  for (;;){
    __syncthreads();
    if (tid == 0) s_tile = atomicAdd(&g_ctr, 1);
    __syncthreads();
    int u = s_tile;
    if (u >= NTILE) break;

    // descending-cost (LPT) ordering
    int tr = (T/RPT - 1) - (u >> 1);
    int b  = u & 1;
    int t0 = tr*RPT + w*2;                 // this warp's rows: t0, t0+1
    int t1 = t0 + 1;
    int tmax = tr*RPT + (RPT-1);
    int ncc  = tmax/CHW + 1;               // active chunks (1..4), block-uniform

    // stage q tile [16][128]
    for (int i = tid; i < RPT*D; i += 256)
      qs[i] = g_q[(size_t)(b*T + tr*RPT + (i >> 7))*D + (i & 127)];

    const float* kbase = g_kT + (size_t)b*H*SL;
    const float* vbase = g_vcT + (size_t)b*DKh*T;

    // prologue: issue k chunk (h=0, c=0) into buf[cur]
    issue_chunk(sbase + (unsigned)cur*(CHF*4), kbase, tid);

    float wa0[NJ], wa1[NJ];
    #pragma unroll
    for (int j = 0; j < NJ; ++j){ wa0[j] = 0.f; wa1[j] = 0.f; }

    #pragma unroll 1
    for (int h = 0; h < H; ++h){
      float z0[NJ], z1[NJ];
      #pragma unroll
      for (int c = 0; c < 4; ++c){
        if (c < ncc){
          asm volatile("cp.async.wait_group 0;\n" ::: "memory");
          __syncthreads();
          // issue next chunk into other buffer
          if (c + 1 < ncc)      issue_chunk(sbase + (unsigned)(cur^1)*(CHF*4), kbase + (size_t)h*SL + (c+1)*CHW, tid);
          else if (h + 1 < H)   issue_chunk(sbase + (unsigned)(cur^1)*(CHF*4), kbase + (size_t)(h+1)*SL, tid);
          else                  issue_chunk(sbase + (unsigned)(cur^1)*(CHF*4), vbase, tid);
          // scores for chunk c: lane owns columns c*384 + g*128 + lane*4 + r
          const float* kb = chbuf + cur*CHF;
          #pragma unroll
          for (int g = 0; g < 3; ++g){
            #pragma unroll
            for (int r = 0; r < 4; ++r){ z0[c*12 + g*4 + r] = 0.f; z1[c*12 + g*4 + r] = 0.f; }
          }
          #pragma unroll 4
          for (int e = 0; e < DKh; ++e){
            float qe0 = qs[(w*2+0)*D + h*DKh + e];
            float qe1 = qs[(w*2+1)*D + h*DKh + e];
            const float4* kr = (const float4*)(kb + e*CHW);
            #pragma unroll
            for (int g = 0; g < 3; ++g){
              float4 kv = kr[g*32 + lane];
              z0[c*12 + g*4 + 0] = fmaf(qe0, kv.x, z0[c*12 + g*4 + 0]);
              z0[c*12 + g*4 + 1] = fmaf(qe0, kv.y, z0[c*12 + g*4 + 1]);
              z0[c*12 + g*4 + 2] = fmaf(qe0, kv.z, z0[c*12 + g*4 + 2]);
              z0[c*12 + g*4 + 3] = fmaf(qe0, kv.w, z0[c*12 + g*4 + 3]);
              z1[c*12 + g*4 + 0] = fmaf(qe1, kv.x, z1[c*12 + g*4 + 0]);
              z1[c*12 + g*4 + 1] = fmaf(qe1, kv.y, z1[c*12 + g*4 + 1]);
              z1[c*12 + g*4 + 2] = fmaf(qe1, kv.z, z1[c*12 + g*4 + 2]);
              z1[c*12 + g*4 + 3] = fmaf(qe1, kv.w, z1[c*12 + g*4 + 3]);
            }
          }
          cur ^= 1;
        }
      }

      // mask + zmax (both rows)
      float m0 = -3.0e30f, m1 = -3.0e30f;
      #pragma unroll
      for (int c = 0; c < 4; ++c){
        if (c < ncc){
          #pragma unroll
          for (int g = 0; g < 3; ++g){
            int sb4 = c*CHW + g*128 + (lane << 2);
            #pragma unroll
            for (int r = 0; r < 4; ++r){
              int j = c*12 + g*4 + r;
              int col = sb4 + r;
              float a0 = (col <= t0) ? z0[j]*0.125f : -5000.0f;
              float a1 = (col <= t1) ? z1[j]*0.125f : -5000.0f;
              z0[j] = a0; z1[j] = a1;
              m0 = fmaxf(m0, a0); m1 = fmaxf(m1, a1);
            }
          }
        }
      }
      #pragma unroll
      for (int off = 16; off; off >>= 1){
        m0 = fmaxf(m0, __shfl_xor_sync(~0u, m0, off));
        m1 = fmaxf(m1, __shfl_xor_sync(~0u, m1, off));
      }

      // active-set exact-quadratic solver for both rows (interleaved)
      float lo0 = m0 - 1.f, hi0 = m0, tau0 = m0 - 1.f;
      float lo1 = m1 - 1.f, hi1 = m1, tau1 = m1 - 1.f;
      #pragma unroll 1
      for (int it = 0; it < 6; ++it){
        float f0 = 0.f, g0 = 0.f, n0 = 0.f;
        float f1 = 0.f, g1 = 0.f, n1 = 0.f;
        #pragma unroll
        for (int c = 0; c < 4; ++c){
          if (c < ncc){
            #pragma unroll
            for (int jj = 0; jj < 12; ++jj){
              int j = c*12 + jj;
              float d0 = z0[j] - tau0, d1 = z1[j] - tau1;
              float p0 = fmaxf(d0, 0.f), p1 = fmaxf(d1, 0.f);
              f0 = fmaf(p0, p0, f0); g0 += p0; n0 += (d0 > 0.f) ? 1.f : 0.f;
              f1 = fmaf(p1, p1, f1); g1 += p1; n1 += (d1 > 0.f) ? 1.f : 0.f;
            }
          }
        }
        #pragma unroll
        for (int off = 16; off; off >>= 1){
          f0 += __shfl_xor_sync(~0u, f0, off);
          f1 += __shfl_xor_sync(~0u, f1, off);
          g0 += __shfl_xor_sync(~0u, g0, off);
          g1 += __shfl_xor_sync(~0u, g1, off);
          n0 += __shfl_xor_sync(~0u, n0, off);
          n1 += __shfl_xor_sync(~0u, n1, off);
        }
        if (f0 > 1.f) lo0 = fmaxf(lo0, tau0); else hi0 = fminf(hi0, tau0);
        if (f1 > 1.f) lo1 = fmaxf(lo1, tau1); else hi1 = fminf(hi1, tau1);
        float d0 = fmaf(g0, g0, -n0*(f0 - 1.f));
        float d1 = fmaf(g1, g1, -n1*(f1 - 1.f));
        float nt0 = tau0 + (g0 - sqrtf(fmaxf(d0, 0.f))) / n0;
        float nt1 = tau1 + (g1 - sqrtf(fmaxf(d1, 0.f))) / n1;
        if (!(d0 > 0.f) || !(nt0 >= lo0 && nt0 <= hi0)) nt0 = 0.5f*(lo0 + hi0);
        if (!(d1 > 0.f) || !(nt1 >= lo1 && nt1 <= hi1)) nt1 = 0.5f*(lo1 + hi1);
        tau0 = nt0; tau1 = nt1;
      }
      #pragma unroll
      for (int c = 0; c < 4; ++c){
        if (c < ncc){
          #pragma unroll
          for (int jj = 0; jj < 12; ++jj){
            int j = c*12 + jj;
            float p0 = fmaxf(z0[j] - tau0, 0.f);
            float p1 = fmaxf(z1[j] - tau1, 0.f);
            wa0[j] = fmaf(p0, p0, wa0[j]);
            wa1[j] = fmaf(p1, p1, wa1[j]);
          }
        }
      }
    }

    // epilogue: head-average -> logs, y = w_avg @ v_comb (v chunks pipelined)
    float* logrow0 = dout + LOGS_OFS + (size_t)((l*B + b)*T + t0)*T;
    float* logrow1 = dout + LOGS_OFS + (size_t)((l*B + b)*T + t1)*T;
    float acc0[DKh], acc1[DKh];
    #pragma unroll
    for (int e = 0; e < DKh; ++e){ acc0[e] = 0.f; acc1[e] = 0.f; }

    #pragma unroll
    for (int c = 0; c < 4; ++c){
      if (c < ncc){
        asm volatile("cp.async.wait_group 0;\n" ::: "memory");
        __syncthreads();
        if (c + 1 < ncc) issue_chunk(sbase + (unsigned)(cur^1)*(CHF*4), vbase + (c+1)*CHW, tid);
        const float* vb = chbuf + cur*CHF;
        #pragma unroll
        for (int g = 0; g < 3; ++g){
          int j = c*12 + g*4;
          float a0 = wa0[j+0]*0.125f, a1 = wa0[j+1]*0.125f, a2 = wa0[j+2]*0.125f, a3 = wa0[j+3]*0.125f;
          float b0 = wa1[j+0]*0.125f, b1 = wa1[j+1]*0.125f, b2 = wa1[j+2]*0.125f, b3 = wa1[j+3]*0.125f;
          ((float4*)(logrow0 + c*CHW + g*128))[lane] = make_float4(a0, a1, a2, a3);
          ((float4*)(logrow1 + c*CHW + g*128))[lane] = make_float4(b0, b1, b2, b3);
          #pragma unroll
          for (int e = 0; e < DKh; ++e){
            float4 vv = ((const float4*)(vb + e*CHW + g*128))[lane];
            acc0[e] = fmaf(a0, vv.x, acc0[e]);
            acc0[e] = fmaf(a1, vv.y, acc0[e]);
            acc0[e] = fmaf(a2, vv.z, acc0[e]);
            acc0[e] = fmaf(a3, vv.w, acc0[e]);
            acc1[e] = fmaf(b0, vv.x, acc1[e]);
            acc1[e] = fmaf(b1, vv.y, acc1[e]);
            acc1[e] = fmaf(b2, vv.z, acc1[e]);
            acc1[e] = fmaf(b3, vv.w, acc1[e]);
          }
        }
        cur ^= 1;
      } else {
        #pragma unroll
        for (int g = 0; g < 3; ++g){
          ((float4*)(logrow0 + c*CHW + g*128))[lane] = make_float4(0.f, 0.f, 0.f, 0.f);
          ((float4*)(logrow1 + c*CHW + g*128))[lane] = make_float4(0.f, 0.f, 0.f, 0.f);
        }
      }
    }

    float myv0 = 0.f, myv1 = 0.f;
    #pragma unroll
    for (int e = 0; e < DKh; ++e){
      float v0 = acc0[e], v1 = acc1[e];
      #pragma unroll
      for (int off = 16; off; off >>= 1){
        v0 += __shfl_xor_sync(~0u, v0, off);
        v1 += __shfl_xor_sync(~0u, v1, off);
      }
      if (lane == e){ myv0 = v0; myv1 = v1; }
    }
    if (lane < DKh){
      g_y[(size_t)(b*T + t0)*DKh + lane] = myv0;
      g_y[(size_t)(b*T + t1)*DKh + lane] = myv1;
    }
  }
}

// ---------------- fused Wo + LN1 + FFN + LN2 : 8 rows per block ----------------
__global__ void __launch_bounds__(256) ffn_kernel(
    int l,
    const float* __restrict__ Wo,  const float* __restrict__ bo,
    const float* __restrict__ g1,  const float* __restrict__ b1,
    const float* __restrict__ fw1, const float* __restrict__ fb1,
    const float* __restrict__ fw2, const float* __restrict__ fb2,
    const float* __restrict__ g2,  const float* __restrict__ b2){
  __shared__ float xs[8][D];
  __shared__ float xsT[D][8];
  __shared__ float hsT[DFF][8];
  __shared__ float o3[8][D];
  int bidx = blockIdx.x;
  int b  = bidx / (T/8);
  int t0 = (bidx % (T/8)) * 8;
  int tid = threadIdx.x, w = tid >> 5, lane = tid & 31;
  int t = t0 + w;

  // step 1: a = y@Wo + bo ; LN1(x + a) -> xs, xsT
  {
    float yv[DKh];
    #pragma unroll
    for (int e = 0; e < DKh; ++e) yv[e] = g_y[(b*T + t)*DKh + e];
    float tv[4];
    #pragma unroll
    for (int i = 0; i < 4; ++i){
      int c = lane + 32*i;
      float a = bo[l*D + c];
      #pragma unroll
      for (int e = 0; e < DKh; ++e) a = fmaf(yv[e], Wo[l*DKh*D + e*D + c], a);
      tv[i] = g_x[(b*T + t)*D + c] + a;
    }
    float s = tv[0] + tv[1] + tv[2] + tv[3];
    #pragma unroll
    for (int off = 16; off; off >>= 1) s += __shfl_xor_sync(~0u, s, off);
    float m = s * (1.0f/D);
    float sq = 0.f;
    #pragma unroll
    for (int i = 0; i < 4; ++i){ float dv = tv[i] - m; sq = fmaf(dv, dv, sq); }
    #pragma unroll
    for (int off = 16; off; off >>= 1) sq += __shfl_xor_sync(~0u, sq, off);
    float rs = rsqrtf(sq * (1.0f/D) + 1e-5f);
    #pragma unroll
    for (int i = 0; i < 4; ++i){
      int c = lane + 32*i;
      float v = (tv[i] - m) * rs * g1[l*D + c] + b1[l*D + c];
      xs[w][c] = v;
      xsT[c][w] = v;
    }
  }
  __syncthreads();

  // step 2: hT = relu(xs @ fw1 + fb1), transposed [DFF][8]
  {
    int c = tid;                // columns c and c+256
    float a0[8], a1[8];
    float bb0 = fb1[l*DFF + c], bb1 = fb1[l*DFF + c + 256];
    #pragma unroll
    for (int r = 0; r < 8; ++r){ a0[r] = bb0; a1[r] = bb1; }
    const float* W = fw1 + l*D*DFF;
    for (int e = 0; e < D; ++e){
      float w0 = W[e*DFF + c];
      float w1 = W[e*DFF + c + 256];
      float4 xA = *(const float4*)&xsT[e][0];
      float4 xB = *(const float4*)&xsT[e][4];
      a0[0]=fmaf(w0,xA.x,a0[0]); a0[1]=fmaf(w0,xA.y,a0[1]); a0[2]=fmaf(w0,xA.z,a0[2]); a0[3]=fmaf(w0,xA.w,a0[3]);
      a0[4]=fmaf(w0,xB.x,a0[4]); a0[5]=fmaf(w0,xB.y,a0[5]); a0[6]=fmaf(w0,xB.z,a0[6]); a0[7]=fmaf(w0,xB.w,a0[7]);
      a1[0]=fmaf(w1,xA.x,a1[0]); a1[1]=fmaf(w1,xA.y,a1[1]); a1[2]=fmaf(w1,xA.z,a1[2]); a1[3]=fmaf(w1,xA.w,a1[3]);
      a1[4]=fmaf(w1,xB.x,a1[4]); a1[5]=fmaf(w1,xB.y,a1[5]); a1[6]=fmaf(w1,xB.z,a1[6]); a1[7]=fmaf(w1,xB.w,a1[7]);
    }
    #pragma unroll
    for (int r = 0; r < 8; ++r){ a0[r] = fmaxf(a0[r], 0.f); a1[r] = fmaxf(a1[r], 0.f); }
    *(float4*)&hsT[c][0]       = make_float4(a0[0], a0[1], a0[2], a0[3]);
    *(float4*)&hsT[c][4]       = make_float4(a0[4], a0[5], a0[6], a0[7]);
    *(float4*)&hsT[c + 256][0] = make_float4(a1[0], a1[1], a1[2], a1[3]);
    *(float4*)&hsT[c + 256][4] = make_float4(a1[4], a1[5], a1[6], a1[7]);
  }
  __syncthreads();

  // step 3: o3 = h @ fw2 + fb2 + xs   (thread: col c, 4 rows)
  {
    int c  = tid & 127;
    int rh = tid >> 7;           // 0 or 1 -> rows rh*4 .. rh*4+3
    float acc[4] = {0.f, 0.f, 0.f, 0.f};
    const float* W = fw2 + l*DFF*D;
    for (int s2 = 0; s2 < DFF; ++s2){
      float wv = W[s2*D + c];
      float4 hv = *(const float4*)&hsT[s2][rh*4];
      acc[0] = fmaf(wv, hv.x, acc[0]);
      acc[1] = fmaf(wv, hv.y, acc[1]);
      acc[2] = fmaf(wv, hv.z, acc[2]);
      acc[3] = fmaf(wv, hv.w, acc[3]);
    }
    float bb = fb2[l*D + c];
    #pragma unroll
    for (int k = 0; k < 4; ++k) o3[rh*4 + k][c] = acc[k] + bb + xs[rh*4 + k][c];
  }
  __syncthreads();

  // step 4: LN2 -> g_x
  {
    float tv[4];
    #pragma unroll
    for (int i = 0; i < 4; ++i) tv[i] = o3[w][lane + 32*i];
    float s = tv[0] + tv[1] + tv[2] + tv[3];
    #pragma unroll
    for (int off = 16; off; off >>= 1) s += __shfl_xor_sync(~0u, s, off);
    float m = s * (1.0f/D);
    float sq = 0.f;
    #pragma unroll
    for (int i = 0; i < 4; ++i){ float dv = tv[i] - m; sq = fmaf(dv, dv, sq); }
    #pragma unroll
    for (int off = 16; off; off >>= 1) sq += __shfl_xor_sync(~0u, sq, off);
    float rs = rsqrtf(sq * (1.0f/D) + 1e-5f);
    #pragma unroll
    for (int i = 0; i < 4; ++i){
      int c = lane + 32*i;
      g_x[(b*T + t)*D + c] = (tv[i] - m) * rs * g2[l*D + c] + b2[l*D + c];
    }
  }
}

// ---------------- final projection ----------------
__global__ void proj_kernel(const float* __restrict__ pw, const float* __restrict__ pb,
                            float* __restrict__ dout){
  int i = threadIdx.x;  // 576 threads
  int b = i / (NQ*HOR), q = (i / HOR) % NQ, hh = i % HOR;
  float acc = pb[q*HOR + hh];
  const float* xr = g_x + (b*T + (T-1))*D;
  for (int d = 0; d < D; ++d) acc = fmaf(xr[d], pw[(q*D + d)*HOR + hh], acc);
  dout[(b*NQ + q)*HOR + hh] = acc;
}

// ---------------- launch ----------------
extern "C" void kernel_launch(void* const* d_in, const int* in_sizes, int n_in,
                              void* d_out, int out_size) {
  const float* x_cond = (const float*)d_in[0];
  const float* x_pred = (const float*)d_in[1];
  const float* cw_c   = (const float*)d_in[2];
  const float* cb_c   = (const float*)d_in[3];
  const float* sw_c   = (const float*)d_in[4];
  const float* sb_c   = (const float*)d_in[5];
  const float* cw_p   = (const float*)d_in[6];
  const float* cb_p   = (const float*)d_in[7];
  const float* sw_p   = (const float*)d_in[8];
  const float* sb_p   = (const float*)d_in[9];
  const float* Wq     = (const float*)d_in[10];
  const float* bq     = (const float*)d_in[11];
  const float* Wk     = (const float*)d_in[12];
  const float* bk     = (const float*)d_in[13];
  const float* Wv     = (const float*)d_in[14];
  const float* bv     = (const float*)d_in[15];
  const float* Wo     = (const float*)d_in[16];
  const float* bo     = (const float*)d_in[17];
  const float* ln1_g  = (const float*)d_in[18];
  const float* ln1_b  = (const float*)d_in[19];
  const float* fw1    = (const float*)d_in[20];
  const float* fb1    = (const float*)d_in[21];
  const float* fw2    = (const float*)d_in[22];
  const float* fb2    = (const float*)d_in[23];
  const float* ln2_g  = (const float*)d_in[24];
  const float* ln2_b  = (const float*)d_in[25];
  const float* proj_w = (const float*)d_in[26];
  const float* proj_b = (const float*)d_in[27];
  float* out = (float*)d_out;

  const int smemA = 2 * CHF * (int)sizeof(float);   // 49152 B dynamic
  cudaFuncSetAttribute(attn_fused_kernel, cudaFuncAttributeMaxDynamicSharedMemorySize, smemA);

  prep_kernel<<<1, 256>>>(cw_c, cb_c, sw_c, sb_c, cw_p, cb_p, sw_p, sb_p, Wv, bv);
  selector_kernel<NVC, TCOND, 0><<<(B*TCOND + 127)/128, 128>>>(x_cond, out, VC_OFS);
  selector_kernel<NVP, TPRED, 1><<<(B*TPRED + 127)/128, 128>>>(x_pred, out, VP_OFS);
  weighted_kernel<<<B*T, 128>>>(x_cond, x_pred, cw_c, cb_c, cw_p, cb_p);

  for (int l = 0; l < L; ++l){
    qkv_kernel<<<B*T/16, 256>>>(l, Wq, bq, Wk, bk);
    attn_fused_kernel<<<148, 256, smemA>>>(l, out);
    ffn_kernel<<<B*T/8, 256>>>(l, Wo, bo, ln1_g, ln1_b, fw1, fb1, fw2, fb2, ln2_g, ln2_b);
  }
  proj_kernel<<<1, B*NQ*HOR>>>(proj_w, proj_b, out);
}

// round 13
// speedup vs baseline: 1.1057x; 1.0122x over previous
#include <cuda_runtime.h>
#include <cuda_bf16.h>
#include <stdint.h>

// ---------------- problem constants ----------------
namespace {
constexpr int B = 2, TCOND = 1024, TPRED = 512, NVC = 8, NVP = 4;
constexpr int D = 128, KW = 3, H = 8, DFF = 512, L = 2, HOR = 96, NQ = 3;
constexpr int T = TCOND + TPRED;   // 1536
constexpr int DKh = D / H;         // 16
constexpr int NJ = T / 32;         // 48 (12 per chunk * 4 chunks)
constexpr int SL = DKh * T;        // 24576 floats per (b,h) kT slab
constexpr int RPT = 16;            // rows per tile (2 per warp, 8 warps)
constexpr int NTILE = B * (T / RPT); // 192 tiles
constexpr int CHW = 384;           // chunk width (columns)
constexpr int CHF = DKh * CHW;     // 6144 floats per chunk (24 KB)

constexpr int VC_OFS   = B * NQ * HOR;              // 576
constexpr int VP_OFS   = VC_OFS + B * TCOND * NVC;  // 16960
constexpr int LOGS_OFS = VP_OFS + B * TPRED * NVP;  // 21056
}

// ---------------- device scratch (static, no allocation) ----------------
__device__ float g_x[B*T*D];
__device__ float g_q[B*T*D];
__device__ float g_kT[B*H*SL];
__device__ float g_vcT[B*DKh*T];     // v_comb transposed: [b][e][T]
__device__ float g_y[B*T*DKh];
__device__ float g_wc[B*TCOND*NVC];
__device__ float g_wp[B*TPRED*NVP];
__device__ float g_Ac[NVC*KW], g_Cc[NVC], g_Ap[NVP*KW], g_Cp[NVP];
__device__ float g_Wvc[L*D*DKh], g_bvc[L*DKh];
__device__ unsigned g_key[4];
__device__ int g_ctr;                // attention tile work queue

// ---------------- threefry2x32 (matches JAX) ----------------
__device__ __forceinline__ unsigned rotl32(unsigned v, int r){ return (v<<r)|(v>>(32-r)); }

__device__ __forceinline__ void threefry(unsigned k0, unsigned k1,
                                         unsigned x0, unsigned x1,
                                         unsigned& o0, unsigned& o1){
  unsigned ks2 = k0 ^ k1 ^ 0x1BD11BDAu;
  unsigned ks[3] = {k0, k1, ks2};
  x0 += ks[0]; x1 += ks[1];
  const int R0[4] = {13,15,26,6};
  const int R1[4] = {17,29,16,24};
  #pragma unroll
  for (int i = 0; i < 5; ++i){
    #pragma unroll
    for (int j = 0; j < 4; ++j){
      int r = (i & 1) ? R1[j] : R0[j];
      x0 += x1; x1 = rotl32(x1, r); x1 ^= x0;
    }
    x0 += ks[(i+1)%3];
    x1 += ks[(i+2)%3] + (unsigned)(i+1);
  }
  o0 = x0; o1 = x1;
}

// ---------------- XLA f32 erfinv ----------------
__device__ __forceinline__ float erfinv32(float x){
  float w = -log1pf(-x*x);
  float p;
  if (w < 5.0f){
    w = w - 2.5f;
    p = 2.81022636e-08f;
    p = fmaf(p, w, 3.43273939e-07f);
    p = fmaf(p, w, -3.5233877e-06f);
    p = fmaf(p, w, -4.39150654e-06f);
    p = fmaf(p, w, 0.00021858087f);
    p = fmaf(p, w, -0.00125372503f);
    p = fmaf(p, w, -0.00417768164f);
    p = fmaf(p, w, 0.246640727f);
    p = fmaf(p, w, 1.50140941f);
  } else {
    w = sqrtf(w) - 3.0f;
    p = -0.000200214257f;
    p = fmaf(p, w, 0.000100950558f);
    p = fmaf(p, w, 0.00134934322f);
    p = fmaf(p, w, -0.00367342844f);
    p = fmaf(p, w, 0.00573950773f);
    p = fmaf(p, w, -0.0076224613f);
    p = fmaf(p, w, 0.00943887047f);
    p = fmaf(p, w, 1.00167406f);
    p = fmaf(p, w, 2.83297682f);
  }
  return p * x;
}

// ---------------- prep: keys, folded selector weights, head-averaged Wv ----------------
__global__ void prep_kernel(const float* __restrict__ cwc, const float* __restrict__ cbc,
                            const float* __restrict__ swc, const float* __restrict__ sbc,
                            const float* __restrict__ cwp, const float* __restrict__ cbp,
                            const float* __restrict__ swp, const float* __restrict__ sbp,
                            const float* __restrict__ Wv,  const float* __restrict__ bv){
  int tid = threadIdx.x;
  if (tid == 0) threefry(0u, 42u, 0u, 0u, g_key[0], g_key[1]);
  if (tid == 1) threefry(0u, 42u, 0u, 1u, g_key[2], g_key[3]);

  if (tid >= 2 && tid < 2 + NVC*KW){
    int i = tid - 2, g = i / KW, k = i % KW;
    float s = 0.f;
    for (int d = 0; d < D; ++d) s = fmaf(cwc[(g*D + d)*KW + k], swc[d], s);
    g_Ac[i] = s;
  } else if (tid >= 26 && tid < 26 + NVC){
    int g = tid - 26;
    float s = 0.f;
    for (int d = 0; d < D; ++d) s = fmaf(cbc[g*D + d], swc[d], s);
    g_Cc[g] = s + sbc[0];
  } else if (tid >= 34 && tid < 34 + NVP*KW){
    int i = tid - 34, g = i / KW, k = i % KW;
    float s = 0.f;
    for (int d = 0; d < D; ++d) s = fmaf(cwp[(g*D + d)*KW + k], swp[d], s);
    g_Ap[i] = s;
  } else if (tid >= 46 && tid < 46 + NVP){
    int g = tid - 46;
    float s = 0.f;
    for (int d = 0; d < D; ++d) s = fmaf(cbp[g*D + d], swp[d], s);
    g_Cp[g] = s + sbp[0];
  } else if (tid >= 50 && tid < 50 + L*DKh){
    int i = tid - 50, l = i / DKh, d = i % DKh;
    float s = 0.f;
    for (int h = 0; h < H; ++h) s += bv[l*D + h*DKh + d];
    g_bvc[i] = s * (1.0f/H);
  }

  for (int i = tid; i < L*D*DKh; i += blockDim.x){
    int l = i / (D*DKh), e = (i / DKh) % D, d = i % DKh;
    float s = 0.f;
    for (int h = 0; h < H; ++h) s += Wv[l*D*D + e*D + h*DKh + d];
    g_Wvc[i] = s * (1.0f/H);
  }
}

// ---------------- selector ----------------
template<int NV, int TS, int WHICH>
__global__ void selector_kernel(const float* __restrict__ xin,
                                float* __restrict__ dout, int oofs){
  int r = blockIdx.x * blockDim.x + threadIdx.x;
  if (r >= B*TS) return;
  int b = r / TS, t = r % TS;

  const float* A = (WHICH == 0) ? g_Ac : g_Ap;
  const float* C = (WHICH == 0) ? g_Cc : g_Cp;
  float* wscr    = (WHICH == 0) ? g_wc : g_wp;
  unsigned k0 = g_key[WHICH*2], k1 = g_key[WHICH*2 + 1];

  const int N = B*TS*NV, half = N >> 1;
  float z[NV];
  float m = -1e30f;
  #pragma unroll
  for (int g = 0; g < NV; ++g){
    float x0  = xin[(b*TS + t)*NV + g];
    float xm1 = (t >= 1) ? xin[(b*TS + t - 1)*NV + g] : 0.f;
    float xm2 = (t >= 2) ? xin[(b*TS + t - 2)*NV + g] : 0.f;
    float s = A[g*KW+0]*xm2 + A[g*KW+1]*xm1 + A[g*KW+2]*x0 + C[g];
    s = fminf(10.f, fmaxf(-10.f, s));
    int idx = (b*TS + t)*NV + g;
    unsigned o0, o1, bits;
    if (idx < half){ threefry(k0, k1, (unsigned)idx, (unsigned)(idx + half), o0, o1); bits = o0; }
    else           { threefry(k0, k1, (unsigned)(idx - half), (unsigned)idx, o0, o1); bits = o1; }
    float fu = __uint_as_float((bits >> 9) | 0x3f800000u) - 1.0f;
    const float lom = -0.99999994f, him = 1.0f;
    float u = fmaxf(lom, fmaf(fu, him - lom, lom));
    s = s + 1e-4f * (1.41421356f * erfinv32(u));
    z[g] = 0.5f * s;
    m = fmaxf(m, z[g]);
  }
  #pragma unroll
  for (int g = 0; g < NV; ++g) z[g] -= m;

  float tau = -1.0f;
  #pragma unroll 1
  for (int it = 0; it < 22; ++it){
    float f = 0.f, gg = 0.f;
    #pragma unroll
    for (int g = 0; g < NV; ++g){
      float dd = fmaxf(z[g] - tau, 0.f);
      f = fmaf(dd, dd, f); gg += dd;
    }
    tau += (f - 1.0f) / fmaxf(2.0f*gg, 1e-30f);
  }
  #pragma unroll
  for (int g = 0; g < NV; ++g){
    float dd = fmaxf(z[g] - tau, 0.f);
    float p = dd*dd;
    wscr[r*NV + g] = p;
    dout[oofs + r*NV + g] = p;
  }
}

// ---------------- weighted conv features -> concat x : 16-t tiles, staged weights ----------------
__global__ void __launch_bounds__(128) weighted_kernel(
    const float* __restrict__ xc, const float* __restrict__ xp,
    const float* __restrict__ cwc, const float* __restrict__ cbc,
    const float* __restrict__ cwp, const float* __restrict__ cbp){
  __shared__ float cw_s[NVC*D*KW];   // up to 12 KB
  __shared__ float cb_s[NVC*D];      // up to 4 KB
  __shared__ float xw[18*NVC];       // x window: rows t0-2..t0+15
  __shared__ float ws[16*NVC];       // selector weights

  int bt = blockIdx.x;
  int b  = bt / (T/16);
  int t0 = (bt % (T/16)) * 16;
  int d  = threadIdx.x;              // 128

  const float *xin, *cw, *cb, *wsel;
  int nv, Ts, tt0;
  if (t0 < TCOND){ xin = xc; cw = cwc; cb = cbc; wsel = g_wc; nv = NVC; Ts = TCOND; tt0 = t0; }
  else           { xin = xp; cw = cwp; cb = cbp; wsel = g_wp; nv = NVP; Ts = TPRED; tt0 = t0 - TCOND; }

  for (int i = d; i < nv*D*KW; i += 128) cw_s[i] = cw[i];
  for (int i = d; i < nv*D;    i += 128) cb_s[i] = cb[i];
  for (int i = d; i < 18*nv;   i += 128){
    int row = i / nv, g = i % nv;
    int tt = tt0 - 2 + row;
    xw[i] = (tt >= 0) ? xin[(b*Ts + tt)*nv + g] : 0.f;
  }
  for (int i = d; i < 16*nv; i += 128){
    int row = i / nv, g = i % nv;
    ws[i] = wsel[(b*Ts + tt0 + row)*nv + g];
  }
  __syncthreads();

  #pragma unroll 1
  for (int r = 0; r < 16; ++r){
    float acc = 0.f;
    #pragma unroll 1
    for (int g = 0; g < nv; ++g){
      float xm2 = xw[(r+0)*nv + g];
      float xm1 = xw[(r+1)*nv + g];
      float x0  = xw[(r+2)*nv + g];
      const float* cwg = cw_s + (g*D + d)*KW;
      float ls = cb_s[g*D + d] + cwg[0]*xm2 + cwg[1]*xm1 + cwg[2]*x0;
      acc = fmaf(ws[r*nv + g], ls, acc);
    }
    g_x[(size_t)(b*T + t0 + r)*D + d] = acc;
  }
}

// ---------------- QKV (+ head-averaged V, transposed): 8 rows per block ----------------
__global__ void qkv_kernel(int l, const float* __restrict__ Wq, const float* __restrict__ bq,
                           const float* __restrict__ Wk, const float* __restrict__ bk){
  __shared__ float xr[8][D];
  if (blockIdx.x == 0 && threadIdx.x == 0) g_ctr = 0;   // reset attn work queue
  int b  = blockIdx.x / (T/8);
  int t0 = (blockIdx.x % (T/8)) * 8;
  int tid = threadIdx.x;  // 256
  for (int i = tid; i < 8*D; i += 256) xr[i/D][i%D] = g_x[(b*T + t0 + i/D)*D + (i%D)];
  __syncthreads();

  for (int col = tid; col < 2*D + DKh; col += 256){
    const float* W; float bias; int c, ld, kind;
    if (col < D)        { c = col;       W = Wq + l*D*D;       bias = bq[l*D + c];     ld = D;   kind = 0; }
    else if (col < 2*D) { c = col - D;   W = Wk + l*D*D;       bias = bk[l*D + c];     ld = D;   kind = 1; }
    else                { c = col - 2*D; W = g_Wvc + l*D*DKh;  bias = g_bvc[l*DKh+c];  ld = DKh; kind = 2; }
    float acc[8];
    #pragma unroll
    for (int r = 0; r < 8; ++r) acc[r] = bias;
    for (int e = 0; e < D; ++e){
      float w = W[e*ld + c];
      #pragma unroll
      for (int r = 0; r < 8; ++r) acc[r] = fmaf(xr[r][e], w, acc[r]);
    }
    #pragma unroll
    for (int r = 0; r < 8; ++r){
      int t = t0 + r;
      if (kind == 0)      g_q[(b*T + t)*D + c] = acc[r];
      else if (kind == 1){ int h = c / DKh, d = c % DKh;
                           g_kT[((b*H + h)*DKh + d)*T + t] = acc[r]; }
      else                g_vcT[((size_t)b*DKh + c)*T + t] = acc[r];
    }
  }
}

// ---------------- chunk loader: 16 rows x 384 cols from row-strided source ----------------
// 256 threads: 6 x 16B per thread
__device__ __forceinline__ void issue_chunk(unsigned sdst, const float* gsrc, int tid){
  #pragma unroll
  for (int i = 0; i < 6; ++i){
    int u = i*256 + tid;
    int e = u / 96, off = u - e*96;
    unsigned sa = sdst + (unsigned)(e*1536 + off*16);
    const char* ga = (const char*)gsrc + (size_t)e*T*4 + (size_t)off*16;
    asm volatile("cp.async.cg.shared.global [%0], [%1], 16;\n" :: "r"(sa), "l"(ga) : "memory");
  }
  asm volatile("cp.async.commit_group;\n" ::: "memory");
}

// ---------------- fused attention: persistent, work-stealing, 2 rows per warp ----------------
// block = 256 threads (8 warps x 2 rows = 16-row tile); smem = 2 x 24KB chunk buffers
__global__ void __launch_bounds__(256, 1) attn_fused_kernel(int l, float* __restrict__ dout){
  extern __shared__ float chbuf[];         // 2 * CHF floats (48 KB)
  __shared__ float qs[RPT*D];              // 8 KB q tile
  __shared__ int s_tile;

  const int tid = threadIdx.x, w = tid >> 5, lane = tid & 31;
  const unsigned sbase = (unsigned)__cvta_generic_to_shared(chbuf);
  int cur = 0;

  for (;;){
    __syncthreads();
    if (tid == 0) s_tile = atomicAdd(&g_ctr, 1);
    __syncthreads();
    int u = s_tile;
    if (u >= NTILE) break;

    // descending-cost (LPT) ordering
    int tr = (T/RPT - 1) - (u >> 1);
    int b  = u & 1;
    int t0 = tr*RPT + w*2;                 // this warp's rows: t0, t0+1
    int t1 = t0 + 1;
    int tmax = tr*RPT + (RPT-1);
    int ncc  = tmax/CHW + 1;               // active chunks (1..4), block-uniform

    // stage q tile [16][128]
    for (int i = tid; i < RPT*D; i += 256)
      qs[i] = g_q[(size_t)(b*T + tr*RPT + (i >> 7))*D + (i & 127)];

    const float* kbase = g_kT + (size_t)b*H*SL;
    const float* vbase = g_vcT + (size_t)b*DKh*T;

    // prologue: issue k chunk (h=0, c=0) into buf[cur]
    issue_chunk(sbase + (unsigned)cur*(CHF*4), kbase, tid);

    float wa0[NJ], wa1[NJ];
    #pragma unroll
    for (int j = 0; j < NJ; ++j){ wa0[j] = 0.f; wa1[j] = 0.f; }

    #pragma unroll 1
    for (int h = 0; h < H; ++h){
      float z0[NJ], z1[NJ];
      #pragma unroll
      for (int c = 0; c < 4; ++c){
        if (c < ncc){
          asm volatile("cp.async.wait_group 0;\n" ::: "memory");
          __syncthreads();
          // issue next chunk into other buffer
          if (c + 1 < ncc)      issue_chunk(sbase + (unsigned)(cur^1)*(CHF*4), kbase + (size_t)h*SL + (c+1)*CHW, tid);
          else if (h + 1 < H)   issue_chunk(sbase + (unsigned)(cur^1)*(CHF*4), kbase + (size_t)(h+1)*SL, tid);
          else                  issue_chunk(sbase + (unsigned)(cur^1)*(CHF*4), vbase, tid);
          // scores for chunk c: lane owns columns c*384 + g*128 + lane*4 + r
          const float* kb = chbuf + cur*CHF;
          #pragma unroll
          for (int g = 0; g < 3; ++g){
            #pragma unroll
            for (int r = 0; r < 4; ++r){ z0[c*12 + g*4 + r] = 0.f; z1[c*12 + g*4 + r] = 0.f; }
          }
          #pragma unroll 4
          for (int e = 0; e < DKh; ++e){
            float qe0 = qs[(w*2+0)*D + h*DKh + e];
            float qe1 = qs[(w*2+1)*D + h*DKh + e];
            const float4* kr = (const float4*)(kb + e*CHW);
            #pragma unroll
            for (int g = 0; g < 3; ++g){
              float4 kv = kr[g*32 + lane];
              z0[c*12 + g*4 + 0] = fmaf(qe0, kv.x, z0[c*12 + g*4 + 0]);
              z0[c*12 + g*4 + 1] = fmaf(qe0, kv.y, z0[c*12 + g*4 + 1]);
              z0[c*12 + g*4 + 2] = fmaf(qe0, kv.z, z0[c*12 + g*4 + 2]);
              z0[c*12 + g*4 + 3] = fmaf(qe0, kv.w, z0[c*12 + g*4 + 3]);
              z1[c*12 + g*4 + 0] = fmaf(qe1, kv.x, z1[c*12 + g*4 + 0]);
              z1[c*12 + g*4 + 1] = fmaf(qe1, kv.y, z1[c*12 + g*4 + 1]);
              z1[c*12 + g*4 + 2] = fmaf(qe1, kv.z, z1[c*12 + g*4 + 2]);
              z1[c*12 + g*4 + 3] = fmaf(qe1, kv.w, z1[c*12 + g*4 + 3]);
            }
          }
          cur ^= 1;
        }
      }

      // mask + zmax (both rows)
      float m0 = -3.0e30f, m1 = -3.0e30f;
      #pragma unroll
      for (int c = 0; c < 4; ++c){
        if (c < ncc){
          #pragma unroll
          for (int g = 0; g < 3; ++g){
            int sb4 = c*CHW + g*128 + (lane << 2);
            #pragma unroll
            for (int r = 0; r < 4; ++r){
              int j = c*12 + g*4 + r;
              int col = sb4 + r;
              float a0 = (col <= t0) ? z0[j]*0.125f : -5000.0f;
              float a1 = (col <= t1) ? z1[j]*0.125f : -5000.0f;
              z0[j] = a0; z1[j] = a1;
              m0 = fmaxf(m0, a0); m1 = fmaxf(m1, a1);
            }
          }
        }
      }
      #pragma unroll
      for (int off = 16; off; off >>= 1){
        m0 = fmaxf(m0, __shfl_xor_sync(~0u, m0, off));
        m1 = fmaxf(m1, __shfl_xor_sync(~0u, m1, off));
      }

      // active-set exact-quadratic solver for both rows (interleaved)
      float lo0 = m0 - 1.f, hi0 = m0, tau0 = m0 - 1.f;
      float lo1 = m1 - 1.f, hi1 = m1, tau1 = m1 - 1.f;
      #pragma unroll 1
      for (int it = 0; it < 6; ++it){
        float f0 = 0.f, g0 = 0.f, n0 = 0.f;
        float f1 = 0.f, g1 = 0.f, n1 = 0.f;
        #pragma unroll
        for (int c = 0; c < 4; ++c){
          if (c < ncc){
            #pragma unroll
            for (int jj = 0; jj < 12; ++jj){
              int j = c*12 + jj;
              float d0 = z0[j] - tau0, d1 = z1[j] - tau1;
              float p0 = fmaxf(d0, 0.f), p1 = fmaxf(d1, 0.f);
              f0 = fmaf(p0, p0, f0); g0 += p0; n0 += (d0 > 0.f) ? 1.f : 0.f;
              f1 = fmaf(p1, p1, f1); g1 += p1; n1 += (d1 > 0.f) ? 1.f : 0.f;
            }
          }
        }
        #pragma unroll
        for (int off = 16; off; off >>= 1){
          f0 += __shfl_xor_sync(~0u, f0, off);
          f1 += __shfl_xor_sync(~0u, f1, off);
          g0 += __shfl_xor_sync(~0u, g0, off);
          g1 += __shfl_xor_sync(~0u, g1, off);
          n0 += __shfl_xor_sync(~0u, n0, off);
          n1 += __shfl_xor_sync(~0u, n1, off);
        }
        if (f0 > 1.f) lo0 = fmaxf(lo0, tau0); else hi0 = fminf(hi0, tau0);
        if (f1 > 1.f) lo1 = fmaxf(lo1, tau1); else hi1 = fminf(hi1, tau1);
        float d0 = fmaf(g0, g0, -n0*(f0 - 1.f));
        float d1 = fmaf(g1, g1, -n1*(f1 - 1.f));
        float nt0 = tau0 + (g0 - sqrtf(fmaxf(d0, 0.f))) / n0;
        float nt1 = tau1 + (g1 - sqrtf(fmaxf(d1, 0.f))) / n1;
        if (!(d0 > 0.f) || !(nt0 >= lo0 && nt0 <= hi0)) nt0 = 0.5f*(lo0 + hi0);
        if (!(d1 > 0.f) || !(nt1 >= lo1 && nt1 <= hi1)) nt1 = 0.5f*(lo1 + hi1);
        tau0 = nt0; tau1 = nt1;
      }
      #pragma unroll
      for (int c = 0; c < 4; ++c){
        if (c < ncc){
          #pragma unroll
          for (int jj = 0; jj < 12; ++jj){
            int j = c*12 + jj;
            float p0 = fmaxf(z0[j] - tau0, 0.f);
            float p1 = fmaxf(z1[j] - tau1, 0.f);
            wa0[j] = fmaf(p0, p0, wa0[j]);
            wa1[j] = fmaf(p1, p1, wa1[j]);
          }
        }
      }
    }

    // epilogue: head-average -> logs, y = w_avg @ v_comb (v chunks pipelined)
    float* logrow0 = dout + LOGS_OFS + (size_t)((l*B + b)*T + t0)*T;
    float* logrow1 = dout + LOGS_OFS + (size_t)((l*B + b)*T + t1)*T;
    float acc0[DKh], acc1[DKh];
    #pragma unroll
    for (int e = 0; e < DKh; ++e){ acc0[e] = 0.f; acc1[e] = 0.f; }

    #pragma unroll
    for (int c = 0; c < 4; ++c){
      if (c < ncc){
        asm volatile("cp.async.wait_group 0;\n" ::: "memory");
        __syncthreads();
        if (c + 1 < ncc) issue_chunk(sbase + (unsigned)(cur^1)*(CHF*4), vbase + (c+1)*CHW, tid);
        const float* vb = chbuf + cur*CHF;
        #pragma unroll
        for (int g = 0; g < 3; ++g){
          int j = c*12 + g*4;
          float a0 = wa0[j+0]*0.125f, a1 = wa0[j+1]*0.125f, a2 = wa0[j+2]*0.125f, a3 = wa0[j+3]*0.125f;
          float b0 = wa1[j+0]*0.125f, b1 = wa1[j+1]*0.125f, b2 = wa1[j+2]*0.125f, b3 = wa1[j+3]*0.125f;
          ((float4*)(logrow0 + c*CHW + g*128))[lane] = make_float4(a0, a1, a2, a3);
          ((float4*)(logrow1 + c*CHW + g*128))[lane] = make_float4(b0, b1, b2, b3);
          #pragma unroll
          for (int e = 0; e < DKh; ++e){
            float4 vv = ((const float4*)(vb + e*CHW + g*128))[lane];
            acc0[e] = fmaf(a0, vv.x, acc0[e]);
            acc0[e] = fmaf(a1, vv.y, acc0[e]);
            acc0[e] = fmaf(a2, vv.z, acc0[e]);
            acc0[e] = fmaf(a3, vv.w, acc0[e]);
            acc1[e] = fmaf(b0, vv.x, acc1[e]);
            acc1[e] = fmaf(b1, vv.y, acc1[e]);
            acc1[e] = fmaf(b2, vv.z, acc1[e]);
            acc1[e] = fmaf(b3, vv.w, acc1[e]);
          }
        }
        cur ^= 1;
      } else {
        #pragma unroll
        for (int g = 0; g < 3; ++g){
          ((float4*)(logrow0 + c*CHW + g*128))[lane] = make_float4(0.f, 0.f, 0.f, 0.f);
          ((float4*)(logrow1 + c*CHW + g*128))[lane] = make_float4(0.f, 0.f, 0.f, 0.f);
        }
      }
    }

    float myv0 = 0.f, myv1 = 0.f;
    #pragma unroll
    for (int e = 0; e < DKh; ++e){
      float v0 = acc0[e], v1 = acc1[e];
      #pragma unroll
      for (int off = 16; off; off >>= 1){
        v0 += __shfl_xor_sync(~0u, v0, off);
        v1 += __shfl_xor_sync(~0u, v1, off);
      }
      if (lane == e){ myv0 = v0; myv1 = v1; }
    }
    if (lane < DKh){
      g_y[(size_t)(b*T + t0)*DKh + lane] = myv0;
      g_y[(size_t)(b*T + t1)*DKh + lane] = myv1;
    }
  }
}

// ---------------- fused Wo + LN1 + FFN + LN2 : 8 rows per block (padded smem) ----------------
__global__ void __launch_bounds__(256) ffn_kernel(
    int l,
    const float* __restrict__ Wo,  const float* __restrict__ bo,
    const float* __restrict__ g1,  const float* __restrict__ b1,
    const float* __restrict__ fw1, const float* __restrict__ fb1,
    const float* __restrict__ fw2, const float* __restrict__ fb2,
    const float* __restrict__ g2,  const float* __restrict__ b2){
  __shared__ float xs[8][D];
  __shared__ float xsT[D][12];    // stride 12 (48B rows): float4 @0/@16 aligned, fewer bank conflicts
  __shared__ float hsT[DFF][12];  // stride 12
  __shared__ float o3[8][D];
  int bidx = blockIdx.x;
  int b  = bidx / (T/8);
  int t0 = (bidx % (T/8)) * 8;
  int tid = threadIdx.x, w = tid >> 5, lane = tid & 31;
  int t = t0 + w;

  // step 1: a = y@Wo + bo ; LN1(x + a) -> xs, xsT
  {
    float yv[DKh];
    #pragma unroll
    for (int e = 0; e < DKh; ++e) yv[e] = g_y[(b*T + t)*DKh + e];
    float tv[4];
    #pragma unroll
    for (int i = 0; i < 4; ++i){
      int c = lane + 32*i;
      float a = bo[l*D + c];
      #pragma unroll
      for (int e = 0; e < DKh; ++e) a = fmaf(yv[e], Wo[l*DKh*D + e*D + c], a);
      tv[i] = g_x[(b*T + t)*D + c] + a;
    }
    float s = tv[0] + tv[1] + tv[2] + tv[3];
    #pragma unroll
    for (int off = 16; off; off >>= 1) s += __shfl_xor_sync(~0u, s, off);
    float m = s * (1.0f/D);
    float sq = 0.f;
    #pragma unroll
    for (int i = 0; i < 4; ++i){ float dv = tv[i] - m; sq = fmaf(dv, dv, sq); }
    #pragma unroll
    for (int off = 16; off; off >>= 1) sq += __shfl_xor_sync(~0u, sq, off);
    float rs = rsqrtf(sq * (1.0f/D) + 1e-5f);
    #pragma unroll
    for (int i = 0; i < 4; ++i){
      int c = lane + 32*i;
      float v = (tv[i] - m) * rs * g1[l*D + c] + b1[l*D + c];
      xs[w][c] = v;
      xsT[c][w] = v;
    }
  }
  __syncthreads();

  // step 2: hT = relu(xs @ fw1 + fb1), transposed [DFF][12-padded]
  {
    int c = tid;                // columns c and c+256
    float a0[8], a1[8];
    float bb0 = fb1[l*DFF + c], bb1 = fb1[l*DFF + c + 256];
    #pragma unroll
    for (int r = 0; r < 8; ++r){ a0[r] = bb0; a1[r] = bb1; }
    const float* W = fw1 + l*D*DFF;
    for (int e = 0; e < D; ++e){
      float w0 = W[e*DFF + c];
      float w1 = W[e*DFF + c + 256];
      float4 xA = *(const float4*)&xsT[e][0];
      float4 xB = *(const float4*)&xsT[e][4];
      a0[0]=fmaf(w0,xA.x,a0[0]); a0[1]=fmaf(w0,xA.y,a0[1]); a0[2]=fmaf(w0,xA.z,a0[2]); a0[3]=fmaf(w0,xA.w,a0[3]);
      a0[4]=fmaf(w0,xB.x,a0[4]); a0[5]=fmaf(w0,xB.y,a0[5]); a0[6]=fmaf(w0,xB.z,a0[6]); a0[7]=fmaf(w0,xB.w,a0[7]);
      a1[0]=fmaf(w1,xA.x,a1[0]); a1[1]=fmaf(w1,xA.y,a1[1]); a1[2]=fmaf(w1,xA.z,a1[2]); a1[3]=fmaf(w1,xA.w,a1[3]);
      a1[4]=fmaf(w1,xB.x,a1[4]); a1[5]=fmaf(w1,xB.y,a1[5]); a1[6]=fmaf(w1,xB.z,a1[6]); a1[7]=fmaf(w1,xB.w,a1[7]);
    }
    #pragma unroll
    for (int r = 0; r < 8; ++r){ a0[r] = fmaxf(a0[r], 0.f); a1[r] = fmaxf(a1[r], 0.f); }
    *(float4*)&hsT[c][0]       = make_float4(a0[0], a0[1], a0[2], a0[3]);
    *(float4*)&hsT[c][4]       = make_float4(a0[4], a0[5], a0[6], a0[7]);
    *(float4*)&hsT[c + 256][0] = make_float4(a1[0], a1[1], a1[2], a1[3]);
    *(float4*)&hsT[c + 256][4] = make_float4(a1[4], a1[5], a1[6], a1[7]);
  }
  __syncthreads();

  // step 3: o3 = h @ fw2 + fb2 + xs   (thread: col c, 4 rows)
  {
    int c  = tid & 127;
    int rh = tid >> 7;           // 0 or 1 -> rows rh*4 .. rh*4+3
    float acc[4] = {0.f, 0.f, 0.f, 0.f};
    const float* W = fw2 + l*DFF*D;
    for (int s2 = 0; s2 < DFF; ++s2){
      float wv = W[s2*D + c];
      float4 hv = *(const float4*)&hsT[s2][rh*4];
      acc[0] = fmaf(wv, hv.x, acc[0]);
      acc[1] = fmaf(wv, hv.y, acc[1]);
      acc[2] = fmaf(wv, hv.z, acc[2]);
      acc[3] = fmaf(wv, hv.w, acc[3]);
    }
    float bb = fb2[l*D + c];
    #pragma unroll
    for (int k = 0; k < 4; ++k) o3[rh*4 + k][c] = acc[k] + bb + xs[rh*4 + k][c];
  }
  __syncthreads();

  // step 4: LN2 -> g_x
  {
    float tv[4];
    #pragma unroll
    for (int i = 0; i < 4; ++i) tv[i] = o3[w][lane + 32*i];
    float s = tv[0] + tv[1] + tv[2] + tv[3];
    #pragma unroll
    for (int off = 16; off; off >>= 1) s += __shfl_xor_sync(~0u, s, off);
    float m = s * (1.0f/D);
    float sq = 0.f;
    #pragma unroll
    for (int i = 0; i < 4; ++i){ float dv = tv[i] - m; sq = fmaf(dv, dv, sq); }
    #pragma unroll
    for (int off = 16; off; off >>= 1) sq += __shfl_xor_sync(~0u, sq, off);
    float rs = rsqrtf(sq * (1.0f/D) + 1e-5f);
    #pragma unroll
    for (int i = 0; i < 4; ++i){
      int c = lane + 32*i;
      g_x[(b*T + t)*D + c] = (tv[i] - m) * rs * g2[l*D + c] + b2[l*D + c];
    }
  }
}

// ---------------- final projection ----------------
__global__ void proj_kernel(const float* __restrict__ pw, const float* __restrict__ pb,
                            float* __restrict__ dout){
  int i = threadIdx.x;  // 576 threads
  int b = i / (NQ*HOR), q = (i / HOR) % NQ, hh = i % HOR;
  float acc = pb[q*HOR + hh];
  const float* xr = g_x + (b*T + (T-1))*D;
  for (int d = 0; d < D; ++d) acc = fmaf(xr[d], pw[(q*D + d)*HOR + hh], acc);
  dout[(b*NQ + q)*HOR + hh] = acc;
}

// ---------------- launch ----------------
extern "C" void kernel_launch(void* const* d_in, const int* in_sizes, int n_in,
                              void* d_out, int out_size) {
  const float* x_cond = (const float*)d_in[0];
  const float* x_pred = (const float*)d_in[1];
  const float* cw_c   = (const float*)d_in[2];
  const float* cb_c   = (const float*)d_in[3];
  const float* sw_c   = (const float*)d_in[4];
  const float* sb_c   = (const float*)d_in[5];
  const float* cw_p   = (const float*)d_in[6];
  const float* cb_p   = (const float*)d_in[7];
  const float* sw_p   = (const float*)d_in[8];
  const float* sb_p   = (const float*)d_in[9];
  const float* Wq     = (const float*)d_in[10];
  const float* bq     = (const float*)d_in[11];
  const float* Wk     = (const float*)d_in[12];
  const float* bk     = (const float*)d_in[13];
  const float* Wv     = (const float*)d_in[14];
  const float* bv     = (const float*)d_in[15];
  const float* Wo     = (const float*)d_in[16];
  const float* bo     = (const float*)d_in[17];
  const float* ln1_g  = (const float*)d_in[18];
  const float* ln1_b  = (const float*)d_in[19];
  const float* fw1    = (const float*)d_in[20];
  const float* fb1    = (const float*)d_in[21];
  const float* fw2    = (const float*)d_in[22];
  const float* fb2    = (const float*)d_in[23];
  const float* ln2_g  = (const float*)d_in[24];
  const float* ln2_b  = (const float*)d_in[25];
  const float* proj_w = (const float*)d_in[26];
  const float* proj_b = (const float*)d_in[27];
  float* out = (float*)d_out;

  const int smemA = 2 * CHF * (int)sizeof(float);   // 49152 B dynamic
  cudaFuncSetAttribute(attn_fused_kernel, cudaFuncAttributeMaxDynamicSharedMemorySize, smemA);

  prep_kernel<<<1, 256>>>(cw_c, cb_c, sw_c, sb_c, cw_p, cb_p, sw_p, sb_p, Wv, bv);
  selector_kernel<NVC, TCOND, 0><<<(B*TCOND + 127)/128, 128>>>(x_cond, out, VC_OFS);
  selector_kernel<NVP, TPRED, 1><<<(B*TPRED + 127)/128, 128>>>(x_pred, out, VP_OFS);
  weighted_kernel<<<B*T/16, 128>>>(x_cond, x_pred, cw_c, cb_c, cw_p, cb_p);

  for (int l = 0; l < L; ++l){
    qkv_kernel<<<B*T/8, 256>>>(l, Wq, bq, Wk, bk);
    attn_fused_kernel<<<148, 256, smemA>>>(l, out);
    ffn_kernel<<<B*T/8, 256>>>(l, Wo, bo, ln1_g, ln1_b, fw1, fb1, fw2, fb2, ln2_g, ln2_b);
  }
  proj_kernel<<<1, B*NQ*HOR>>>(proj_w, proj_b, out);
}

// round 14
// speedup vs baseline: 1.1127x; 1.0063x over previous
#include <cuda_runtime.h>
#include <cuda_bf16.h>
#include <stdint.h>

// ---------------- problem constants ----------------
namespace {
constexpr int B = 2, TCOND = 1024, TPRED = 512, NVC = 8, NVP = 4;
constexpr int D = 128, KW = 3, H = 8, DFF = 512, L = 2, HOR = 96, NQ = 3;
constexpr int T = TCOND + TPRED;   // 1536
constexpr int DKh = D / H;         // 16
constexpr int NJ = T / 32;         // 48 (12 per chunk * 4 chunks)
constexpr int SL = DKh * T;        // 24576 floats per (b,h) kT slab
constexpr int RPT = 16;            // rows per tile (2 per warp, 8 warps)
constexpr int NTILE = B * (T / RPT); // 192 tiles
constexpr int CHW = 384;           // chunk width (columns)
constexpr int CHF = DKh * CHW;     // 6144 floats per chunk (24 KB)

constexpr int VC_OFS   = B * NQ * HOR;              // 576
constexpr int VP_OFS   = VC_OFS + B * TCOND * NVC;  // 16960
constexpr int LOGS_OFS = VP_OFS + B * TPRED * NVP;  // 21056
}

// ---------------- device scratch (static, no allocation) ----------------
__device__ float g_x[B*T*D];
__device__ float g_q[B*T*D];
__device__ float g_kT[B*H*SL];
__device__ float g_vcT[B*DKh*T];     // v_comb transposed: [b][e][T]
__device__ float g_y[B*T*DKh];
__device__ float g_wc[B*TCOND*NVC];
__device__ float g_wp[B*TPRED*NVP];
__device__ float g_Ac[NVC*KW], g_Cc[NVC], g_Ap[NVP*KW], g_Cp[NVP];
__device__ float g_Wvc[L*D*DKh], g_bvc[L*DKh];
__device__ unsigned g_key[4];
__device__ int g_ctr;                // attention tile work queue

// ---------------- threefry2x32 (matches JAX) ----------------
__device__ __forceinline__ unsigned rotl32(unsigned v, int r){ return (v<<r)|(v>>(32-r)); }

__device__ __forceinline__ void threefry(unsigned k0, unsigned k1,
                                         unsigned x0, unsigned x1,
                                         unsigned& o0, unsigned& o1){
  unsigned ks2 = k0 ^ k1 ^ 0x1BD11BDAu;
  unsigned ks[3] = {k0, k1, ks2};
  x0 += ks[0]; x1 += ks[1];
  const int R0[4] = {13,15,26,6};
  const int R1[4] = {17,29,16,24};
  #pragma unroll
  for (int i = 0; i < 5; ++i){
    #pragma unroll
    for (int j = 0; j < 4; ++j){
      int r = (i & 1) ? R1[j] : R0[j];
      x0 += x1; x1 = rotl32(x1, r); x1 ^= x0;
    }
    x0 += ks[(i+1)%3];
    x1 += ks[(i+2)%3] + (unsigned)(i+1);
  }
  o0 = x0; o1 = x1;
}

// ---------------- XLA f32 erfinv ----------------
__device__ __forceinline__ float erfinv32(float x){
  float w = -log1pf(-x*x);
  float p;
  if (w < 5.0f){
    w = w - 2.5f;
    p = 2.81022636e-08f;
    p = fmaf(p, w, 3.43273939e-07f);
    p = fmaf(p, w, -3.5233877e-06f);
    p = fmaf(p, w, -4.39150654e-06f);
    p = fmaf(p, w, 0.00021858087f);
    p = fmaf(p, w, -0.00125372503f);
    p = fmaf(p, w, -0.00417768164f);
    p = fmaf(p, w, 0.246640727f);
    p = fmaf(p, w, 1.50140941f);
  } else {
    w = sqrtf(w) - 3.0f;
    p = -0.000200214257f;
    p = fmaf(p, w, 0.000100950558f);
    p = fmaf(p, w, 0.00134934322f);
    p = fmaf(p, w, -0.00367342844f);
    p = fmaf(p, w, 0.00573950773f);
    p = fmaf(p, w, -0.0076224613f);
    p = fmaf(p, w, 0.00943887047f);
    p = fmaf(p, w, 1.00167406f);
    p = fmaf(p, w, 2.83297682f);
  }
  return p * x;
}

// ---------------- prep: keys, folded selector weights, head-averaged Wv ----------------
__global__ void prep_kernel(const float* __restrict__ cwc, const float* __restrict__ cbc,
                            const float* __restrict__ swc, const float* __restrict__ sbc,
                            const float* __restrict__ cwp, const float* __restrict__ cbp,
                            const float* __restrict__ swp, const float* __restrict__ sbp,
                            const float* __restrict__ Wv,  const float* __restrict__ bv){
  int tid = threadIdx.x;
  if (tid == 0) threefry(0u, 42u, 0u, 0u, g_key[0], g_key[1]);
  if (tid == 1) threefry(0u, 42u, 0u, 1u, g_key[2], g_key[3]);

  if (tid >= 2 && tid < 2 + NVC*KW){
    int i = tid - 2, g = i / KW, k = i % KW;
    float s = 0.f;
    for (int d = 0; d < D; ++d) s = fmaf(cwc[(g*D + d)*KW + k], swc[d], s);
    g_Ac[i] = s;
  } else if (tid >= 26 && tid < 26 + NVC){
    int g = tid - 26;
    float s = 0.f;
    for (int d = 0; d < D; ++d) s = fmaf(cbc[g*D + d], swc[d], s);
    g_Cc[g] = s + sbc[0];
  } else if (tid >= 34 && tid < 34 + NVP*KW){
    int i = tid - 34, g = i / KW, k = i % KW;
    float s = 0.f;
    for (int d = 0; d < D; ++d) s = fmaf(cwp[(g*D + d)*KW + k], swp[d], s);
    g_Ap[i] = s;
  } else if (tid >= 46 && tid < 46 + NVP){
    int g = tid - 46;
    float s = 0.f;
    for (int d = 0; d < D; ++d) s = fmaf(cbp[g*D + d], swp[d], s);
    g_Cp[g] = s + sbp[0];
  } else if (tid >= 50 && tid < 50 + L*DKh){
    int i = tid - 50, l = i / DKh, d = i % DKh;
    float s = 0.f;
    for (int h = 0; h < H; ++h) s += bv[l*D + h*DKh + d];
    g_bvc[i] = s * (1.0f/H);
  }

  for (int i = tid; i < L*D*DKh; i += blockDim.x){
    int l = i / (D*DKh), e = (i / DKh) % D, d = i % DKh;
    float s = 0.f;
    for (int h = 0; h < H; ++h) s += Wv[l*D*D + e*D + h*DKh + d];
    g_Wvc[i] = s * (1.0f/H);
  }
}

// ---------------- selector ----------------
template<int NV, int TS, int WHICH>
__global__ void selector_kernel(const float* __restrict__ xin,
                                float* __restrict__ dout, int oofs){
  int r = blockIdx.x * blockDim.x + threadIdx.x;
  if (r >= B*TS) return;
  int b = r / TS, t = r % TS;

  const float* A = (WHICH == 0) ? g_Ac : g_Ap;
  const float* C = (WHICH == 0) ? g_Cc : g_Cp;
  float* wscr    = (WHICH == 0) ? g_wc : g_wp;
  unsigned k0 = g_key[WHICH*2], k1 = g_key[WHICH*2 + 1];

  const int N = B*TS*NV, half = N >> 1;
  float z[NV];
  float m = -1e30f;
  #pragma unroll
  for (int g = 0; g < NV; ++g){
    float x0  = xin[(b*TS + t)*NV + g];
    float xm1 = (t >= 1) ? xin[(b*TS + t - 1)*NV + g] : 0.f;
    float xm2 = (t >= 2) ? xin[(b*TS + t - 2)*NV + g] : 0.f;
    float s = A[g*KW+0]*xm2 + A[g*KW+1]*xm1 + A[g*KW+2]*x0 + C[g];
    s = fminf(10.f, fmaxf(-10.f, s));
    int idx = (b*TS + t)*NV + g;
    unsigned o0, o1, bits;
    if (idx < half){ threefry(k0, k1, (unsigned)idx, (unsigned)(idx + half), o0, o1); bits = o0; }
    else           { threefry(k0, k1, (unsigned)(idx - half), (unsigned)idx, o0, o1); bits = o1; }
    float fu = __uint_as_float((bits >> 9) | 0x3f800000u) - 1.0f;
    const float lom = -0.99999994f, him = 1.0f;
    float u = fmaxf(lom, fmaf(fu, him - lom, lom));
    s = s + 1e-4f * (1.41421356f * erfinv32(u));
    z[g] = 0.5f * s;
    m = fmaxf(m, z[g]);
  }
  #pragma unroll
  for (int g = 0; g < NV; ++g) z[g] -= m;

  float tau = -1.0f;
  #pragma unroll 1
  for (int it = 0; it < 22; ++it){
    float f = 0.f, gg = 0.f;
    #pragma unroll
    for (int g = 0; g < NV; ++g){
      float dd = fmaxf(z[g] - tau, 0.f);
      f = fmaf(dd, dd, f); gg += dd;
    }
    tau += (f - 1.0f) / fmaxf(2.0f*gg, 1e-30f);
  }
  #pragma unroll
  for (int g = 0; g < NV; ++g){
    float dd = fmaxf(z[g] - tau, 0.f);
    float p = dd*dd;
    wscr[r*NV + g] = p;
    dout[oofs + r*NV + g] = p;
  }
}

// ---------------- weighted conv features -> concat x (B,T,128) ----------------
__global__ void weighted_kernel(const float* __restrict__ xc, const float* __restrict__ xp,
                                const float* __restrict__ cwc, const float* __restrict__ cbc,
                                const float* __restrict__ cwp, const float* __restrict__ cbp){
  int bt = blockIdx.x;
  int d = threadIdx.x;
  int b = bt / T, t = bt % T;
  const float *xin, *cw, *cb, *wsel;
  int nv, Ts, tt;
  if (t < TCOND){ xin = xc; cw = cwc; cb = cbc; wsel = g_wc; nv = NVC; Ts = TCOND; tt = t; }
  else          { xin = xp; cw = cwp; cb = cbp; wsel = g_wp; nv = NVP; Ts = TPRED; tt = t - TCOND; }
  float acc = 0.f;
  for (int g = 0; g < nv; ++g){
    float w = wsel[(b*Ts + tt)*nv + g];
    float x0  = xin[(b*Ts + tt)*nv + g];
    float xm1 = (tt >= 1) ? xin[(b*Ts + tt - 1)*nv + g] : 0.f;
    float xm2 = (tt >= 2) ? xin[(b*Ts + tt - 2)*nv + g] : 0.f;
    const float* cwg = cw + (g*D + d)*KW;
    float ls = cb[g*D + d] + cwg[0]*xm2 + cwg[1]*xm1 + cwg[2]*x0;
    acc = fmaf(w, ls, acc);
  }
  g_x[(b*T + t)*D + d] = acc;
}

// ---------------- QKV (+ head-averaged V, transposed): 8 rows per block ----------------
__global__ void qkv_kernel(int l, const float* __restrict__ Wq, const float* __restrict__ bq,
                           const float* __restrict__ Wk, const float* __restrict__ bk){
  __shared__ float xr[8][D];
  if (blockIdx.x == 0 && threadIdx.x == 0) g_ctr = 0;   // reset attn work queue
  int b  = blockIdx.x / (T/8);
  int t0 = (blockIdx.x % (T/8)) * 8;
  int tid = threadIdx.x;  // 256
  for (int i = tid; i < 8*D; i += 256) xr[i/D][i%D] = g_x[(b*T + t0 + i/D)*D + (i%D)];
  __syncthreads();

  for (int col = tid; col < 2*D + DKh; col += 256){
    const float* W; float bias; int c, ld, kind;
    if (col < D)        { c = col;       W = Wq + l*D*D;       bias = bq[l*D + c];     ld = D;   kind = 0; }
    else if (col < 2*D) { c = col - D;   W = Wk + l*D*D;       bias = bk[l*D + c];     ld = D;   kind = 1; }
    else                { c = col - 2*D; W = g_Wvc + l*D*DKh;  bias = g_bvc[l*DKh+c];  ld = DKh; kind = 2; }
    float acc[8];
    #pragma unroll
    for (int r = 0; r < 8; ++r) acc[r] = bias;
    for (int e = 0; e < D; ++e){
      float w = W[e*ld + c];
      #pragma unroll
      for (int r = 0; r < 8; ++r) acc[r] = fmaf(xr[r][e], w, acc[r]);
    }
    #pragma unroll
    for (int r = 0; r < 8; ++r){
      int t = t0 + r;
      if (kind == 0)      g_q[(b*T + t)*D + c] = acc[r];
      else if (kind == 1){ int h = c / DKh, d = c % DKh;
                           g_kT[((b*H + h)*DKh + d)*T + t] = acc[r]; }
      else                g_vcT[((size_t)b*DKh + c)*T + t] = acc[r];
    }
  }
}

// ---------------- chunk loader: 16 rows x 384 cols from row-strided source ----------------
// 256 threads: 6 x 16B per thread
__device__ __forceinline__ void issue_chunk(unsigned sdst, const float* gsrc, int tid){
  #pragma unroll
  for (int i = 0; i < 6; ++i){
    int u = i*256 + tid;
    int e = u / 96, off = u - e*96;
    unsigned sa = sdst + (unsigned)(e*1536 + off*16);
    const char* ga = (const char*)gsrc + (size_t)e*T*4 + (size_t)off*16;
    asm volatile("cp.async.cg.shared.global [%0], [%1], 16;\n" :: "r"(sa), "l"(ga) : "memory");
  }
  asm volatile("cp.async.commit_group;\n" ::: "memory");
}

// ---------------- fused attention: persistent, work-stealing, 2 rows per warp ----------------
// block = 256 threads (8 warps x 2 rows = 16-row tile); smem = 2 x 24KB chunk buffers
__global__ void __launch_bounds__(256, 1) attn_fused_kernel(int l, float* __restrict__ dout){
  extern __shared__ float chbuf[];         // 2 * CHF floats (48 KB)
  __shared__ float qs[RPT*D];              // 8 KB q tile
  __shared__ int s_tile;

  const int tid = threadIdx.x, w = tid >> 5, lane = tid & 31;
  const unsigned sbase = (unsigned)__cvta_generic_to_shared(chbuf);
  int cur = 0;

  for (;;){
    __syncthreads();
    if (tid == 0) s_tile = atomicAdd(&g_ctr, 1);
    __syncthreads();
    int u = s_tile;
    if (u >= NTILE) break;

    // descending-cost (LPT) ordering
    int tr = (T/RPT - 1) - (u >> 1);
    int b  = u & 1;
    int t0 = tr*RPT + w*2;                 // this warp's rows: t0, t0+1
    int t1 = t0 + 1;
    int tmax = tr*RPT + (RPT-1);
    int ncc  = tmax/CHW + 1;               // active chunks (1..4), block-uniform

    // stage q tile [16][128]
    for (int i = tid; i < RPT*D; i += 256)
      qs[i] = g_q[(size_t)(b*T + tr*RPT + (i >> 7))*D + (i & 127)];

    const float* kbase = g_kT + (size_t)b*H*SL;
    const float* vbase = g_vcT + (size_t)b*DKh*T;

    // prologue: issue k chunk (h=0, c=0) into buf[cur]
    issue_chunk(sbase + (unsigned)cur*(CHF*4), kbase, tid);

    float wa0[NJ], wa1[NJ];
    #pragma unroll
    for (int j = 0; j < NJ; ++j){ wa0[j] = 0.f; wa1[j] = 0.f; }

    #pragma unroll 1
    for (int h = 0; h < H; ++h){
      float z0[NJ], z1[NJ];
      #pragma unroll
      for (int c = 0; c < 4; ++c){
        if (c < ncc){
          asm volatile("cp.async.wait_group 0;\n" ::: "memory");
          __syncthreads();
          // issue next chunk into other buffer
          if (c + 1 < ncc)      issue_chunk(sbase + (unsigned)(cur^1)*(CHF*4), kbase + (size_t)h*SL + (c+1)*CHW, tid);
          else if (h + 1 < H)   issue_chunk(sbase + (unsigned)(cur^1)*(CHF*4), kbase + (size_t)(h+1)*SL, tid);
          else                  issue_chunk(sbase + (unsigned)(cur^1)*(CHF*4), vbase, tid);
          // scores for chunk c: lane owns columns c*384 + g*128 + lane*4 + r
          const float* kb = chbuf + cur*CHF;
          #pragma unroll
          for (int g = 0; g < 3; ++g){
            #pragma unroll
            for (int r = 0; r < 4; ++r){ z0[c*12 + g*4 + r] = 0.f; z1[c*12 + g*4 + r] = 0.f; }
          }
          #pragma unroll 4
          for (int e = 0; e < DKh; ++e){
            float qe0 = qs[(w*2+0)*D + h*DKh + e];
            float qe1 = qs[(w*2+1)*D + h*DKh + e];
            const float4* kr = (const float4*)(kb + e*CHW);
            #pragma unroll
            for (int g = 0; g < 3; ++g){
              float4 kv = kr[g*32 + lane];
              z0[c*12 + g*4 + 0] = fmaf(qe0, kv.x, z0[c*12 + g*4 + 0]);
              z0[c*12 + g*4 + 1] = fmaf(qe0, kv.y, z0[c*12 + g*4 + 1]);
              z0[c*12 + g*4 + 2] = fmaf(qe0, kv.z, z0[c*12 + g*4 + 2]);
              z0[c*12 + g*4 + 3] = fmaf(qe0, kv.w, z0[c*12 + g*4 + 3]);
              z1[c*12 + g*4 + 0] = fmaf(qe1, kv.x, z1[c*12 + g*4 + 0]);
              z1[c*12 + g*4 + 1] = fmaf(qe1, kv.y, z1[c*12 + g*4 + 1]);
              z1[c*12 + g*4 + 2] = fmaf(qe1, kv.z, z1[c*12 + g*4 + 2]);
              z1[c*12 + g*4 + 3] = fmaf(qe1, kv.w, z1[c*12 + g*4 + 3]);
            }
          }
          cur ^= 1;
        }
      }

      // mask + zmax (both rows)
      float m0 = -3.0e30f, m1 = -3.0e30f;
      #pragma unroll
      for (int c = 0; c < 4; ++c){
        if (c < ncc){
          #pragma unroll
          for (int g = 0; g < 3; ++g){
            int sb4 = c*CHW + g*128 + (lane << 2);
            #pragma unroll
            for (int r = 0; r < 4; ++r){
              int j = c*12 + g*4 + r;
              int col = sb4 + r;
              float a0 = (col <= t0) ? z0[j]*0.125f : -5000.0f;
              float a1 = (col <= t1) ? z1[j]*0.125f : -5000.0f;
              z0[j] = a0; z1[j] = a1;
              m0 = fmaxf(m0, a0); m1 = fmaxf(m1, a1);
            }
          }
        }
      }
      #pragma unroll
      for (int off = 16; off; off >>= 1){
        m0 = fmaxf(m0, __shfl_xor_sync(~0u, m0, off));
        m1 = fmaxf(m1, __shfl_xor_sync(~0u, m1, off));
      }

      // active-set exact-quadratic solver for both rows (interleaved)
      float lo0 = m0 - 1.f, hi0 = m0, tau0 = m0 - 1.f;
      float lo1 = m1 - 1.f, hi1 = m1, tau1 = m1 - 1.f;
      #pragma unroll 1
      for (int it = 0; it < 6; ++it){
        float f0 = 0.f, g0 = 0.f, n0 = 0.f;
        float f1 = 0.f, g1 = 0.f, n1 = 0.f;
        #pragma unroll
        for (int c = 0; c < 4; ++c){
          if (c < ncc){
            #pragma unroll
            for (int jj = 0; jj < 12; ++jj){
              int j = c*12 + jj;
              float d0 = z0[j] - tau0, d1 = z1[j] - tau1;
              float p0 = fmaxf(d0, 0.f), p1 = fmaxf(d1, 0.f);
              f0 = fmaf(p0, p0, f0); g0 += p0; n0 += (d0 > 0.f) ? 1.f : 0.f;
              f1 = fmaf(p1, p1, f1); g1 += p1; n1 += (d1 > 0.f) ? 1.f : 0.f;
            }
          }
        }
        #pragma unroll
        for (int off = 16; off; off >>= 1){
          f0 += __shfl_xor_sync(~0u, f0, off);
          f1 += __shfl_xor_sync(~0u, f1, off);
          g0 += __shfl_xor_sync(~0u, g0, off);
          g1 += __shfl_xor_sync(~0u, g1, off);
          n0 += __shfl_xor_sync(~0u, n0, off);
          n1 += __shfl_xor_sync(~0u, n1, off);
        }
        if (f0 > 1.f) lo0 = fmaxf(lo0, tau0); else hi0 = fminf(hi0, tau0);
        if (f1 > 1.f) lo1 = fmaxf(lo1, tau1); else hi1 = fminf(hi1, tau1);
        float d0 = fmaf(g0, g0, -n0*(f0 - 1.f));
        float d1 = fmaf(g1, g1, -n1*(f1 - 1.f));
        float nt0 = tau0 + (g0 - sqrtf(fmaxf(d0, 0.f))) / n0;
        float nt1 = tau1 + (g1 - sqrtf(fmaxf(d1, 0.f))) / n1;
        if (!(d0 > 0.f) || !(nt0 >= lo0 && nt0 <= hi0)) nt0 = 0.5f*(lo0 + hi0);
        if (!(d1 > 0.f) || !(nt1 >= lo1 && nt1 <= hi1)) nt1 = 0.5f*(lo1 + hi1);
        tau0 = nt0; tau1 = nt1;
      }
      #pragma unroll
      for (int c = 0; c < 4; ++c){
        if (c < ncc){
          #pragma unroll
          for (int jj = 0; jj < 12; ++jj){
            int j = c*12 + jj;
            float p0 = fmaxf(z0[j] - tau0, 0.f);
            float p1 = fmaxf(z1[j] - tau1, 0.f);
            wa0[j] = fmaf(p0, p0, wa0[j]);
            wa1[j] = fmaf(p1, p1, wa1[j]);
          }
        }
      }
    }

    // epilogue: head-average -> logs, y = w_avg @ v_comb (v chunks pipelined)
    float* logrow0 = dout + LOGS_OFS + (size_t)((l*B + b)*T + t0)*T;
    float* logrow1 = dout + LOGS_OFS + (size_t)((l*B + b)*T + t1)*T;
    float acc0[DKh], acc1[DKh];
    #pragma unroll
    for (int e = 0; e < DKh; ++e){ acc0[e] = 0.f; acc1[e] = 0.f; }

    #pragma unroll
    for (int c = 0; c < 4; ++c){
      if (c < ncc){
        asm volatile("cp.async.wait_group 0;\n" ::: "memory");
        __syncthreads();
        if (c + 1 < ncc) issue_chunk(sbase + (unsigned)(cur^1)*(CHF*4), vbase + (c+1)*CHW, tid);
        const float* vb = chbuf + cur*CHF;
        #pragma unroll
        for (int g = 0; g < 3; ++g){
          int j = c*12 + g*4;
          float a0 = wa0[j+0]*0.125f, a1 = wa0[j+1]*0.125f, a2 = wa0[j+2]*0.125f, a3 = wa0[j+3]*0.125f;
          float b0 = wa1[j+0]*0.125f, b1 = wa1[j+1]*0.125f, b2 = wa1[j+2]*0.125f, b3 = wa1[j+3]*0.125f;
          ((float4*)(logrow0 + c*CHW + g*128))[lane] = make_float4(a0, a1, a2, a3);
          ((float4*)(logrow1 + c*CHW + g*128))[lane] = make_float4(b0, b1, b2, b3);
          #pragma unroll
          for (int e = 0; e < DKh; ++e){
            float4 vv = ((const float4*)(vb + e*CHW + g*128))[lane];
            acc0[e] = fmaf(a0, vv.x, acc0[e]);
            acc0[e] = fmaf(a1, vv.y, acc0[e]);
            acc0[e] = fmaf(a2, vv.z, acc0[e]);
            acc0[e] = fmaf(a3, vv.w, acc0[e]);
            acc1[e] = fmaf(b0, vv.x, acc1[e]);
            acc1[e] = fmaf(b1, vv.y, acc1[e]);
            acc1[e] = fmaf(b2, vv.z, acc1[e]);
            acc1[e] = fmaf(b3, vv.w, acc1[e]);
          }
        }
        cur ^= 1;
      } else {
        #pragma unroll
        for (int g = 0; g < 3; ++g){
          ((float4*)(logrow0 + c*CHW + g*128))[lane] = make_float4(0.f, 0.f, 0.f, 0.f);
          ((float4*)(logrow1 + c*CHW + g*128))[lane] = make_float4(0.f, 0.f, 0.f, 0.f);
        }
      }
    }

    float myv0 = 0.f, myv1 = 0.f;
    #pragma unroll
    for (int e = 0; e < DKh; ++e){
      float v0 = acc0[e], v1 = acc1[e];
      #pragma unroll
      for (int off = 16; off; off >>= 1){
        v0 += __shfl_xor_sync(~0u, v0, off);
        v1 += __shfl_xor_sync(~0u, v1, off);
      }
      if (lane == e){ myv0 = v0; myv1 = v1; }
    }
    if (lane < DKh){
      g_y[(size_t)(b*T + t0)*DKh + lane] = myv0;
      g_y[(size_t)(b*T + t1)*DKh + lane] = myv1;
    }
  }
}

// ---------------- fused Wo + LN1 + FFN + LN2 : 8 rows per block (padded smem) ----------------
__global__ void __launch_bounds__(256) ffn_kernel(
    int l,
    const float* __restrict__ Wo,  const float* __restrict__ bo,
    const float* __restrict__ g1,  const float* __restrict__ b1,
    const float* __restrict__ fw1, const float* __restrict__ fb1,
    const float* __restrict__ fw2, const float* __restrict__ fb2,
    const float* __restrict__ g2,  const float* __restrict__ b2){
  __shared__ float xs[8][D];
  __shared__ float xsT[D][12];    // stride 12 (48B rows): float4 @0/@16 aligned, fewer bank conflicts
  __shared__ float hsT[DFF][12];  // stride 12
  __shared__ float o3[8][D];
  int bidx = blockIdx.x;
  int b  = bidx / (T/8);
  int t0 = (bidx % (T/8)) * 8;
  int tid = threadIdx.x, w = tid >> 5, lane = tid & 31;
  int t = t0 + w;

  // step 1: a = y@Wo + bo ; LN1(x + a) -> xs, xsT
  {
    float yv[DKh];
    #pragma unroll
    for (int e = 0; e < DKh; ++e) yv[e] = g_y[(b*T + t)*DKh + e];
    float tv[4];
    #pragma unroll
    for (int i = 0; i < 4; ++i){
      int c = lane + 32*i;
      float a = bo[l*D + c];
      #pragma unroll
      for (int e = 0; e < DKh; ++e) a = fmaf(yv[e], Wo[l*DKh*D + e*D + c], a);
      tv[i] = g_x[(b*T + t)*D + c] + a;
    }
    float s = tv[0] + tv[1] + tv[2] + tv[3];
    #pragma unroll
    for (int off = 16; off; off >>= 1) s += __shfl_xor_sync(~0u, s, off);
    float m = s * (1.0f/D);
    float sq = 0.f;
    #pragma unroll
    for (int i = 0; i < 4; ++i){ float dv = tv[i] - m; sq = fmaf(dv, dv, sq); }
    #pragma unroll
    for (int off = 16; off; off >>= 1) sq += __shfl_xor_sync(~0u, sq, off);
    float rs = rsqrtf(sq * (1.0f/D) + 1e-5f);
    #pragma unroll
    for (int i = 0; i < 4; ++i){
      int c = lane + 32*i;
      float v = (tv[i] - m) * rs * g1[l*D + c] + b1[l*D + c];
      xs[w][c] = v;
      xsT[c][w] = v;
    }
  }
  __syncthreads();

  // step 2: hT = relu(xs @ fw1 + fb1), transposed [DFF][12-padded]
  {
    int c = tid;                // columns c and c+256
    float a0[8], a1[8];
    float bb0 = fb1[l*DFF + c], bb1 = fb1[l*DFF + c + 256];
    #pragma unroll
    for (int r = 0; r < 8; ++r){ a0[r] = bb0; a1[r] = bb1; }
    const float* W = fw1 + l*D*DFF;
    for (int e = 0; e < D; ++e){
      float w0 = W[e*DFF + c];
      float w1 = W[e*DFF + c + 256];
      float4 xA = *(const float4*)&xsT[e][0];
      float4 xB = *(const float4*)&xsT[e][4];
      a0[0]=fmaf(w0,xA.x,a0[0]); a0[1]=fmaf(w0,xA.y,a0[1]); a0[2]=fmaf(w0,xA.z,a0[2]); a0[3]=fmaf(w0,xA.w,a0[3]);
      a0[4]=fmaf(w0,xB.x,a0[4]); a0[5]=fmaf(w0,xB.y,a0[5]); a0[6]=fmaf(w0,xB.z,a0[6]); a0[7]=fmaf(w0,xB.w,a0[7]);
      a1[0]=fmaf(w1,xA.x,a1[0]); a1[1]=fmaf(w1,xA.y,a1[1]); a1[2]=fmaf(w1,xA.z,a1[2]); a1[3]=fmaf(w1,xA.w,a1[3]);
      a1[4]=fmaf(w1,xB.x,a1[4]); a1[5]=fmaf(w1,xB.y,a1[5]); a1[6]=fmaf(w1,xB.z,a1[6]); a1[7]=fmaf(w1,xB.w,a1[7]);
    }
    #pragma unroll
    for (int r = 0; r < 8; ++r){ a0[r] = fmaxf(a0[r], 0.f); a1[r] = fmaxf(a1[r], 0.f); }
    *(float4*)&hsT[c][0]       = make_float4(a0[0], a0[1], a0[2], a0[3]);
    *(float4*)&hsT[c][4]       = make_float4(a0[4], a0[5], a0[6], a0[7]);
    *(float4*)&hsT[c + 256][0] = make_float4(a1[0], a1[1], a1[2], a1[3]);
    *(float4*)&hsT[c + 256][4] = make_float4(a1[4], a1[5], a1[6], a1[7]);
  }
  __syncthreads();

  // step 3: o3 = h @ fw2 + fb2 + xs   (thread: col c, 4 rows)
  {
    int c  = tid & 127;
    int rh = tid >> 7;           // 0 or 1 -> rows rh*4 .. rh*4+3
    float acc[4] = {0.f, 0.f, 0.f, 0.f};
    const float* W = fw2 + l*DFF*D;
    for (int s2 = 0; s2 < DFF; ++s2){
      float wv = W[s2*D + c];
      float4 hv = *(const float4*)&hsT[s2][rh*4];
      acc[0] = fmaf(wv, hv.x, acc[0]);
      acc[1] = fmaf(wv, hv.y, acc[1]);
      acc[2] = fmaf(wv, hv.z, acc[2]);
      acc[3] = fmaf(wv, hv.w, acc[3]);
    }
    float bb = fb2[l*D + c];
    #pragma unroll
    for (int k = 0; k < 4; ++k) o3[rh*4 + k][c] = acc[k] + bb + xs[rh*4 + k][c];
  }
  __syncthreads();

  // step 4: LN2 -> g_x
  {
    float tv[4];
    #pragma unroll
    for (int i = 0; i < 4; ++i) tv[i] = o3[w][lane + 32*i];
    float s = tv[0] + tv[1] + tv[2] + tv[3];
    #pragma unroll
    for (int off = 16; off; off >>= 1) s += __shfl_xor_sync(~0u, s, off);
    float m = s * (1.0f/D);
    float sq = 0.f;
    #pragma unroll
    for (int i = 0; i < 4; ++i){ float dv = tv[i] - m; sq = fmaf(dv, dv, sq); }
    #pragma unroll
    for (int off = 16; off; off >>= 1) sq += __shfl_xor_sync(~0u, sq, off);
    float rs = rsqrtf(sq * (1.0f/D) + 1e-5f);
    #pragma unroll
    for (int i = 0; i < 4; ++i){
      int c = lane + 32*i;
      g_x[(b*T + t)*D + c] = (tv[i] - m) * rs * g2[l*D + c] + b2[l*D + c];
    }
  }
}

// ---------------- final projection ----------------
__global__ void proj_kernel(const float* __restrict__ pw, const float* __restrict__ pb,
                            float* __restrict__ dout){
  int i = threadIdx.x;  // 576 threads
  int b = i / (NQ*HOR), q = (i / HOR) % NQ, hh = i % HOR;
  float acc = pb[q*HOR + hh];
  const float* xr = g_x + (b*T + (T-1))*D;
  for (int d = 0; d < D; ++d) acc = fmaf(xr[d], pw[(q*D + d)*HOR + hh], acc);
  dout[(b*NQ + q)*HOR + hh] = acc;
}

// ---------------- launch ----------------
extern "C" void kernel_launch(void* const* d_in, const int* in_sizes, int n_in,
                              void* d_out, int out_size) {
  const float* x_cond = (const float*)d_in[0];
  const float* x_pred = (const float*)d_in[1];
  const float* cw_c   = (const float*)d_in[2];
  const float* cb_c   = (const float*)d_in[3];
  const float* sw_c   = (const float*)d_in[4];
  const float* sb_c   = (const float*)d_in[5];
  const float* cw_p   = (const float*)d_in[6];
  const float* cb_p   = (const float*)d_in[7];
  const float* sw_p   = (const float*)d_in[8];
  const float* sb_p   = (const float*)d_in[9];
  const float* Wq     = (const float*)d_in[10];
  const float* bq     = (const float*)d_in[11];
  const float* Wk     = (const float*)d_in[12];
  const float* bk     = (const float*)d_in[13];
  const float* Wv     = (const float*)d_in[14];
  const float* bv     = (const float*)d_in[15];
  const float* Wo     = (const float*)d_in[16];
  const float* bo     = (const float*)d_in[17];
  const float* ln1_g  = (const float*)d_in[18];
  const float* ln1_b  = (const float*)d_in[19];
  const float* fw1    = (const float*)d_in[20];
  const float* fb1    = (const float*)d_in[21];
  const float* fw2    = (const float*)d_in[22];
  const float* fb2    = (const float*)d_in[23];
  const float* ln2_g  = (const float*)d_in[24];
  const float* ln2_b  = (const float*)d_in[25];
  const float* proj_w = (const float*)d_in[26];
  const float* proj_b = (const float*)d_in[27];
  float* out = (float*)d_out;

  const int smemA = 2 * CHF * (int)sizeof(float);   // 49152 B dynamic
  cudaFuncSetAttribute(attn_fused_kernel, cudaFuncAttributeMaxDynamicSharedMemorySize, smemA);

  prep_kernel<<<1, 256>>>(cw_c, cb_c, sw_c, sb_c, cw_p, cb_p, sw_p, sb_p, Wv, bv);
  selector_kernel<NVC, TCOND, 0><<<(B*TCOND + 127)/128, 128>>>(x_cond, out, VC_OFS);
  selector_kernel<NVP, TPRED, 1><<<(B*TPRED + 127)/128, 128>>>(x_pred, out, VP_OFS);
  weighted_kernel<<<B*T, 128>>>(x_cond, x_pred, cw_c, cb_c, cw_p, cb_p);

  for (int l = 0; l < L; ++l){
    qkv_kernel<<<B*T/8, 256>>>(l, Wq, bq, Wk, bk);
    attn_fused_kernel<<<148, 256, smemA>>>(l, out);
    ffn_kernel<<<B*T/8, 256>>>(l, Wo, bo, ln1_g, ln1_b, fw1, fb1, fw2, fb2, ln2_g, ln2_b);
  }
  proj_kernel<<<1, B*NQ*HOR>>>(proj_w, proj_b, out);
}

// round 15
// speedup vs baseline: 1.1233x; 1.0096x over previous
#include <cuda_runtime.h>
#include <cuda_bf16.h>
#include <stdint.h>

// ---------------- problem constants ----------------
namespace {
constexpr int B = 2, TCOND = 1024, TPRED = 512, NVC = 8, NVP = 4;
constexpr int D = 128, KW = 3, H = 8, DFF = 512, L = 2, HOR = 96, NQ = 3;
constexpr int T = TCOND + TPRED;   // 1536
constexpr int DKh = D / H;         // 16
constexpr int NJ = T / 32;         // 48 (12 per chunk * 4 chunks)
constexpr int SL = DKh * T;        // 24576 floats per (b,h) kT slab
constexpr int RPT = 16;            // rows per tile (2 per warp, 8 warps)
constexpr int NTILE = B * (T / RPT); // 192 tiles
constexpr int CHW = 384;           // chunk width (columns)
constexpr int CHF = DKh * CHW;     // 6144 floats per chunk (24 KB)

constexpr int VC_OFS   = B * NQ * HOR;              // 576
constexpr int VP_OFS   = VC_OFS + B * TCOND * NVC;  // 16960
constexpr int LOGS_OFS = VP_OFS + B * TPRED * NVP;  // 21056
}

// ---------------- device scratch (static, no allocation) ----------------
__device__ float g_x[B*T*D];
__device__ float g_q[B*T*D];
__device__ float g_kT[B*H*SL];
__device__ float g_vcT[B*DKh*T];     // v_comb transposed: [b][e][T]
__device__ float g_y[B*T*DKh];
__device__ float g_wc[B*TCOND*NVC];
__device__ float g_wp[B*TPRED*NVP];
__device__ float g_Ac[NVC*KW], g_Cc[NVC], g_Ap[NVP*KW], g_Cp[NVP];
__device__ float g_Wvc[L*D*DKh], g_bvc[L*DKh];
__device__ unsigned g_key[4];
__device__ int g_ctr;                // attention tile work queue

// ---------------- threefry2x32 (matches JAX) ----------------
__device__ __forceinline__ unsigned rotl32(unsigned v, int r){ return (v<<r)|(v>>(32-r)); }

__device__ __forceinline__ void threefry(unsigned k0, unsigned k1,
                                         unsigned x0, unsigned x1,
                                         unsigned& o0, unsigned& o1){
  unsigned ks2 = k0 ^ k1 ^ 0x1BD11BDAu;
  unsigned ks[3] = {k0, k1, ks2};
  x0 += ks[0]; x1 += ks[1];
  const int R0[4] = {13,15,26,6};
  const int R1[4] = {17,29,16,24};
  #pragma unroll
  for (int i = 0; i < 5; ++i){
    #pragma unroll
    for (int j = 0; j < 4; ++j){
      int r = (i & 1) ? R1[j] : R0[j];
      x0 += x1; x1 = rotl32(x1, r); x1 ^= x0;
    }
    x0 += ks[(i+1)%3];
    x1 += ks[(i+2)%3] + (unsigned)(i+1);
  }
  o0 = x0; o1 = x1;
}

// ---------------- XLA f32 erfinv ----------------
__device__ __forceinline__ float erfinv32(float x){
  float w = -log1pf(-x*x);
  float p;
  if (w < 5.0f){
    w = w - 2.5f;
    p = 2.81022636e-08f;
    p = fmaf(p, w, 3.43273939e-07f);
    p = fmaf(p, w, -3.5233877e-06f);
    p = fmaf(p, w, -4.39150654e-06f);
    p = fmaf(p, w, 0.00021858087f);
    p = fmaf(p, w, -0.00125372503f);
    p = fmaf(p, w, -0.00417768164f);
    p = fmaf(p, w, 0.246640727f);
    p = fmaf(p, w, 1.50140941f);
  } else {
    w = sqrtf(w) - 3.0f;
    p = -0.000200214257f;
    p = fmaf(p, w, 0.000100950558f);
    p = fmaf(p, w, 0.00134934322f);
    p = fmaf(p, w, -0.00367342844f);
    p = fmaf(p, w, 0.00573950773f);
    p = fmaf(p, w, -0.0076224613f);
    p = fmaf(p, w, 0.00943887047f);
    p = fmaf(p, w, 1.00167406f);
    p = fmaf(p, w, 2.83297682f);
  }
  return p * x;
}

// ---------------- prep: keys, folded selector weights, head-averaged Wv ----------------
__global__ void prep_kernel(const float* __restrict__ cwc, const float* __restrict__ cbc,
                            const float* __restrict__ swc, const float* __restrict__ sbc,
                            const float* __restrict__ cwp, const float* __restrict__ cbp,
                            const float* __restrict__ swp, const float* __restrict__ sbp,
                            const float* __restrict__ Wv,  const float* __restrict__ bv){
  int tid = threadIdx.x;
  if (tid == 0) threefry(0u, 42u, 0u, 0u, g_key[0], g_key[1]);
  if (tid == 1) threefry(0u, 42u, 0u, 1u, g_key[2], g_key[3]);

  if (tid >= 2 && tid < 2 + NVC*KW){
    int i = tid - 2, g = i / KW, k = i % KW;
    float s = 0.f;
    for (int d = 0; d < D; ++d) s = fmaf(cwc[(g*D + d)*KW + k], swc[d], s);
    g_Ac[i] = s;
  } else if (tid >= 26 && tid < 26 + NVC){
    int g = tid - 26;
    float s = 0.f;
    for (int d = 0; d < D; ++d) s = fmaf(cbc[g*D + d], swc[d], s);
    g_Cc[g] = s + sbc[0];
  } else if (tid >= 34 && tid < 34 + NVP*KW){
    int i = tid - 34, g = i / KW, k = i % KW;
    float s = 0.f;
    for (int d = 0; d < D; ++d) s = fmaf(cwp[(g*D + d)*KW + k], swp[d], s);
    g_Ap[i] = s;
  } else if (tid >= 46 && tid < 46 + NVP){
    int g = tid - 46;
    float s = 0.f;
    for (int d = 0; d < D; ++d) s = fmaf(cbp[g*D + d], swp[d], s);
    g_Cp[g] = s + sbp[0];
  } else if (tid >= 50 && tid < 50 + L*DKh){
    int i = tid - 50, l = i / DKh, d = i % DKh;
    float s = 0.f;
    for (int h = 0; h < H; ++h) s += bv[l*D + h*DKh + d];
    g_bvc[i] = s * (1.0f/H);
  }

  for (int i = tid; i < L*D*DKh; i += blockDim.x){
    int l = i / (D*DKh), e = (i / DKh) % D, d = i % DKh;
    float s = 0.f;
    for (int h = 0; h < H; ++h) s += Wv[l*D*D + e*D + h*DKh + d];
    g_Wvc[i] = s * (1.0f/H);
  }
}

// ---------------- selector ----------------
template<int NV, int TS, int WHICH>
__global__ void selector_kernel(const float* __restrict__ xin,
                                float* __restrict__ dout, int oofs){
  int r = blockIdx.x * blockDim.x + threadIdx.x;
  if (r >= B*TS) return;
  int b = r / TS, t = r % TS;

  const float* A = (WHICH == 0) ? g_Ac : g_Ap;
  const float* C = (WHICH == 0) ? g_Cc : g_Cp;
  float* wscr    = (WHICH == 0) ? g_wc : g_wp;
  unsigned k0 = g_key[WHICH*2], k1 = g_key[WHICH*2 + 1];

  const int N = B*TS*NV, half = N >> 1;
  float z[NV];
  float m = -1e30f;
  #pragma unroll
  for (int g = 0; g < NV; ++g){
    float x0  = xin[(b*TS + t)*NV + g];
    float xm1 = (t >= 1) ? xin[(b*TS + t - 1)*NV + g] : 0.f;
    float xm2 = (t >= 2) ? xin[(b*TS + t - 2)*NV + g] : 0.f;
    float s = A[g*KW+0]*xm2 + A[g*KW+1]*xm1 + A[g*KW+2]*x0 + C[g];
    s = fminf(10.f, fmaxf(-10.f, s));
    int idx = (b*TS + t)*NV + g;
    unsigned o0, o1, bits;
    if (idx < half){ threefry(k0, k1, (unsigned)idx, (unsigned)(idx + half), o0, o1); bits = o0; }
    else           { threefry(k0, k1, (unsigned)(idx - half), (unsigned)idx, o0, o1); bits = o1; }
    float fu = __uint_as_float((bits >> 9) | 0x3f800000u) - 1.0f;
    const float lom = -0.99999994f, him = 1.0f;
    float u = fmaxf(lom, fmaf(fu, him - lom, lom));
    s = s + 1e-4f * (1.41421356f * erfinv32(u));
    z[g] = 0.5f * s;
    m = fmaxf(m, z[g]);
  }
  #pragma unroll
  for (int g = 0; g < NV; ++g) z[g] -= m;

  float tau = -1.0f;
  #pragma unroll 1
  for (int it = 0; it < 22; ++it){
    float f = 0.f, gg = 0.f;
    #pragma unroll
    for (int g = 0; g < NV; ++g){
      float dd = fmaxf(z[g] - tau, 0.f);
      f = fmaf(dd, dd, f); gg += dd;
    }
    tau += (f - 1.0f) / fmaxf(2.0f*gg, 1e-30f);
  }
  #pragma unroll
  for (int g = 0; g < NV; ++g){
    float dd = fmaxf(z[g] - tau, 0.f);
    float p = dd*dd;
    wscr[r*NV + g] = p;
    dout[oofs + r*NV + g] = p;
  }
}

// ---------------- weighted conv features -> concat x (B,T,128) ----------------
__global__ void weighted_kernel(const float* __restrict__ xc, const float* __restrict__ xp,
                                const float* __restrict__ cwc, const float* __restrict__ cbc,
                                const float* __restrict__ cwp, const float* __restrict__ cbp){
  int bt = blockIdx.x;
  int d = threadIdx.x;
  int b = bt / T, t = bt % T;
  const float *xin, *cw, *cb, *wsel;
  int nv, Ts, tt;
  if (t < TCOND){ xin = xc; cw = cwc; cb = cbc; wsel = g_wc; nv = NVC; Ts = TCOND; tt = t; }
  else          { xin = xp; cw = cwp; cb = cbp; wsel = g_wp; nv = NVP; Ts = TPRED; tt = t - TCOND; }
  float acc = 0.f;
  for (int g = 0; g < nv; ++g){
    float w = wsel[(b*Ts + tt)*nv + g];
    float x0  = xin[(b*Ts + tt)*nv + g];
    float xm1 = (tt >= 1) ? xin[(b*Ts + tt - 1)*nv + g] : 0.f;
    float xm2 = (tt >= 2) ? xin[(b*Ts + tt - 2)*nv + g] : 0.f;
    const float* cwg = cw + (g*D + d)*KW;
    float ls = cb[g*D + d] + cwg[0]*xm2 + cwg[1]*xm1 + cwg[2]*x0;
    acc = fmaf(w, ls, acc);
  }
  g_x[(b*T + t)*D + d] = acc;
}

// ---------------- qkv column stage (shared by qkv_kernel and fused ffn) ----------------
__device__ __forceinline__ void qkv_stage(int l, int b, int t0,
                                          const float (*xr)[D], int tid,
                                          const float* __restrict__ Wq, const float* __restrict__ bq,
                                          const float* __restrict__ Wk, const float* __restrict__ bk){
  for (int col = tid; col < 2*D + DKh; col += 256){
    const float* W; float bias; int c, ld, kind;
    if (col < D)        { c = col;       W = Wq + l*D*D;       bias = bq[l*D + c];     ld = D;   kind = 0; }
    else if (col < 2*D) { c = col - D;   W = Wk + l*D*D;       bias = bk[l*D + c];     ld = D;   kind = 1; }
    else                { c = col - 2*D; W = g_Wvc + l*D*DKh;  bias = g_bvc[l*DKh+c];  ld = DKh; kind = 2; }
    float acc[8];
    #pragma unroll
    for (int r = 0; r < 8; ++r) acc[r] = bias;
    for (int e = 0; e < D; ++e){
      float w = W[e*ld + c];
      #pragma unroll
      for (int r = 0; r < 8; ++r) acc[r] = fmaf(xr[r][e], w, acc[r]);
    }
    #pragma unroll
    for (int r = 0; r < 8; ++r){
      int t = t0 + r;
      if (kind == 0)      g_q[(b*T + t)*D + c] = acc[r];
      else if (kind == 1){ int h = c / DKh, d = c % DKh;
                           g_kT[((b*H + h)*DKh + d)*T + t] = acc[r]; }
      else                g_vcT[((size_t)b*DKh + c)*T + t] = acc[r];
    }
  }
}

// ---------------- QKV standalone (layer 0 only) ----------------
__global__ void qkv_kernel(int l, const float* __restrict__ Wq, const float* __restrict__ bq,
                           const float* __restrict__ Wk, const float* __restrict__ bk){
  __shared__ float xr[8][D];
  if (blockIdx.x == 0 && threadIdx.x == 0) g_ctr = 0;   // reset attn work queue
  int b  = blockIdx.x / (T/8);
  int t0 = (blockIdx.x % (T/8)) * 8;
  int tid = threadIdx.x;  // 256
  for (int i = tid; i < 8*D; i += 256) xr[i/D][i%D] = g_x[(b*T + t0 + i/D)*D + (i%D)];
  __syncthreads();
  qkv_stage(l, b, t0, xr, tid, Wq, bq, Wk, bk);
}

// ---------------- chunk loader: 16 rows x 384 cols from row-strided source ----------------
// 256 threads: 6 x 16B per thread
__device__ __forceinline__ void issue_chunk(unsigned sdst, const float* gsrc, int tid){
  #pragma unroll
  for (int i = 0; i < 6; ++i){
    int u = i*256 + tid;
    int e = u / 96, off = u - e*96;
    unsigned sa = sdst + (unsigned)(e*1536 + off*16);
    const char* ga = (const char*)gsrc + (size_t)e*T*4 + (size_t)off*16;
    asm volatile("cp.async.cg.shared.global [%0], [%1], 16;\n" :: "r"(sa), "l"(ga) : "memory");
  }
  asm volatile("cp.async.commit_group;\n" ::: "memory");
}

// ---------------- fused attention: persistent, work-stealing, 2 rows per warp ----------------
// block = 256 threads (8 warps x 2 rows = 16-row tile); smem = 2 x 24KB chunk buffers
__global__ void __launch_bounds__(256, 1) attn_fused_kernel(int l, float* __restrict__ dout){
  extern __shared__ float chbuf[];         // 2 * CHF floats (48 KB)
  __shared__ float qs[RPT*D];              // 8 KB q tile
  __shared__ int s_tile;

  const int tid = threadIdx.x, w = tid >> 5, lane = tid & 31;
  const unsigned sbase = (unsigned)__cvta_generic_to_shared(chbuf);
  int cur = 0;

  for (;;){
    __syncthreads();
    if (tid == 0) s_tile = atomicAdd(&g_ctr, 1);
    __syncthreads();
    int u = s_tile;
    if (u >= NTILE) break;

    // descending-cost (LPT) ordering
    int tr = (T/RPT - 1) - (u >> 1);
    int b  = u & 1;
    int t0 = tr*RPT + w*2;                 // this warp's rows: t0, t0+1
    int t1 = t0 + 1;
    int tmax = tr*RPT + (RPT-1);
    int ncc  = tmax/CHW + 1;               // active chunks (1..4), block-uniform

    // stage q tile [16][128]
    for (int i = tid; i < RPT*D; i += 256)
      qs[i] = g_q[(size_t)(b*T + tr*RPT + (i >> 7))*D + (i & 127)];

    const float* kbase = g_kT + (size_t)b*H*SL;
    const float* vbase = g_vcT + (size_t)b*DKh*T;

    // prologue: issue k chunk (h=0, c=0) into buf[cur]
    issue_chunk(sbase + (unsigned)cur*(CHF*4), kbase, tid);

    float wa0[NJ], wa1[NJ];
    #pragma unroll
    for (int j = 0; j < NJ; ++j){ wa0[j] = 0.f; wa1[j] = 0.f; }

    #pragma unroll 1
    for (int h = 0; h < H; ++h){
      float z0[NJ], z1[NJ];
      #pragma unroll
      for (int c = 0; c < 4; ++c){
        if (c < ncc){
          asm volatile("cp.async.wait_group 0;\n" ::: "memory");
          __syncthreads();
          // issue next chunk into other buffer
          if (c + 1 < ncc)      issue_chunk(sbase + (unsigned)(cur^1)*(CHF*4), kbase + (size_t)h*SL + (c+1)*CHW, tid);
          else if (h + 1 < H)   issue_chunk(sbase + (unsigned)(cur^1)*(CHF*4), kbase + (size_t)(h+1)*SL, tid);
          else                  issue_chunk(sbase + (unsigned)(cur^1)*(CHF*4), vbase, tid);
          // scores for chunk c: lane owns columns c*384 + g*128 + lane*4 + r
          const float* kb = chbuf + cur*CHF;
          #pragma unroll
          for (int g = 0; g < 3; ++g){
            #pragma unroll
            for (int r = 0; r < 4; ++r){ z0[c*12 + g*4 + r] = 0.f; z1[c*12 + g*4 + r] = 0.f; }
          }
          #pragma unroll 4
          for (int e = 0; e < DKh; ++e){
            float qe0 = qs[(w*2+0)*D + h*DKh + e];
            float qe1 = qs[(w*2+1)*D + h*DKh + e];
            const float4* kr = (const float4*)(kb + e*CHW);
            #pragma unroll
            for (int g = 0; g < 3; ++g){
              float4 kv = kr[g*32 + lane];
              z0[c*12 + g*4 + 0] = fmaf(qe0, kv.x, z0[c*12 + g*4 + 0]);
              z0[c*12 + g*4 + 1] = fmaf(qe0, kv.y, z0[c*12 + g*4 + 1]);
              z0[c*12 + g*4 + 2] = fmaf(qe0, kv.z, z0[c*12 + g*4 + 2]);
              z0[c*12 + g*4 + 3] = fmaf(qe0, kv.w, z0[c*12 + g*4 + 3]);
              z1[c*12 + g*4 + 0] = fmaf(qe1, kv.x, z1[c*12 + g*4 + 0]);
              z1[c*12 + g*4 + 1] = fmaf(qe1, kv.y, z1[c*12 + g*4 + 1]);
              z1[c*12 + g*4 + 2] = fmaf(qe1, kv.z, z1[c*12 + g*4 + 2]);
              z1[c*12 + g*4 + 3] = fmaf(qe1, kv.w, z1[c*12 + g*4 + 3]);
            }
          }
          cur ^= 1;
        }
      }

      // mask + zmax (both rows)
      float m0 = -3.0e30f, m1 = -3.0e30f;
      #pragma unroll
      for (int c = 0; c < 4; ++c){
        if (c < ncc){
          #pragma unroll
          for (int g = 0; g < 3; ++g){
            int sb4 = c*CHW + g*128 + (lane << 2);
            #pragma unroll
            for (int r = 0; r < 4; ++r){
              int j = c*12 + g*4 + r;
              int col = sb4 + r;
              float a0 = (col <= t0) ? z0[j]*0.125f : -5000.0f;
              float a1 = (col <= t1) ? z1[j]*0.125f : -5000.0f;
              z0[j] = a0; z1[j] = a1;
              m0 = fmaxf(m0, a0); m1 = fmaxf(m1, a1);
            }
          }
        }
      }
      #pragma unroll
      for (int off = 16; off; off >>= 1){
        m0 = fmaxf(m0, __shfl_xor_sync(~0u, m0, off));
        m1 = fmaxf(m1, __shfl_xor_sync(~0u, m1, off));
      }

      // active-set exact-quadratic solver for both rows (interleaved)
      float lo0 = m0 - 1.f, hi0 = m0, tau0 = m0 - 1.f;
      float lo1 = m1 - 1.f, hi1 = m1, tau1 = m1 - 1.f;
      #pragma unroll 1
      for (int it = 0; it < 6; ++it){
        float f0 = 0.f, g0 = 0.f, n0 = 0.f;
        float f1 = 0.f, g1 = 0.f, n1 = 0.f;
        #pragma unroll
        for (int c = 0; c < 4; ++c){
          if (c < ncc){
            #pragma unroll
            for (int jj = 0; jj < 12; ++jj){
              int j = c*12 + jj;
              float d0 = z0[j] - tau0, d1 = z1[j] - tau1;
              float p0 = fmaxf(d0, 0.f), p1 = fmaxf(d1, 0.f);
              f0 = fmaf(p0, p0, f0); g0 += p0; n0 += (d0 > 0.f) ? 1.f : 0.f;
              f1 = fmaf(p1, p1, f1); g1 += p1; n1 += (d1 > 0.f) ? 1.f : 0.f;
            }
          }
        }
        #pragma unroll
        for (int off = 16; off; off >>= 1){
          f0 += __shfl_xor_sync(~0u, f0, off);
          f1 += __shfl_xor_sync(~0u, f1, off);
          g0 += __shfl_xor_sync(~0u, g0, off);
          g1 += __shfl_xor_sync(~0u, g1, off);
          n0 += __shfl_xor_sync(~0u, n0, off);
          n1 += __shfl_xor_sync(~0u, n1, off);
        }
        if (f0 > 1.f) lo0 = fmaxf(lo0, tau0); else hi0 = fminf(hi0, tau0);
        if (f1 > 1.f) lo1 = fmaxf(lo1, tau1); else hi1 = fminf(hi1, tau1);
        float d0 = fmaf(g0, g0, -n0*(f0 - 1.f));
        float d1 = fmaf(g1, g1, -n1*(f1 - 1.f));
        float nt0 = tau0 + (g0 - sqrtf(fmaxf(d0, 0.f))) / n0;
        float nt1 = tau1 + (g1 - sqrtf(fmaxf(d1, 0.f))) / n1;
        if (!(d0 > 0.f) || !(nt0 >= lo0 && nt0 <= hi0)) nt0 = 0.5f*(lo0 + hi0);
        if (!(d1 > 0.f) || !(nt1 >= lo1 && nt1 <= hi1)) nt1 = 0.5f*(lo1 + hi1);
        tau0 = nt0; tau1 = nt1;
      }
      #pragma unroll
      for (int c = 0; c < 4; ++c){
        if (c < ncc){
          #pragma unroll
          for (int jj = 0; jj < 12; ++jj){
            int j = c*12 + jj;
            float p0 = fmaxf(z0[j] - tau0, 0.f);
            float p1 = fmaxf(z1[j] - tau1, 0.f);
            wa0[j] = fmaf(p0, p0, wa0[j]);
            wa1[j] = fmaf(p1, p1, wa1[j]);
          }
        }
      }
    }

    // epilogue: head-average -> logs, y = w_avg @ v_comb (v chunks pipelined)
    float* logrow0 = dout + LOGS_OFS + (size_t)((l*B + b)*T + t0)*T;
    float* logrow1 = dout + LOGS_OFS + (size_t)((l*B + b)*T + t1)*T;
    float acc0[DKh], acc1[DKh];
    #pragma unroll
    for (int e = 0; e < DKh; ++e){ acc0[e] = 0.f; acc1[e] = 0.f; }

    #pragma unroll
    for (int c = 0; c < 4; ++c){
      if (c < ncc){
        asm volatile("cp.async.wait_group 0;\n" ::: "memory");
        __syncthreads();
        if (c + 1 < ncc) issue_chunk(sbase + (unsigned)(cur^1)*(CHF*4), vbase + (c+1)*CHW, tid);
        const float* vb = chbuf + cur*CHF;
        #pragma unroll
        for (int g = 0; g < 3; ++g){
          int j = c*12 + g*4;
          float a0 = wa0[j+0]*0.125f, a1 = wa0[j+1]*0.125f, a2 = wa0[j+2]*0.125f, a3 = wa0[j+3]*0.125f;
          float b0 = wa1[j+0]*0.125f, b1 = wa1[j+1]*0.125f, b2 = wa1[j+2]*0.125f, b3 = wa1[j+3]*0.125f;
          ((float4*)(logrow0 + c*CHW + g*128))[lane] = make_float4(a0, a1, a2, a3);
          ((float4*)(logrow1 + c*CHW + g*128))[lane] = make_float4(b0, b1, b2, b3);
          #pragma unroll
          for (int e = 0; e < DKh; ++e){
            float4 vv = ((const float4*)(vb + e*CHW + g*128))[lane];
            acc0[e] = fmaf(a0, vv.x, acc0[e]);
            acc0[e] = fmaf(a1, vv.y, acc0[e]);
            acc0[e] = fmaf(a2, vv.z, acc0[e]);
            acc0[e] = fmaf(a3, vv.w, acc0[e]);
            acc1[e] = fmaf(b0, vv.x, acc1[e]);
            acc1[e] = fmaf(b1, vv.y, acc1[e]);
            acc1[e] = fmaf(b2, vv.z, acc1[e]);
            acc1[e] = fmaf(b3, vv.w, acc1[e]);
          }
        }
        cur ^= 1;
      } else {
        #pragma unroll
        for (int g = 0; g < 3; ++g){
          ((float4*)(logrow0 + c*CHW + g*128))[lane] = make_float4(0.f, 0.f, 0.f, 0.f);
          ((float4*)(logrow1 + c*CHW + g*128))[lane] = make_float4(0.f, 0.f, 0.f, 0.f);
        }
      }
    }

    float myv0 = 0.f, myv1 = 0.f;
    #pragma unroll
    for (int e = 0; e < DKh; ++e){
      float v0 = acc0[e], v1 = acc1[e];
      #pragma unroll
      for (int off = 16; off; off >>= 1){
        v0 += __shfl_xor_sync(~0u, v0, off);
        v1 += __shfl_xor_sync(~0u, v1, off);
      }
      if (lane == e){ myv0 = v0; myv1 = v1; }
    }
    if (lane < DKh){
      g_y[(size_t)(b*T + t0)*DKh + lane] = myv0;
      g_y[(size_t)(b*T + t1)*DKh + lane] = myv1;
    }
  }
}

// ---------------- fused Wo + LN1 + FFN + LN2 (+ next-layer QKV) : 8 rows per block ----------------
__global__ void __launch_bounds__(256) ffn_kernel(
    int l, int fuse,
    const float* __restrict__ Wo,  const float* __restrict__ bo,
    const float* __restrict__ g1,  const float* __restrict__ b1,
    const float* __restrict__ fw1, const float* __restrict__ fb1,
    const float* __restrict__ fw2, const float* __restrict__ fb2,
    const float* __restrict__ g2,  const float* __restrict__ b2,
    const float* __restrict__ Wq,  const float* __restrict__ bq,
    const float* __restrict__ Wk,  const float* __restrict__ bk){
  __shared__ float xs[8][D];
  __shared__ float xsT[D][12];    // stride 12 (48B rows): float4 @0/@16 aligned, fewer bank conflicts
  __shared__ float hsT[DFF][12];  // stride 12
  __shared__ float o3[8][D];
  if (fuse && blockIdx.x == 0 && threadIdx.x == 0) g_ctr = 0;  // reset attn queue for layer l+1
  int bidx = blockIdx.x;
  int b  = bidx / (T/8);
  int t0 = (bidx % (T/8)) * 8;
  int tid = threadIdx.x, w = tid >> 5, lane = tid & 31;
  int t = t0 + w;

  // step 1: a = y@Wo + bo ; LN1(x + a) -> xs, xsT
  {
    float yv[DKh];
    #pragma unroll
    for (int e = 0; e < DKh; ++e) yv[e] = g_y[(b*T + t)*DKh + e];
    float tv[4];
    #pragma unroll
    for (int i = 0; i < 4; ++i){
      int c = lane + 32*i;
      float a = bo[l*D + c];
      #pragma unroll
      for (int e = 0; e < DKh; ++e) a = fmaf(yv[e], Wo[l*DKh*D + e*D + c], a);
      tv[i] = g_x[(b*T + t)*D + c] + a;
    }
    float s = tv[0] + tv[1] + tv[2] + tv[3];
    #pragma unroll
    for (int off = 16; off; off >>= 1) s += __shfl_xor_sync(~0u, s, off);
    float m = s * (1.0f/D);
    float sq = 0.f;
    #pragma unroll
    for (int i = 0; i < 4; ++i){ float dv = tv[i] - m; sq = fmaf(dv, dv, sq); }
    #pragma unroll
    for (int off = 16; off; off >>= 1) sq += __shfl_xor_sync(~0u, sq, off);
    float rs = rsqrtf(sq * (1.0f/D) + 1e-5f);
    #pragma unroll
    for (int i = 0; i < 4; ++i){
      int c = lane + 32*i;
      float v = (tv[i] - m) * rs * g1[l*D + c] + b1[l*D + c];
      xs[w][c] = v;
      xsT[c][w] = v;
    }
  }
  __syncthreads();

  // step 2: hT = relu(xs @ fw1 + fb1), transposed [DFF][12-padded]
  {
    int c = tid;                // columns c and c+256
    float a0[8], a1[8];
    float bb0 = fb1[l*DFF + c], bb1 = fb1[l*DFF + c + 256];
    #pragma unroll
    for (int r = 0; r < 8; ++r){ a0[r] = bb0; a1[r] = bb1; }
    const float* W = fw1 + l*D*DFF;
    for (int e = 0; e < D; ++e){
      float w0 = W[e*DFF + c];
      float w1 = W[e*DFF + c + 256];
      float4 xA = *(const float4*)&xsT[e][0];
      float4 xB = *(const float4*)&xsT[e][4];
      a0[0]=fmaf(w0,xA.x,a0[0]); a0[1]=fmaf(w0,xA.y,a0[1]); a0[2]=fmaf(w0,xA.z,a0[2]); a0[3]=fmaf(w0,xA.w,a0[3]);
      a0[4]=fmaf(w0,xB.x,a0[4]); a0[5]=fmaf(w0,xB.y,a0[5]); a0[6]=fmaf(w0,xB.z,a0[6]); a0[7]=fmaf(w0,xB.w,a0[7]);
      a1[0]=fmaf(w1,xA.x,a1[0]); a1[1]=fmaf(w1,xA.y,a1[1]); a1[2]=fmaf(w1,xA.z,a1[2]); a1[3]=fmaf(w1,xA.w,a1[3]);
      a1[4]=fmaf(w1,xB.x,a1[4]); a1[5]=fmaf(w1,xB.y,a1[5]); a1[6]=fmaf(w1,xB.z,a1[6]); a1[7]=fmaf(w1,xB.w,a1[7]);
    }
    #pragma unroll
    for (int r = 0; r < 8; ++r){ a0[r] = fmaxf(a0[r], 0.f); a1[r] = fmaxf(a1[r], 0.f); }
    *(float4*)&hsT[c][0]       = make_float4(a0[0], a0[1], a0[2], a0[3]);
    *(float4*)&hsT[c][4]       = make_float4(a0[4], a0[5], a0[6], a0[7]);
    *(float4*)&hsT[c + 256][0] = make_float4(a1[0], a1[1], a1[2], a1[3]);
    *(float4*)&hsT[c + 256][4] = make_float4(a1[4], a1[5], a1[6], a1[7]);
  }
  __syncthreads();

  // step 3: o3 = h @ fw2 + fb2 + xs   (thread: col c, 4 rows)
  {
    int c  = tid & 127;
    int rh = tid >> 7;           // 0 or 1 -> rows rh*4 .. rh*4+3
    float acc[4] = {0.f, 0.f, 0.f, 0.f};
    const float* W = fw2 + l*DFF*D;
    for (int s2 = 0; s2 < DFF; ++s2){
      float wv = W[s2*D + c];
      float4 hv = *(const float4*)&hsT[s2][rh*4];
      acc[0] = fmaf(wv, hv.x, acc[0]);
      acc[1] = fmaf(wv, hv.y, acc[1]);
      acc[2] = fmaf(wv, hv.z, acc[2]);
      acc[3] = fmaf(wv, hv.w, acc[3]);
    }
    float bb = fb2[l*D + c];
    #pragma unroll
    for (int k = 0; k < 4; ++k) o3[rh*4 + k][c] = acc[k] + bb + xs[rh*4 + k][c];
  }
  __syncthreads();

  // step 4: LN2 -> g_x (and xs, for the fused next-layer QKV)
  {
    float tv[4];
    #pragma unroll
    for (int i = 0; i < 4; ++i) tv[i] = o3[w][lane + 32*i];
    float s = tv[0] + tv[1] + tv[2] + tv[3];
    #pragma unroll
    for (int off = 16; off; off >>= 1) s += __shfl_xor_sync(~0u, s, off);
    float m = s * (1.0f/D);
    float sq = 0.f;
    #pragma unroll
    for (int i = 0; i < 4; ++i){ float dv = tv[i] - m; sq = fmaf(dv, dv, sq); }
    #pragma unroll
    for (int off = 16; off; off >>= 1) sq += __shfl_xor_sync(~0u, sq, off);
    float rs = rsqrtf(sq * (1.0f/D) + 1e-5f);
    #pragma unroll
    for (int i = 0; i < 4; ++i){
      int c = lane + 32*i;
      float v = (tv[i] - m) * rs * g2[l*D + c] + b2[l*D + c];
      g_x[(b*T + t)*D + c] = v;
      xs[w][c] = v;
    }
  }

  // step 5 (fused): next-layer QKV from xs
  if (fuse){
    __syncthreads();
    qkv_stage(l + 1, b, t0, xs, tid, Wq, bq, Wk, bk);
  }
}

// ---------------- final projection ----------------
__global__ void proj_kernel(const float* __restrict__ pw, const float* __restrict__ pb,
                            float* __restrict__ dout){
  int i = threadIdx.x;  // 576 threads
  int b = i / (NQ*HOR), q = (i / HOR) % NQ, hh = i % HOR;
  float acc = pb[q*HOR + hh];
  const float* xr = g_x + (b*T + (T-1))*D;
  for (int d = 0; d < D; ++d) acc = fmaf(xr[d], pw[(q*D + d)*HOR + hh], acc);
  dout[(b*NQ + q)*HOR + hh] = acc;
}

// ---------------- launch ----------------
extern "C" void kernel_launch(void* const* d_in, const int* in_sizes, int n_in,
                              void* d_out, int out_size) {
  const float* x_cond = (const float*)d_in[0];
  const float* x_pred = (const float*)d_in[1];
  const float* cw_c   = (const float*)d_in[2];
  const float* cb_c   = (const float*)d_in[3];
  const float* sw_c   = (const float*)d_in[4];
  const float* sb_c   = (const float*)d_in[5];
  const float* cw_p   = (const float*)d_in[6];
  const float* cb_p   = (const float*)d_in[7];
  const float* sw_p   = (const float*)d_in[8];
  const float* sb_p   = (const float*)d_in[9];
  const float* Wq     = (const float*)d_in[10];
  const float* bq     = (const float*)d_in[11];
  const float* Wk     = (const float*)d_in[12];
  const float* bk     = (const float*)d_in[13];
  const float* Wv     = (const float*)d_in[14];
  const float* bv     = (const float*)d_in[15];
  const float* Wo     = (const float*)d_in[16];
  const float* bo     = (const float*)d_in[17];
  const float* ln1_g  = (const float*)d_in[18];
  const float* ln1_b  = (const float*)d_in[19];
  const float* fw1    = (const float*)d_in[20];
  const float* fb1    = (const float*)d_in[21];
  const float* fw2    = (const float*)d_in[22];
  const float* fb2    = (const float*)d_in[23];
  const float* ln2_g  = (const float*)d_in[24];
  const float* ln2_b  = (const float*)d_in[25];
  const float* proj_w = (const float*)d_in[26];
  const float* proj_b = (const float*)d_in[27];
  float* out = (float*)d_out;

  const int smemA = 2 * CHF * (int)sizeof(float);   // 49152 B dynamic
  cudaFuncSetAttribute(attn_fused_kernel, cudaFuncAttributeMaxDynamicSharedMemorySize, smemA);

  prep_kernel<<<1, 256>>>(cw_c, cb_c, sw_c, sb_c, cw_p, cb_p, sw_p, sb_p, Wv, bv);
  selector_kernel<NVC, TCOND, 0><<<(B*TCOND + 127)/128, 128>>>(x_cond, out, VC_OFS);
  selector_kernel<NVP, TPRED, 1><<<(B*TPRED + 127)/128, 128>>>(x_pred, out, VP_OFS);
  weighted_kernel<<<B*T, 128>>>(x_cond, x_pred, cw_c, cb_c, cw_p, cb_p);

  qkv_kernel<<<B*T/8, 256>>>(0, Wq, bq, Wk, bk);
  for (int l = 0; l < L; ++l){
    attn_fused_kernel<<<148, 256, smemA>>>(l, out);
    ffn_kernel<<<B*T/8, 256>>>(l, (l + 1 < L) ? 1 : 0,
                               Wo, bo, ln1_g, ln1_b, fw1, fb1, fw2, fb2, ln2_g, ln2_b,
                               Wq, bq, Wk, bk);
  }
  proj_kernel<<<1, B*NQ*HOR>>>(proj_w, proj_b, out);
}

// round 16
// speedup vs baseline: 1.1415x; 1.0162x over previous
#include <cuda_runtime.h>
#include <cuda_bf16.h>
#include <stdint.h>

// ---------------- problem constants ----------------
namespace {
constexpr int B = 2, TCOND = 1024, TPRED = 512, NVC = 8, NVP = 4;
constexpr int D = 128, KW = 3, H = 8, DFF = 512, L = 2, HOR = 96, NQ = 3;
constexpr int T = TCOND + TPRED;   // 1536
constexpr int DKh = D / H;         // 16
constexpr int NJ = T / 32;         // 48 (12 per chunk * 4 chunks)
constexpr int SL = DKh * T;        // 24576 floats per (b,h) kT slab
constexpr int RPT = 16;            // rows per tile (2 per warp, 8 warps)
constexpr int NTILE = B * (T / RPT); // 192 tiles
constexpr int CHW = 384;           // chunk width (columns)
constexpr int CHF = DKh * CHW;     // 6144 floats per chunk (24 KB)

constexpr int VC_OFS   = B * NQ * HOR;              // 576
constexpr int VP_OFS   = VC_OFS + B * TCOND * NVC;  // 16960
constexpr int LOGS_OFS = VP_OFS + B * TPRED * NVP;  // 21056
}

// ---------------- device scratch (static, no allocation) ----------------
__device__ float g_x[B*T*D];
__device__ float g_q[B*T*D];
__device__ float g_kT[B*H*SL];
__device__ float g_vcT[B*DKh*T];     // v_comb transposed: [b][e][T]
__device__ float g_y[B*T*DKh];
__device__ float g_wc[B*TCOND*NVC];
__device__ float g_wp[B*TPRED*NVP];
__device__ float g_Ac[NVC*KW], g_Cc[NVC], g_Ap[NVP*KW], g_Cp[NVP];
__device__ float g_Wvc[L*D*DKh], g_bvc[L*DKh];
__device__ unsigned g_key[4];
__device__ int g_ctr;                // attention tile work queue

// ---------------- threefry2x32 (matches JAX) ----------------
__device__ __forceinline__ unsigned rotl32(unsigned v, int r){ return (v<<r)|(v>>(32-r)); }

__device__ __forceinline__ void threefry(unsigned k0, unsigned k1,
                                         unsigned x0, unsigned x1,
                                         unsigned& o0, unsigned& o1){
  unsigned ks2 = k0 ^ k1 ^ 0x1BD11BDAu;
  unsigned ks[3] = {k0, k1, ks2};
  x0 += ks[0]; x1 += ks[1];
  const int R0[4] = {13,15,26,6};
  const int R1[4] = {17,29,16,24};
  #pragma unroll
  for (int i = 0; i < 5; ++i){
    #pragma unroll
    for (int j = 0; j < 4; ++j){
      int r = (i & 1) ? R1[j] : R0[j];
      x0 += x1; x1 = rotl32(x1, r); x1 ^= x0;
    }
    x0 += ks[(i+1)%3];
    x1 += ks[(i+2)%3] + (unsigned)(i+1);
  }
  o0 = x0; o1 = x1;
}

// ---------------- XLA f32 erfinv ----------------
__device__ __forceinline__ float erfinv32(float x){
  float w = -log1pf(-x*x);
  float p;
  if (w < 5.0f){
    w = w - 2.5f;
    p = 2.81022636e-08f;
    p = fmaf(p, w, 3.43273939e-07f);
    p = fmaf(p, w, -3.5233877e-06f);
    p = fmaf(p, w, -4.39150654e-06f);
    p = fmaf(p, w, 0.00021858087f);
    p = fmaf(p, w, -0.00125372503f);
    p = fmaf(p, w, -0.00417768164f);
    p = fmaf(p, w, 0.246640727f);
    p = fmaf(p, w, 1.50140941f);
  } else {
    w = sqrtf(w) - 3.0f;
    p = -0.000200214257f;
    p = fmaf(p, w, 0.000100950558f);
    p = fmaf(p, w, 0.00134934322f);
    p = fmaf(p, w, -0.00367342844f);
    p = fmaf(p, w, 0.00573950773f);
    p = fmaf(p, w, -0.0076224613f);
    p = fmaf(p, w, 0.00943887047f);
    p = fmaf(p, w, 1.00167406f);
    p = fmaf(p, w, 2.83297682f);
  }
  return p * x;
}

// ---------------- prep: keys, folded selector weights, head-averaged Wv ----------------
__global__ void prep_kernel(const float* __restrict__ cwc, const float* __restrict__ cbc,
                            const float* __restrict__ swc, const float* __restrict__ sbc,
                            const float* __restrict__ cwp, const float* __restrict__ cbp,
                            const float* __restrict__ swp, const float* __restrict__ sbp,
                            const float* __restrict__ Wv,  const float* __restrict__ bv){
  int tid = threadIdx.x;
  if (tid == 0) threefry(0u, 42u, 0u, 0u, g_key[0], g_key[1]);
  if (tid == 1) threefry(0u, 42u, 0u, 1u, g_key[2], g_key[3]);

  if (tid >= 2 && tid < 2 + NVC*KW){
    int i = tid - 2, g = i / KW, k = i % KW;
    float s = 0.f;
    for (int d = 0; d < D; ++d) s = fmaf(cwc[(g*D + d)*KW + k], swc[d], s);
    g_Ac[i] = s;
  } else if (tid >= 26 && tid < 26 + NVC){
    int g = tid - 26;
    float s = 0.f;
    for (int d = 0; d < D; ++d) s = fmaf(cbc[g*D + d], swc[d], s);
    g_Cc[g] = s + sbc[0];
  } else if (tid >= 34 && tid < 34 + NVP*KW){
    int i = tid - 34, g = i / KW, k = i % KW;
    float s = 0.f;
    for (int d = 0; d < D; ++d) s = fmaf(cwp[(g*D + d)*KW + k], swp[d], s);
    g_Ap[i] = s;
  } else if (tid >= 46 && tid < 46 + NVP){
    int g = tid - 46;
    float s = 0.f;
    for (int d = 0; d < D; ++d) s = fmaf(cbp[g*D + d], swp[d], s);
    g_Cp[g] = s + sbp[0];
  } else if (tid >= 50 && tid < 50 + L*DKh){
    int i = tid - 50, l = i / DKh, d = i % DKh;
    float s = 0.f;
    for (int h = 0; h < H; ++h) s += bv[l*D + h*DKh + d];
    g_bvc[i] = s * (1.0f/H);
  }

  for (int i = tid; i < L*D*DKh; i += blockDim.x){
    int l = i / (D*DKh), e = (i / DKh) % D, d = i % DKh;
    float s = 0.f;
    for (int h = 0; h < H; ++h) s += Wv[l*D*D + e*D + h*DKh + d];
    g_Wvc[i] = s * (1.0f/H);
  }
}

// ---------------- selector ----------------
template<int NV, int TS, int WHICH>
__global__ void selector_kernel(const float* __restrict__ xin,
                                float* __restrict__ dout, int oofs){
  int r = blockIdx.x * blockDim.x + threadIdx.x;
  if (r >= B*TS) return;
  int b = r / TS, t = r % TS;

  const float* A = (WHICH == 0) ? g_Ac : g_Ap;
  const float* C = (WHICH == 0) ? g_Cc : g_Cp;
  float* wscr    = (WHICH == 0) ? g_wc : g_wp;
  unsigned k0 = g_key[WHICH*2], k1 = g_key[WHICH*2 + 1];

  const int N = B*TS*NV, half = N >> 1;
  float z[NV];
  float m = -1e30f;
  #pragma unroll
  for (int g = 0; g < NV; ++g){
    float x0  = xin[(b*TS + t)*NV + g];
    float xm1 = (t >= 1) ? xin[(b*TS + t - 1)*NV + g] : 0.f;
    float xm2 = (t >= 2) ? xin[(b*TS + t - 2)*NV + g] : 0.f;
    float s = A[g*KW+0]*xm2 + A[g*KW+1]*xm1 + A[g*KW+2]*x0 + C[g];
    s = fminf(10.f, fmaxf(-10.f, s));
    int idx = (b*TS + t)*NV + g;
    unsigned o0, o1, bits;
    if (idx < half){ threefry(k0, k1, (unsigned)idx, (unsigned)(idx + half), o0, o1); bits = o0; }
    else           { threefry(k0, k1, (unsigned)(idx - half), (unsigned)idx, o0, o1); bits = o1; }
    float fu = __uint_as_float((bits >> 9) | 0x3f800000u) - 1.0f;
    const float lom = -0.99999994f, him = 1.0f;
    float u = fmaxf(lom, fmaf(fu, him - lom, lom));
    s = s + 1e-4f * (1.41421356f * erfinv32(u));
    z[g] = 0.5f * s;
    m = fmaxf(m, z[g]);
  }
  #pragma unroll
  for (int g = 0; g < NV; ++g) z[g] -= m;

  float tau = -1.0f;
  #pragma unroll 1
  for (int it = 0; it < 22; ++it){
    float f = 0.f, gg = 0.f;
    #pragma unroll
    for (int g = 0; g < NV; ++g){
      float dd = fmaxf(z[g] - tau, 0.f);
      f = fmaf(dd, dd, f); gg += dd;
    }
    tau += (f - 1.0f) / fmaxf(2.0f*gg, 1e-30f);
  }
  #pragma unroll
  for (int g = 0; g < NV; ++g){
    float dd = fmaxf(z[g] - tau, 0.f);
    float p = dd*dd;
    wscr[r*NV + g] = p;
    dout[oofs + r*NV + g] = p;
  }
}

// ---------------- qkv column stage (shared) ----------------
__device__ __forceinline__ void qkv_stage(int l, int b, int t0,
                                          const float (*xr)[D], int tid,
                                          const float* __restrict__ Wq, const float* __restrict__ bq,
                                          const float* __restrict__ Wk, const float* __restrict__ bk){
  for (int col = tid; col < 2*D + DKh; col += 256){
    const float* W; float bias; int c, ld, kind;
    if (col < D)        { c = col;       W = Wq + l*D*D;       bias = bq[l*D + c];     ld = D;   kind = 0; }
    else if (col < 2*D) { c = col - D;   W = Wk + l*D*D;       bias = bk[l*D + c];     ld = D;   kind = 1; }
    else                { c = col - 2*D; W = g_Wvc + l*D*DKh;  bias = g_bvc[l*DKh+c];  ld = DKh; kind = 2; }
    float acc[8];
    #pragma unroll
    for (int r = 0; r < 8; ++r) acc[r] = bias;
    for (int e = 0; e < D; ++e){
      float w = W[e*ld + c];
      #pragma unroll
      for (int r = 0; r < 8; ++r) acc[r] = fmaf(xr[r][e], w, acc[r]);
    }
    #pragma unroll
    for (int r = 0; r < 8; ++r){
      int t = t0 + r;
      if (kind == 0)      g_q[(b*T + t)*D + c] = acc[r];
      else if (kind == 1){ int h = c / DKh, d = c % DKh;
                           g_kT[((b*H + h)*DKh + d)*T + t] = acc[r]; }
      else                g_vcT[((size_t)b*DKh + c)*T + t] = acc[r];
    }
  }
}

// ---------------- fused weighted-conv + layer-0 QKV : 8 rows per block ----------------
__global__ void __launch_bounds__(256) wqkv_kernel(
    const float* __restrict__ xc, const float* __restrict__ xp,
    const float* __restrict__ cwc, const float* __restrict__ cbc,
    const float* __restrict__ cwp, const float* __restrict__ cbp,
    const float* __restrict__ Wq,  const float* __restrict__ bq,
    const float* __restrict__ Wk,  const float* __restrict__ bk){
  __shared__ float xs[8][D];
  if (blockIdx.x == 0 && threadIdx.x == 0) g_ctr = 0;   // reset attn work queue
  int b  = blockIdx.x / (T/8);
  int t0 = (blockIdx.x % (T/8)) * 8;
  int tid = threadIdx.x;
  int d  = tid & 127;
  int rh = tid >> 7;                 // 0/1 -> rows rh*4 .. rh*4+3

  const float *xin, *cw, *cb, *wsel;
  int nv, Ts, tt0;
  if (t0 < TCOND){ xin = xc; cw = cwc; cb = cbc; wsel = g_wc; nv = NVC; Ts = TCOND; tt0 = t0; }
  else           { xin = xp; cw = cwp; cb = cbp; wsel = g_wp; nv = NVP; Ts = TPRED; tt0 = t0 - TCOND; }

  float acc[4] = {0.f, 0.f, 0.f, 0.f};
  #pragma unroll 1
  for (int g = 0; g < nv; ++g){
    const float* cwg = cw + (g*D + d)*KW;
    float c0 = cwg[0], c1 = cwg[1], c2 = cwg[2];
    float cbv = cb[g*D + d];
    #pragma unroll
    for (int k = 0; k < 4; ++k){
      int tt = tt0 + rh*4 + k;
      float w   = wsel[(b*Ts + tt)*nv + g];
      float x0  = xin[(b*Ts + tt)*nv + g];
      float xm1 = (tt >= 1) ? xin[(b*Ts + tt - 1)*nv + g] : 0.f;
      float xm2 = (tt >= 2) ? xin[(b*Ts + tt - 2)*nv + g] : 0.f;
      float ls = cbv + c0*xm2 + c1*xm1 + c2*x0;
      acc[k] = fmaf(w, ls, acc[k]);
    }
  }
  #pragma unroll
  for (int k = 0; k < 4; ++k){
    int r = rh*4 + k;
    xs[r][d] = acc[k];
    g_x[(size_t)(b*T + t0 + r)*D + d] = acc[k];
  }
  __syncthreads();
  qkv_stage(0, b, t0, xs, tid, Wq, bq, Wk, bk);
}

// ---------------- chunk loader: 16 rows x 384 cols from row-strided source ----------------
// 256 threads: 6 x 16B per thread
__device__ __forceinline__ void issue_chunk(unsigned sdst, const float* gsrc, int tid){
  #pragma unroll
  for (int i = 0; i < 6; ++i){
    int u = i*256 + tid;
    int e = u / 96, off = u - e*96;
    unsigned sa = sdst + (unsigned)(e*1536 + off*16);
    const char* ga = (const char*)gsrc + (size_t)e*T*4 + (size_t)off*16;
    asm volatile("cp.async.cg.shared.global [%0], [%1], 16;\n" :: "r"(sa), "l"(ga) : "memory");
  }
  asm volatile("cp.async.commit_group;\n" ::: "memory");
}

// ---------------- fused attention: persistent, work-stealing, 2 rows per warp ----------------
// block = 256 threads (8 warps x 2 rows = 16-row tile); smem = 2 x 24KB chunk buffers
__global__ void __launch_bounds__(256, 1) attn_fused_kernel(int l, float* __restrict__ dout){
  extern __shared__ float chbuf[];         // 2 * CHF floats (48 KB)
  __shared__ float qs[RPT*D];              // 8 KB q tile
  __shared__ int s_tile;

  const int tid = threadIdx.x, w = tid >> 5, lane = tid & 31;
  const unsigned sbase = (unsigned)__cvta_generic_to_shared(chbuf);
  int cur = 0;

  for (;;){
    __syncthreads();
    if (tid == 0) s_tile = atomicAdd(&g_ctr, 1);
    __syncthreads();
    int u = s_tile;
    if (u >= NTILE) break;

    // descending-cost (LPT) ordering
    int tr = (T/RPT - 1) - (u >> 1);
    int b  = u & 1;
    int t0 = tr*RPT + w*2;                 // this warp's rows: t0, t0+1
    int t1 = t0 + 1;
    int tmax = tr*RPT + (RPT-1);
    int ncc  = tmax/CHW + 1;               // active chunks (1..4), block-uniform

    // stage q tile [16][128]
    for (int i = tid; i < RPT*D; i += 256)
      qs[i] = g_q[(size_t)(b*T + tr*RPT + (i >> 7))*D + (i & 127)];

    const float* kbase = g_kT + (size_t)b*H*SL;
    const float* vbase = g_vcT + (size_t)b*DKh*T;

    // prologue: issue k chunk (h=0, c=0) into buf[cur]
    issue_chunk(sbase + (unsigned)cur*(CHF*4), kbase, tid);

    float wa0[NJ], wa1[NJ];
    #pragma unroll
    for (int j = 0; j < NJ; ++j){ wa0[j] = 0.f; wa1[j] = 0.f; }

    #pragma unroll 1
    for (int h = 0; h < H; ++h){
      float z0[NJ], z1[NJ];
      #pragma unroll
      for (int c = 0; c < 4; ++c){
        if (c < ncc){
          asm volatile("cp.async.wait_group 0;\n" ::: "memory");
          __syncthreads();
          // issue next chunk into other buffer
          if (c + 1 < ncc)      issue_chunk(sbase + (unsigned)(cur^1)*(CHF*4), kbase + (size_t)h*SL + (c+1)*CHW, tid);
          else if (h + 1 < H)   issue_chunk(sbase + (unsigned)(cur^1)*(CHF*4), kbase + (size_t)(h+1)*SL, tid);
          else                  issue_chunk(sbase + (unsigned)(cur^1)*(CHF*4), vbase, tid);
          // scores for chunk c: lane owns columns c*384 + g*128 + lane*4 + r
          const float* kb = chbuf + cur*CHF;
          #pragma unroll
          for (int g = 0; g < 3; ++g){
            #pragma unroll
            for (int r = 0; r < 4; ++r){ z0[c*12 + g*4 + r] = 0.f; z1[c*12 + g*4 + r] = 0.f; }
          }
          #pragma unroll 4
          for (int e = 0; e < DKh; ++e){
            float qe0 = qs[(w*2+0)*D + h*DKh + e];
            float qe1 = qs[(w*2+1)*D + h*DKh + e];
            const float4* kr = (const float4*)(kb + e*CHW);
            #pragma unroll
            for (int g = 0; g < 3; ++g){
              float4 kv = kr[g*32 + lane];
              z0[c*12 + g*4 + 0] = fmaf(qe0, kv.x, z0[c*12 + g*4 + 0]);
              z0[c*12 + g*4 + 1] = fmaf(qe0, kv.y, z0[c*12 + g*4 + 1]);
              z0[c*12 + g*4 + 2] = fmaf(qe0, kv.z, z0[c*12 + g*4 + 2]);
              z0[c*12 + g*4 + 3] = fmaf(qe0, kv.w, z0[c*12 + g*4 + 3]);
              z1[c*12 + g*4 + 0] = fmaf(qe1, kv.x, z1[c*12 + g*4 + 0]);
              z1[c*12 + g*4 + 1] = fmaf(qe1, kv.y, z1[c*12 + g*4 + 1]);
              z1[c*12 + g*4 + 2] = fmaf(qe1, kv.z, z1[c*12 + g*4 + 2]);
              z1[c*12 + g*4 + 3] = fmaf(qe1, kv.w, z1[c*12 + g*4 + 3]);
            }
          }
          cur ^= 1;
        }
      }

      // mask + zmax (both rows)
      float m0 = -3.0e30f, m1 = -3.0e30f;
      #pragma unroll
      for (int c = 0; c < 4; ++c){
        if (c < ncc){
          #pragma unroll
          for (int g = 0; g < 3; ++g){
            int sb4 = c*CHW + g*128 + (lane << 2);
            #pragma unroll
            for (int r = 0; r < 4; ++r){
              int j = c*12 + g*4 + r;
              int col = sb4 + r;
              float a0 = (col <= t0) ? z0[j]*0.125f : -5000.0f;
              float a1 = (col <= t1) ? z1[j]*0.125f : -5000.0f;
              z0[j] = a0; z1[j] = a1;
              m0 = fmaxf(m0, a0); m1 = fmaxf(m1, a1);
            }
          }
        }
      }
      #pragma unroll
      for (int off = 16; off; off >>= 1){
        m0 = fmaxf(m0, __shfl_xor_sync(~0u, m0, off));
        m1 = fmaxf(m1, __shfl_xor_sync(~0u, m1, off));
      }

      // active-set exact-quadratic solver for both rows (interleaved)
      float lo0 = m0 - 1.f, hi0 = m0, tau0 = m0 - 1.f;
      float lo1 = m1 - 1.f, hi1 = m1, tau1 = m1 - 1.f;
      #pragma unroll 1
      for (int it = 0; it < 6; ++it){
        float f0 = 0.f, g0 = 0.f, n0 = 0.f;
        float f1 = 0.f, g1 = 0.f, n1 = 0.f;
        #pragma unroll
        for (int c = 0; c < 4; ++c){
          if (c < ncc){
            #pragma unroll
            for (int jj = 0; jj < 12; ++jj){
              int j = c*12 + jj;
              float d0 = z0[j] - tau0, d1 = z1[j] - tau1;
              float p0 = fmaxf(d0, 0.f), p1 = fmaxf(d1, 0.f);
              f0 = fmaf(p0, p0, f0); g0 += p0; n0 += (d0 > 0.f) ? 1.f : 0.f;
              f1 = fmaf(p1, p1, f1); g1 += p1; n1 += (d1 > 0.f) ? 1.f : 0.f;
            }
          }
        }
        #pragma unroll
        for (int off = 16; off; off >>= 1){
          f0 += __shfl_xor_sync(~0u, f0, off);
          f1 += __shfl_xor_sync(~0u, f1, off);
          g0 += __shfl_xor_sync(~0u, g0, off);
          g1 += __shfl_xor_sync(~0u, g1, off);
          n0 += __shfl_xor_sync(~0u, n0, off);
          n1 += __shfl_xor_sync(~0u, n1, off);
        }
        if (f0 > 1.f) lo0 = fmaxf(lo0, tau0); else hi0 = fminf(hi0, tau0);
        if (f1 > 1.f) lo1 = fmaxf(lo1, tau1); else hi1 = fminf(hi1, tau1);
        float d0 = fmaf(g0, g0, -n0*(f0 - 1.f));
        float d1 = fmaf(g1, g1, -n1*(f1 - 1.f));
        float nt0 = tau0 + (g0 - sqrtf(fmaxf(d0, 0.f))) / n0;
        float nt1 = tau1 + (g1 - sqrtf(fmaxf(d1, 0.f))) / n1;
        if (!(d0 > 0.f) || !(nt0 >= lo0 && nt0 <= hi0)) nt0 = 0.5f*(lo0 + hi0);
        if (!(d1 > 0.f) || !(nt1 >= lo1 && nt1 <= hi1)) nt1 = 0.5f*(lo1 + hi1);
        tau0 = nt0; tau1 = nt1;
      }
      #pragma unroll
      for (int c = 0; c < 4; ++c){
        if (c < ncc){
          #pragma unroll
          for (int jj = 0; jj < 12; ++jj){
            int j = c*12 + jj;
            float p0 = fmaxf(z0[j] - tau0, 0.f);
            float p1 = fmaxf(z1[j] - tau1, 0.f);
            wa0[j] = fmaf(p0, p0, wa0[j]);
            wa1[j] = fmaf(p1, p1, wa1[j]);
          }
        }
      }
    }

    // epilogue: head-average -> logs, y = w_avg @ v_comb (v chunks pipelined)
    float* logrow0 = dout + LOGS_OFS + (size_t)((l*B + b)*T + t0)*T;
    float* logrow1 = dout + LOGS_OFS + (size_t)((l*B + b)*T + t1)*T;
    float acc0[DKh], acc1[DKh];
    #pragma unroll
    for (int e = 0; e < DKh; ++e){ acc0[e] = 0.f; acc1[e] = 0.f; }

    #pragma unroll
    for (int c = 0; c < 4; ++c){
      if (c < ncc){
        asm volatile("cp.async.wait_group 0;\n" ::: "memory");
        __syncthreads();
        if (c + 1 < ncc) issue_chunk(sbase + (unsigned)(cur^1)*(CHF*4), vbase + (c+1)*CHW, tid);
        const float* vb = chbuf + cur*CHF;
        #pragma unroll
        for (int g = 0; g < 3; ++g){
          int j = c*12 + g*4;
          float a0 = wa0[j+0]*0.125f, a1 = wa0[j+1]*0.125f, a2 = wa0[j+2]*0.125f, a3 = wa0[j+3]*0.125f;
          float b0 = wa1[j+0]*0.125f, b1 = wa1[j+1]*0.125f, b2 = wa1[j+2]*0.125f, b3 = wa1[j+3]*0.125f;
          ((float4*)(logrow0 + c*CHW + g*128))[lane] = make_float4(a0, a1, a2, a3);
          ((float4*)(logrow1 + c*CHW + g*128))[lane] = make_float4(b0, b1, b2, b3);
          #pragma unroll
          for (int e = 0; e < DKh; ++e){
            float4 vv = ((const float4*)(vb + e*CHW + g*128))[lane];
            acc0[e] = fmaf(a0, vv.x, acc0[e]);
            acc0[e] = fmaf(a1, vv.y, acc0[e]);
            acc0[e] = fmaf(a2, vv.z, acc0[e]);
            acc0[e] = fmaf(a3, vv.w, acc0[e]);
            acc1[e] = fmaf(b0, vv.x, acc1[e]);
            acc1[e] = fmaf(b1, vv.y, acc1[e]);
            acc1[e] = fmaf(b2, vv.z, acc1[e]);
            acc1[e] = fmaf(b3, vv.w, acc1[e]);
          }
        }
        cur ^= 1;
      } else {
        #pragma unroll
        for (int g = 0; g < 3; ++g){
          ((float4*)(logrow0 + c*CHW + g*128))[lane] = make_float4(0.f, 0.f, 0.f, 0.f);
          ((float4*)(logrow1 + c*CHW + g*128))[lane] = make_float4(0.f, 0.f, 0.f, 0.f);
        }
      }
    }

    float myv0 = 0.f, myv1 = 0.f;
    #pragma unroll
    for (int e = 0; e < DKh; ++e){
      float v0 = acc0[e], v1 = acc1[e];
      #pragma unroll
      for (int off = 16; off; off >>= 1){
        v0 += __shfl_xor_sync(~0u, v0, off);
        v1 += __shfl_xor_sync(~0u, v1, off);
      }
      if (lane == e){ myv0 = v0; myv1 = v1; }
    }
    if (lane < DKh){
      g_y[(size_t)(b*T + t0)*DKh + lane] = myv0;
      g_y[(size_t)(b*T + t1)*DKh + lane] = myv1;
    }
  }
}

// ---------------- fused Wo + LN1 + FFN + LN2 (+ next-layer QKV / final proj) ----------------
__global__ void __launch_bounds__(256) ffn_kernel(
    int l, int fuse,
    const float* __restrict__ Wo,  const float* __restrict__ bo,
    const float* __restrict__ g1,  const float* __restrict__ b1,
    const float* __restrict__ fw1, const float* __restrict__ fb1,
    const float* __restrict__ fw2, const float* __restrict__ fb2,
    const float* __restrict__ g2,  const float* __restrict__ b2,
    const float* __restrict__ Wq,  const float* __restrict__ bq,
    const float* __restrict__ Wk,  const float* __restrict__ bk,
    const float* __restrict__ pw,  const float* __restrict__ pb,
    float* __restrict__ dout){
  __shared__ float xs[8][D];
  __shared__ float xsT[D][12];    // stride 12 (48B rows): float4 @0/@16 aligned, fewer bank conflicts
  __shared__ float hsT[DFF][12];  // stride 12
  __shared__ float o3[8][D];
  if (fuse && blockIdx.x == 0 && threadIdx.x == 0) g_ctr = 0;  // reset attn queue for layer l+1
  int bidx = blockIdx.x;
  int b  = bidx / (T/8);
  int t0 = (bidx % (T/8)) * 8;
  int tid = threadIdx.x, w = tid >> 5, lane = tid & 31;
  int t = t0 + w;

  // step 1: a = y@Wo + bo ; LN1(x + a) -> xs, xsT
  {
    float yv[DKh];
    #pragma unroll
    for (int e = 0; e < DKh; ++e) yv[e] = g_y[(b*T + t)*DKh + e];
    float tv[4];
    #pragma unroll
    for (int i = 0; i < 4; ++i){
      int c = lane + 32*i;
      float a = bo[l*D + c];
      #pragma unroll
      for (int e = 0; e < DKh; ++e) a = fmaf(yv[e], Wo[l*DKh*D + e*D + c], a);
      tv[i] = g_x[(b*T + t)*D + c] + a;
    }
    float s = tv[0] + tv[1] + tv[2] + tv[3];
    #pragma unroll
    for (int off = 16; off; off >>= 1) s += __shfl_xor_sync(~0u, s, off);
    float m = s * (1.0f/D);
    float sq = 0.f;
    #pragma unroll
    for (int i = 0; i < 4; ++i){ float dv = tv[i] - m; sq = fmaf(dv, dv, sq); }
    #pragma unroll
    for (int off = 16; off; off >>= 1) sq += __shfl_xor_sync(~0u, sq, off);
    float rs = rsqrtf(sq * (1.0f/D) + 1e-5f);
    #pragma unroll
    for (int i = 0; i < 4; ++i){
      int c = lane + 32*i;
      float v = (tv[i] - m) * rs * g1[l*D + c] + b1[l*D + c];
      xs[w][c] = v;
      xsT[c][w] = v;
    }
  }
  __syncthreads();

  // step 2: hT = relu(xs @ fw1 + fb1), transposed [DFF][12-padded]
  {
    int c = tid;                // columns c and c+256
    float a0[8], a1[8];
    float bb0 = fb1[l*DFF + c], bb1 = fb1[l*DFF + c + 256];
    #pragma unroll
    for (int r = 0; r < 8; ++r){ a0[r] = bb0; a1[r] = bb1; }
    const float* W = fw1 + l*D*DFF;
    for (int e = 0; e < D; ++e){
      float w0 = W[e*DFF + c];
      float w1 = W[e*DFF + c + 256];
      float4 xA = *(const float4*)&xsT[e][0];
      float4 xB = *(const float4*)&xsT[e][4];
      a0[0]=fmaf(w0,xA.x,a0[0]); a0[1]=fmaf(w0,xA.y,a0[1]); a0[2]=fmaf(w0,xA.z,a0[2]); a0[3]=fmaf(w0,xA.w,a0[3]);
      a0[4]=fmaf(w0,xB.x,a0[4]); a0[5]=fmaf(w0,xB.y,a0[5]); a0[6]=fmaf(w0,xB.z,a0[6]); a0[7]=fmaf(w0,xB.w,a0[7]);
      a1[0]=fmaf(w1,xA.x,a1[0]); a1[1]=fmaf(w1,xA.y,a1[1]); a1[2]=fmaf(w1,xA.z,a1[2]); a1[3]=fmaf(w1,xA.w,a1[3]);
      a1[4]=fmaf(w1,xB.x,a1[4]); a1[5]=fmaf(w1,xB.y,a1[5]); a1[6]=fmaf(w1,xB.z,a1[6]); a1[7]=fmaf(w1,xB.w,a1[7]);
    }
    #pragma unroll
    for (int r = 0; r < 8; ++r){ a0[r] = fmaxf(a0[r], 0.f); a1[r] = fmaxf(a1[r], 0.f); }
    *(float4*)&hsT[c][0]       = make_float4(a0[0], a0[1], a0[2], a0[3]);
    *(float4*)&hsT[c][4]       = make_float4(a0[4], a0[5], a0[6], a0[7]);
    *(float4*)&hsT[c + 256][0] = make_float4(a1[0], a1[1], a1[2], a1[3]);
    *(float4*)&hsT[c + 256][4] = make_float4(a1[4], a1[5], a1[6], a1[7]);
  }
  __syncthreads();

  // step 3: o3 = h @ fw2 + fb2 + xs   (thread: col c, 4 rows)
  {
    int c  = tid & 127;
    int rh = tid >> 7;           // 0 or 1 -> rows rh*4 .. rh*4+3
    float acc[4] = {0.f, 0.f, 0.f, 0.f};
    const float* W = fw2 + l*DFF*D;
    for (int s2 = 0; s2 < DFF; ++s2){
      float wv = W[s2*D + c];
      float4 hv = *(const float4*)&hsT[s2][rh*4];
      acc[0] = fmaf(wv, hv.x, acc[0]);
      acc[1] = fmaf(wv, hv.y, acc[1]);
      acc[2] = fmaf(wv, hv.z, acc[2]);
      acc[3] = fmaf(wv, hv.w, acc[3]);
    }
    float bb = fb2[l*D + c];
    #pragma unroll
    for (int k = 0; k < 4; ++k) o3[rh*4 + k][c] = acc[k] + bb + xs[rh*4 + k][c];
  }
  __syncthreads();

  // step 4: LN2 -> g_x (and xs, for fused next-layer QKV / proj)
  {
    float tv[4];
    #pragma unroll
    for (int i = 0; i < 4; ++i) tv[i] = o3[w][lane + 32*i];
    float s = tv[0] + tv[1] + tv[2] + tv[3];
    #pragma unroll
    for (int off = 16; off; off >>= 1) s += __shfl_xor_sync(~0u, s, off);
    float m = s * (1.0f/D);
    float sq = 0.f;
    #pragma unroll
    for (int i = 0; i < 4; ++i){ float dv = tv[i] - m; sq = fmaf(dv, dv, sq); }
    #pragma unroll
    for (int off = 16; off; off >>= 1) sq += __shfl_xor_sync(~0u, sq, off);
    float rs = rsqrtf(sq * (1.0f/D) + 1e-5f);
    #pragma unroll
    for (int i = 0; i < 4; ++i){
      int c = lane + 32*i;
      float v = (tv[i] - m) * rs * g2[l*D + c] + b2[l*D + c];
      g_x[(b*T + t)*D + c] = v;
      xs[w][c] = v;
    }
  }

  // step 5 (fused): next-layer QKV from xs
  if (fuse){
    __syncthreads();
    qkv_stage(l + 1, b, t0, xs, tid, Wq, bq, Wk, bk);
  } else if (t0 == T - 8){
    // last layer, tile containing t = T-1: fused final projection for this b
    __syncthreads();
    for (int i = tid; i < NQ*HOR; i += 256){
      int q = i / HOR, hh = i % HOR;
      float acc = pb[q*HOR + hh];
      for (int dd = 0; dd < D; ++dd)
        acc = fmaf(xs[7][dd], pw[(q*D + dd)*HOR + hh], acc);
      dout[(b*NQ + q)*HOR + hh] = acc;
    }
  }
}

// ---------------- launch ----------------
extern "C" void kernel_launch(void* const* d_in, const int* in_sizes, int n_in,
                              void* d_out, int out_size) {
  const float* x_cond = (const float*)d_in[0];
  const float* x_pred = (const float*)d_in[1];
  const float* cw_c   = (const float*)d_in[2];
  const float* cb_c   = (const float*)d_in[3];
  const float* sw_c   = (const float*)d_in[4];
  const float* sb_c   = (const float*)d_in[5];
  const float* cw_p   = (const float*)d_in[6];
  const float* cb_p   = (const float*)d_in[7];
  const float* sw_p   = (const float*)d_in[8];
  const float* sb_p   = (const float*)d_in[9];
  const float* Wq     = (const float*)d_in[10];
  const float* bq     = (const float*)d_in[11];
  const float* Wk     = (const float*)d_in[12];
  const float* bk     = (const float*)d_in[13];
  const float* Wv     = (const float*)d_in[14];
  const float* bv     = (const float*)d_in[15];
  const float* Wo     = (const float*)d_in[16];
  const float* bo     = (const float*)d_in[17];
  const float* ln1_g  = (const float*)d_in[18];
  const float* ln1_b  = (const float*)d_in[19];
  const float* fw1    = (const float*)d_in[20];
  const float* fb1    = (const float*)d_in[21];
  const float* fw2    = (const float*)d_in[22];
  const float* fb2    = (const float*)d_in[23];
  const float* ln2_g  = (const float*)d_in[24];
  const float* ln2_b  = (const float*)d_in[25];
  const float* proj_w = (const float*)d_in[26];
  const float* proj_b = (const float*)d_in[27];
  float* out = (float*)d_out;

  const int smemA = 2 * CHF * (int)sizeof(float);   // 49152 B dynamic
  cudaFuncSetAttribute(attn_fused_kernel, cudaFuncAttributeMaxDynamicSharedMemorySize, smemA);

  prep_kernel<<<1, 256>>>(cw_c, cb_c, sw_c, sb_c, cw_p, cb_p, sw_p, sb_p, Wv, bv);
  selector_kernel<NVC, TCOND, 0><<<(B*TCOND + 127)/128, 128>>>(x_cond, out, VC_OFS);
  selector_kernel<NVP, TPRED, 1><<<(B*TPRED + 127)/128, 128>>>(x_pred, out, VP_OFS);

  wqkv_kernel<<<B*T/8, 256>>>(x_cond, x_pred, cw_c, cb_c, cw_p, cb_p, Wq, bq, Wk, bk);
  for (int l = 0; l < L; ++l){
    attn_fused_kernel<<<148, 256, smemA>>>(l, out);
    ffn_kernel<<<B*T/8, 256>>>(l, (l + 1 < L) ? 1 : 0,
                               Wo, bo, ln1_g, ln1_b, fw1, fb1, fw2, fb2, ln2_g, ln2_b,
                               Wq, bq, Wk, bk, proj_w, proj_b, out);
  }
}